// round 3
// baseline (speedup 1.0000x reference)
#include <cuda_runtime.h>
#include <math.h>

// Shapes (fixed by the problem)
#define A_DIM 64
#define B_DIM 128
#define D_DIM 256
#define H_DIM 64
#define C_DIM 32

// Intermediate out1 [A][H][D] lives in a device global (no allocations allowed).
__device__ float g_out1[A_DIM * H_DIM * D_DIM];

// ---- packed fp32x2 FMA (B300: FFMA-3reg is half-rate; FFMA2 recovers full fp32 rate) ----
union F2U { float2 f; unsigned long long u; };
__device__ __forceinline__ void fma2(float2& d, float2 a, float2 b) {
    F2U du, au, bu; du.f = d; au.f = a; bu.f = b;
    asm("fma.rn.f32x2 %0, %1, %2, %0;" : "+l"(du.u) : "l"(au.u), "l"(bu.u));
    d = du.f;
}

// ---- block reductions over 512 threads (16 warps) ----
__device__ __forceinline__ float warpSum(float v) {
    #pragma unroll
    for (int o = 16; o; o >>= 1) v += __shfl_down_sync(0xffffffffu, v, o);
    return v;
}
__device__ __forceinline__ float warpMax(float v) {
    #pragma unroll
    for (int o = 16; o; o >>= 1) v = fmaxf(v, __shfl_down_sync(0xffffffffu, v, o));
    return v;
}
__device__ __forceinline__ float blockSum(float v, float* red) {
    v = warpSum(v);
    __syncthreads();
    if ((threadIdx.x & 31) == 0) red[threadIdx.x >> 5] = v;
    __syncthreads();
    if (threadIdx.x < 32) {
        float x = (threadIdx.x < 16) ? red[threadIdx.x] : 0.0f;
        x = warpSum(x);
        if (threadIdx.x == 0) red[32] = x;
    }
    __syncthreads();
    return red[32];
}
__device__ __forceinline__ float blockMax(float v, float* red) {
    v = warpMax(v);
    __syncthreads();
    if ((threadIdx.x & 31) == 0) red[threadIdx.x >> 5] = v;
    __syncthreads();
    if (threadIdx.x < 32) {
        float x = (threadIdx.x < 16) ? red[threadIdx.x] : -3.402823466e38f;
        x = warpMax(x);
        if (threadIdx.x == 0) red[32] = x;
    }
    __syncthreads();
    return red[32];
}

// One CTA = one (weight-index, batch-index) pair.
//   Computes P[M,256] = Xblk[M,256] @ Wblk[256,256] in SMEM,
//   then runs 3 dynamic-routing iterations over the M rows,
//   then writes the 256-dim squashed output vector.
// Grid: (x = batch index a, y = weight index h or c).
template<int M>
__global__ void __launch_bounds__(512)
caps_route_kernel(const float* __restrict__ X, const float* __restrict__ W,
                  float* __restrict__ Out,
                  int xBlkStride, int outXStride, int outYStride)
{
    constexpr int KC = 64, NC = 64, XS = KC + 4;  // pad X tile stride to kill bank conflicts
    constexpr int TM = M / 32;                    // rows per thread (4 for M=128, 2 for M=64)

    extern __shared__ float sm[];
    float* P      = sm;                    // M*256   prior tile
    float* Xs     = P + M * 256;           // M*XS    X k-tile
    float* Ws     = Xs + M * XS;           // 64*64   W (k,n)-tile
    float* logits = Ws + 64 * 64;          // M
    float* probs  = logits + M;            // M
    float* vout   = probs + M;             // 256
    float* part   = vout + 256;            // 512
    float* red    = part + 512;            // 64

    const int tid = threadIdx.x;
    const int tx = tid & 15;               // column group (4 cols each)
    const int ty = tid >> 4;               // row group (TM rows each), 0..31
    const float* Xblk = X + (size_t)blockIdx.x * (size_t)xBlkStride;
    const float* Wblk = W + (size_t)blockIdx.y * 65536u;

    // ================= GEMM: P = Xblk @ Wblk =================
    for (int n0 = 0; n0 < 256; n0 += NC) {
        float2 acc[TM][2];
        #pragma unroll
        for (int i = 0; i < TM; i++) {
            acc[i][0] = make_float2(0.f, 0.f);
            acc[i][1] = make_float2(0.f, 0.f);
        }
        for (int k0 = 0; k0 < 256; k0 += KC) {
            __syncthreads();   // protect previous tile's readers
            // load X tile [M x 64] (coalesced float4, padded smem rows)
            #pragma unroll
            for (int e = tid; e < M * 16; e += 512) {
                int r = e >> 4, c4 = e & 15;
                *(float4*)(Xs + r * XS + c4 * 4) =
                    *(const float4*)(Xblk + r * 256 + k0 + c4 * 4);
            }
            // load W tile [64 x 64]
            #pragma unroll
            for (int e = tid; e < 1024; e += 512) {
                int r = e >> 4, c4 = e & 15;
                *(float4*)(Ws + r * 64 + c4 * 4) =
                    *(const float4*)(Wblk + (k0 + r) * 256 + n0 + c4 * 4);
            }
            __syncthreads();
            #pragma unroll 16
            for (int kk = 0; kk < KC; kk++) {
                float4 wv = *(const float4*)(Ws + kk * 64 + tx * 4);
                float2 w01 = make_float2(wv.x, wv.y);
                float2 w23 = make_float2(wv.z, wv.w);
                #pragma unroll
                for (int i = 0; i < TM; i++) {
                    float xv = Xs[(ty * TM + i) * XS + kk];
                    float2 xx = make_float2(xv, xv);
                    fma2(acc[i][0], xx, w01);
                    fma2(acc[i][1], xx, w23);
                }
            }
        }
        #pragma unroll
        for (int i = 0; i < TM; i++) {
            *(float4*)(P + (ty * TM + i) * 256 + n0 + tx * 4) =
                make_float4(acc[i][0].x, acc[i][0].y, acc[i][1].x, acc[i][1].y);
        }
    }
    __syncthreads();

    // ================= dynamic routing (3 iterations) =================
    if (tid < M) logits[tid] = 0.0f;

    const int wid = tid >> 5, lane = tid & 31;

    for (int it = 0; it < 3; ++it) {
        // ---- probs = softmax(logits) over the M rows ----
        if (it == 0) {
            if (tid < M) probs[tid] = 1.0f / (float)M;   // softmax of zeros
        } else {
            float lv = (tid < M) ? logits[tid] : -3.402823466e38f;
            float mx = blockMax(lv, red);
            float ev = (tid < M) ? expf(lv - mx) : 0.0f;
            float Z = blockSum(ev, red);
            if (tid < M) probs[tid] = ev / Z;
        }
        __syncthreads();

        // ---- s[d] = sum_b probs[b] * P[b][d]  (column sums, split over 2 halves) ----
        {
            int d = tid & 255, hf = tid >> 8;
            int b0 = hf * (M / 2);
            float a = 0.0f;
            #pragma unroll 8
            for (int b = 0; b < M / 2; ++b)
                a = fmaf(probs[b0 + b], P[(b0 + b) * 256 + d], a);
            part[tid] = a;
        }
        __syncthreads();
        float sd = 0.0f;
        if (tid < 256) sd = part[tid] + part[tid + 256];

        // ---- squash: v = (sq/(1+sq)) * s / sqrt(sq) ----
        float sq = blockSum(sd * sd, red);
        float scale = sq / ((1.0f + sq) * sqrtf(sq));
        if (tid < 256) vout[tid] = sd * scale;
        __syncthreads();

        if (it < 2) {
            // ---- logits[b] += sum_d P[b][d] * v[d] (warp-per-row-group, coalesced) ----
            constexpr int RPW = M / 16;   // rows per warp
            #pragma unroll
            for (int rr = 0; rr < RPW; ++rr) {
                int r = wid * RPW + rr;
                float a = 0.0f;
                #pragma unroll
                for (int k = 0; k < 8; ++k)
                    a = fmaf(P[r * 256 + k * 32 + lane], vout[k * 32 + lane], a);
                a = warpSum(a);
                if (lane == 0) logits[r] += a;
            }
            __syncthreads();
        } else {
            if (tid < 256)
                Out[(size_t)blockIdx.x * outXStride + (size_t)blockIdx.y * outYStride + tid]
                    = vout[tid];
        }
    }
}

static constexpr size_t smem_bytes(int M) {
    return (size_t)((size_t)M * 256 + (size_t)M * 68 + 64 * 64 + M + M + 256 + 512 + 64)
           * sizeof(float);
}

extern "C" void kernel_launch(void* const* d_in, const int* in_sizes, int n_in,
                              void* d_out, int out_size) {
    const float* x  = (const float*)d_in[0];   // [A=64, B=128, D=256]
    const float* w1 = (const float*)d_in[1];   // [H=64, 256, 256]
    const float* w2 = (const float*)d_in[2];   // [C=32, 256, 256]
    float* out = (float*)d_out;                // [C=32, A=64, 256]

    void* o1v = nullptr;
    cudaGetSymbolAddress(&o1v, g_out1);
    float* o1 = (float*)o1v;                   // [A][H][256]

    const size_t sm1 = smem_bytes(128);        // 186,624 B
    const size_t sm2 = smem_bytes(64);         // 103,168 B
    cudaFuncSetAttribute(caps_route_kernel<128>,
                         cudaFuncAttributeMaxDynamicSharedMemorySize, (int)sm1);
    cudaFuncSetAttribute(caps_route_kernel<64>,
                         cudaFuncAttributeMaxDynamicSharedMemorySize, (int)sm2);

    // Stage 1: grid (a=64, h=64); out1[a*H*256 + h*256 + d]
    caps_route_kernel<128><<<dim3(64, 64), 512, sm1>>>(
        x, w1, o1, /*xBlkStride=*/128 * 256, /*outXStride=*/64 * 256, /*outYStride=*/256);

    // Stage 2: grid (a=64, c=32); out[c*A*256 + a*256 + d]
    caps_route_kernel<64><<<dim3(64, 32), 512, sm2>>>(
        o1, w2, out, /*xBlkStride=*/64 * 256, /*outXStride=*/256, /*outYStride=*/64 * 256);
}

// round 4
// speedup vs baseline: 1.1989x; 1.1989x over previous
#include <cuda_runtime.h>
#include <math.h>

// Shapes (fixed by the problem)
#define A_DIM 64
#define B_DIM 128
#define D_DIM 256
#define H_DIM 64
#define C_DIM 32

// Intermediate out1 [A][H][D] lives in a device global (no allocations allowed).
__device__ float g_out1[A_DIM * H_DIM * D_DIM];

// ---- packed fp32x2 FMA (B300: FFMA2 gives 2 MACs/issue, recovers full fp32 rate) ----
union F2U { float2 f; unsigned long long u; };
__device__ __forceinline__ void fma2(float2& d, float2 a, float2 b) {
    F2U du, au, bu; du.f = d; au.f = a; bu.f = b;
    asm("fma.rn.f32x2 %0, %1, %2, %0;" : "+l"(du.u) : "l"(au.u), "l"(bu.u));
    d = du.f;
}

// ---- block reductions over 512 threads (16 warps) ----
__device__ __forceinline__ float warpSum(float v) {
    #pragma unroll
    for (int o = 16; o; o >>= 1) v += __shfl_down_sync(0xffffffffu, v, o);
    return v;
}
__device__ __forceinline__ float warpMax(float v) {
    #pragma unroll
    for (int o = 16; o; o >>= 1) v = fmaxf(v, __shfl_down_sync(0xffffffffu, v, o));
    return v;
}
__device__ __forceinline__ float blockSum(float v, float* red) {
    v = warpSum(v);
    __syncthreads();
    if ((threadIdx.x & 31) == 0) red[threadIdx.x >> 5] = v;
    __syncthreads();
    if (threadIdx.x < 32) {
        float x = (threadIdx.x < 16) ? red[threadIdx.x] : 0.0f;
        x = warpSum(x);
        if (threadIdx.x == 0) red[32] = x;
    }
    __syncthreads();
    return red[32];
}
__device__ __forceinline__ float blockMax(float v, float* red) {
    v = warpMax(v);
    __syncthreads();
    if ((threadIdx.x & 31) == 0) red[threadIdx.x >> 5] = v;
    __syncthreads();
    if (threadIdx.x < 32) {
        float x = (threadIdx.x < 16) ? red[threadIdx.x] : -3.402823466e38f;
        x = warpMax(x);
        if (threadIdx.x == 0) red[32] = x;
    }
    __syncthreads();
    return red[32];
}

// One CTA = one (weight-index, batch-index) pair.
//   P[M,256] = Xblk[M,256] @ Wblk[256,256] computed into SMEM with an
//   8xTN register tile per thread (FMA-bound), then 3 routing iterations.
// Grid: (x = batch index a, y = weight index h or c).
template<int M>
__global__ void __launch_bounds__(512)
caps_route_kernel(const float* __restrict__ X, const float* __restrict__ W,
                  float* __restrict__ Out,
                  int xBlkStride, int outXStride, int outYStride)
{
    constexpr int KC = 32;                 // k-tile depth
    constexpr int NT = 256 / KC;           // 8 k-tiles
    constexpr int TM = M / 16;             // rows per thread (8 for M=128, 4 for M=64)
    constexpr int MS = M + 4;              // k-major X tile row stride (floats)
    constexpr int XL = (M * KC / 4) / 512; // float4 X loads per thread per tile (2 or 1)

    extern __shared__ float sm[];
    float* P      = sm;                    // M*256   prior tile, row-major [m][d]
    float* Xs     = P + M * 256;           // KC*MS   X k-tile, K-MAJOR [k][m]
    float* Ws     = Xs + KC * MS;          // KC*256  W tile, [k][n]
    float* logits = Ws + KC * 256;         // M
    float* probs  = logits + M;            // M
    float* vout   = probs + M;             // 256
    float* part   = vout + 256;            // 512
    float* red    = part + 512;            // 64

    const int tid = threadIdx.x;
    const int tx = tid & 31;               // col group: cols tx*8 .. tx*8+7
    const int ty = tid >> 5;               // row group: rows ty*TM .. (warp-uniform!)
    const float* Xblk = X + (size_t)blockIdx.x * (size_t)xBlkStride;
    const float* Wblk = W + (size_t)blockIdx.y * 65536u;

    // ================= GEMM: P = Xblk @ Wblk (full N=256 in registers) ==========
    float2 acc[TM][4];
    #pragma unroll
    for (int i = 0; i < TM; i++)
        #pragma unroll
        for (int j = 0; j < 4; j++) acc[i][j] = make_float2(0.f, 0.f);

    float4 xr[XL], wr[4];

    // prefetch helpers (global -> regs), (regs -> smem)
    auto gload = [&](int t) {
        const int k0 = t * KC;
        #pragma unroll
        for (int l = 0; l < XL; l++) {
            int e = tid + l * 512, r = e >> 3, c4 = e & 7;
            xr[l] = *(const float4*)(Xblk + r * 256 + k0 + c4 * 4);
        }
        #pragma unroll
        for (int q = 0; q < 4; q++) {
            int e = tid + q * 512, r = e >> 6, c4 = e & 63;
            wr[q] = *(const float4*)(Wblk + (size_t)(k0 + r) * 256 + c4 * 4);
        }
    };
    auto stile = [&]() {
        #pragma unroll
        for (int l = 0; l < XL; l++) {
            int e = tid + l * 512, r = e >> 3, c4 = e & 7;
            Xs[(c4 * 4 + 0) * MS + r] = xr[l].x;
            Xs[(c4 * 4 + 1) * MS + r] = xr[l].y;
            Xs[(c4 * 4 + 2) * MS + r] = xr[l].z;
            Xs[(c4 * 4 + 3) * MS + r] = xr[l].w;
        }
        #pragma unroll
        for (int q = 0; q < 4; q++) {
            int e = tid + q * 512, r = e >> 6, c4 = e & 63;
            *(float4*)(Ws + r * 256 + c4 * 4) = wr[q];
        }
    };

    gload(0);
    stile();
    __syncthreads();

    for (int t = 0; t < NT; ++t) {
        if (t + 1 < NT) gload(t + 1);   // prefetch next tile into regs

        #pragma unroll 4
        for (int kk = 0; kk < KC; ++kk) {
            // X fragment: vectorized BROADCAST loads (warp-uniform address)
            float xf[TM];
            #pragma unroll
            for (int v = 0; v < TM / 4; v++)
                *(float4*)(xf + v * 4) = *(const float4*)(Xs + kk * MS + ty * TM + v * 4);
            // W fragment: 2x LDS.128, conflict-free
            float4 w0 = *(const float4*)(Ws + kk * 256 + tx * 8);
            float4 w1 = *(const float4*)(Ws + kk * 256 + tx * 8 + 4);
            float2 wp[4] = { make_float2(w0.x, w0.y), make_float2(w0.z, w0.w),
                             make_float2(w1.x, w1.y), make_float2(w1.z, w1.w) };
            #pragma unroll
            for (int i = 0; i < TM; i++) {
                float2 xx = make_float2(xf[i], xf[i]);
                #pragma unroll
                for (int j = 0; j < 4; j++) fma2(acc[i][j], xx, wp[j]);
            }
        }
        __syncthreads();                 // everyone done reading this tile
        if (t + 1 < NT) { stile(); __syncthreads(); }
    }

    // epilogue: acc -> P
    #pragma unroll
    for (int i = 0; i < TM; i++) {
        float* prow = P + (ty * TM + i) * 256 + tx * 8;
        *(float4*)(prow)     = make_float4(acc[i][0].x, acc[i][0].y, acc[i][1].x, acc[i][1].y);
        *(float4*)(prow + 4) = make_float4(acc[i][2].x, acc[i][2].y, acc[i][3].x, acc[i][3].y);
    }
    __syncthreads();

    // ================= dynamic routing (3 iterations) =================
    if (tid < M) logits[tid] = 0.0f;

    const int wid = tid >> 5, lane = tid & 31;

    for (int it = 0; it < 3; ++it) {
        // ---- probs = softmax(logits) over the M rows ----
        if (it == 0) {
            if (tid < M) probs[tid] = 1.0f / (float)M;   // softmax of zeros
        } else {
            float lv = (tid < M) ? logits[tid] : -3.402823466e38f;
            float mx = blockMax(lv, red);
            float ev = (tid < M) ? expf(lv - mx) : 0.0f;
            float Z = blockSum(ev, red);
            if (tid < M) probs[tid] = ev / Z;
        }
        __syncthreads();

        // ---- s[d] = sum_b probs[b] * P[b][d]  (column sums, split over 2 halves) ----
        {
            int d = tid & 255, hf = tid >> 8;
            int b0 = hf * (M / 2);
            float a = 0.0f;
            #pragma unroll 8
            for (int b = 0; b < M / 2; ++b)
                a = fmaf(probs[b0 + b], P[(b0 + b) * 256 + d], a);
            part[tid] = a;
        }
        __syncthreads();
        float sd = 0.0f;
        if (tid < 256) sd = part[tid] + part[tid + 256];

        // ---- squash: v = (sq/(1+sq)) * s / sqrt(sq) ----
        float sq = blockSum(sd * sd, red);
        float scale = sq / ((1.0f + sq) * sqrtf(sq));
        if (tid < 256) vout[tid] = sd * scale;
        __syncthreads();

        if (it < 2) {
            // ---- logits[b] += sum_d P[b][d] * v[d] (warp-per-row-group, coalesced) ----
            constexpr int RPW = M / 16;   // rows per warp
            #pragma unroll
            for (int rr = 0; rr < RPW; ++rr) {
                int r = wid * RPW + rr;
                float a = 0.0f;
                #pragma unroll
                for (int k = 0; k < 8; ++k)
                    a = fmaf(P[r * 256 + k * 32 + lane], vout[k * 32 + lane], a);
                a = warpSum(a);
                if (lane == 0) logits[r] += a;
            }
            __syncthreads();
        } else {
            if (tid < 256)
                Out[(size_t)blockIdx.x * outXStride + (size_t)blockIdx.y * outYStride + tid]
                    = vout[tid];
        }
    }
}

static constexpr size_t smem_bytes(int M) {
    return (size_t)((size_t)M * 256 + 32 * (size_t)(M + 4) + 32 * 256
                    + M + M + 256 + 512 + 64) * sizeof(float);
}

extern "C" void kernel_launch(void* const* d_in, const int* in_sizes, int n_in,
                              void* d_out, int out_size) {
    const float* x  = (const float*)d_in[0];   // [A=64, B=128, D=256]
    const float* w1 = (const float*)d_in[1];   // [H=64, 256, 256]
    const float* w2 = (const float*)d_in[2];   // [C=32, 256, 256]
    float* out = (float*)d_out;                // [C=32, A=64, 256]

    void* o1v = nullptr;
    cudaGetSymbolAddress(&o1v, g_out1);
    float* o1 = (float*)o1v;                   // [A][H][256]

    const size_t sm1 = smem_bytes(128);        // ~185 KB
    const size_t sm2 = smem_bytes(64);         // ~111 KB
    cudaFuncSetAttribute(caps_route_kernel<128>,
                         cudaFuncAttributeMaxDynamicSharedMemorySize, (int)sm1);
    cudaFuncSetAttribute(caps_route_kernel<64>,
                         cudaFuncAttributeMaxDynamicSharedMemorySize, (int)sm2);

    // Stage 1: grid (a=64, h=64); out1[a*H*256 + h*256 + d]
    caps_route_kernel<128><<<dim3(64, 64), 512, sm1>>>(
        x, w1, o1, /*xBlkStride=*/128 * 256, /*outXStride=*/64 * 256, /*outYStride=*/256);

    // Stage 2: grid (a=64, c=32); out[c*A*256 + a*256 + d]
    caps_route_kernel<64><<<dim3(64, 32), 512, sm2>>>(
        o1, w2, out, /*xBlkStride=*/64 * 256, /*outXStride=*/256, /*outYStride=*/64 * 256);
}

// round 8
// speedup vs baseline: 1.3715x; 1.1440x over previous
#include <cuda_runtime.h>
#include <cuda_bf16.h>
#include <math.h>
#include <stdint.h>

// ---------------- device globals (no allocations allowed) ----------------
// 3-level bf16 splits: v = vh + vm + vl (each level bf16)
__device__ __nv_bfloat16 g_xh[64 * 128 * 256], g_xm[64 * 128 * 256], g_xl[64 * 128 * 256];
__device__ __nv_bfloat16 g_w1h[64 * 256 * 256], g_w1m[64 * 256 * 256], g_w1l[64 * 256 * 256];
__device__ __nv_bfloat16 g_w2h[32 * 256 * 256], g_w2m[32 * 256 * 256], g_w2l[32 * 256 * 256];
__device__ __nv_bfloat16 g_o1h[64 * 64 * 256], g_o1m[64 * 64 * 256], g_o1l[64 * 64 * 256];

// ---------------- bf16 HMMA via mma.sync (sm_80+ baseline PTX) ----------------
__device__ __forceinline__ void mma_bf16(float* c, const uint32_t* a, uint32_t b0, uint32_t b1) {
    asm volatile(
        "mma.sync.aligned.m16n8k16.row.col.f32.bf16.bf16.f32 "
        "{%0,%1,%2,%3}, {%4,%5,%6,%7}, {%8,%9}, {%0,%1,%2,%3};"
        : "+f"(c[0]), "+f"(c[1]), "+f"(c[2]), "+f"(c[3])
        : "r"(a[0]), "r"(a[1]), "r"(a[2]), "r"(a[3]), "r"(b0), "r"(b1));
}

// ---------------- block reductions over 512 threads (16 warps) ----------------
__device__ __forceinline__ float warpSum(float v) {
    #pragma unroll
    for (int o = 16; o; o >>= 1) v += __shfl_down_sync(0xffffffffu, v, o);
    return v;
}
__device__ __forceinline__ float warpMax(float v) {
    #pragma unroll
    for (int o = 16; o; o >>= 1) v = fmaxf(v, __shfl_down_sync(0xffffffffu, v, o));
    return v;
}
__device__ __forceinline__ float blockSum(float v, float* red) {
    v = warpSum(v);
    __syncthreads();
    if ((threadIdx.x & 31) == 0) red[threadIdx.x >> 5] = v;
    __syncthreads();
    if (threadIdx.x < 32) {
        float x = (threadIdx.x < 16) ? red[threadIdx.x] : 0.0f;
        x = warpSum(x);
        if (threadIdx.x == 0) red[32] = x;
    }
    __syncthreads();
    return red[32];
}
__device__ __forceinline__ float blockMax(float v, float* red) {
    v = warpMax(v);
    __syncthreads();
    if ((threadIdx.x & 31) == 0) red[threadIdx.x >> 5] = v;
    __syncthreads();
    if (threadIdx.x < 32) {
        float x = (threadIdx.x < 16) ? red[threadIdx.x] : -3.402823466e38f;
        x = warpMax(x);
        if (threadIdx.x == 0) red[32] = x;
    }
    __syncthreads();
    return red[32];
}

// 3-level split of a float
__device__ __forceinline__ void split3(float v, __nv_bfloat16& h, __nv_bfloat16& m, __nv_bfloat16& l) {
    h = __float2bfloat16(v);
    float r1 = v - __bfloat162float(h);
    m = __float2bfloat16(r1);
    float r2 = r1 - __bfloat162float(m);
    l = __float2bfloat16(r2);
}

// ---------------- pre-pass: split X into bf16 h/m/l ----------------
__global__ void split_x_kernel(const float* __restrict__ x,
                               __nv_bfloat16* __restrict__ xh,
                               __nv_bfloat16* __restrict__ xm,
                               __nv_bfloat16* __restrict__ xl, int n) {
    int i = blockIdx.x * blockDim.x + threadIdx.x;
    if (i >= n) return;
    __nv_bfloat16 h, m, l;
    split3(x[i], h, m, l);
    xh[i] = h; xm[i] = m; xl[i] = l;
}

// ---------------- pre-pass: transpose + split W[k][n] -> Wt[n][k] bf16 h/m/l ----------------
__global__ void trans_split_w(const float* __restrict__ W,
                              __nv_bfloat16* __restrict__ Wth,
                              __nv_bfloat16* __restrict__ Wtm,
                              __nv_bfloat16* __restrict__ Wtl) {
    __shared__ float st[32][33];
    int mb = blockIdx.z, k0 = blockIdx.x * 32, n0 = blockIdx.y * 32;
    const float* Wm = W + (size_t)mb * 65536;
    int tid = threadIdx.x;
    #pragma unroll
    for (int i = 0; i < 4; ++i) {
        int e = tid + i * 256, k = e >> 5, n = e & 31;
        st[k][n] = Wm[(k0 + k) * 256 + n0 + n];
    }
    __syncthreads();
    #pragma unroll
    for (int i = 0; i < 4; ++i) {
        int e = tid + i * 256, n = e >> 5, k = e & 31;
        float f = st[k][n];
        __nv_bfloat16 h, m, l;
        split3(f, h, m, l);
        size_t o = (size_t)mb * 65536 + (size_t)(n0 + n) * 256 + k0 + k;
        Wth[o] = h; Wtm[o] = m; Wtl[o] = l;
    }
}

// ---------------- fused HMMA-GEMM + routing kernel ----------------
// One CTA = one (weight, batch) pair.
//   P[M,256] = A[M,256] @ B^T via 6-term 3-level bf16 split,
//   fp32 accumulators, then 3 routing iterations on P in SMEM.
// 16 warps: 4 row-groups x 4 col-groups; warp tile (M/4) x 64.
template<int M, bool F32OUT>
__global__ void __launch_bounds__(512)
caps_mma_route(const __nv_bfloat16* __restrict__ AhG, const __nv_bfloat16* __restrict__ AmG,
               const __nv_bfloat16* __restrict__ AlG,
               const __nv_bfloat16* __restrict__ BhG, const __nv_bfloat16* __restrict__ BmG,
               const __nv_bfloat16* __restrict__ BlG,
               float* __restrict__ OutF,
               __nv_bfloat16* __restrict__ OutH, __nv_bfloat16* __restrict__ OutM,
               __nv_bfloat16* __restrict__ OutL,
               int outXStride, int outYStride)
{
    constexpr int PS = 258;              // padded P row stride (floats, even for float2)
    constexpr int TS = 72;               // smem tile row stride in bf16 (64 k + 8 pad)
    constexpr int MR = M / 64;           // mma row-tiles per warp (2 for M=128, 1 for M=64)
    constexpr uint32_t ATB = (uint32_t)M * TS * 2;    // one A tile bytes
    constexpr uint32_t BTB = 256u * TS * 2;           // one B tile bytes
    constexpr uint32_t ASH = 0, ASM = ATB, ASL = 2 * ATB;
    constexpr uint32_t BSH = 3 * ATB, BSM = BSH + BTB, BSL = BSH + 2 * BTB;
    constexpr uint32_t TILES_END = BSH + 3 * BTB;
    constexpr uint32_t PBYTES = (uint32_t)M * PS * 4;
    constexpr uint32_t SCR = (TILES_END > PBYTES ? TILES_END : PBYTES);

    extern __shared__ char smc[];
    float* P      = (float*)smc;
    float* logits = (float*)(smc + SCR);
    float* probs  = logits + M;
    float* vout   = probs + M;
    float* part   = vout + 256;
    float* red    = part + 512;

    const int tid = threadIdx.x;
    const int wid = tid >> 5, lane = tid & 31;
    const int g = lane >> 2, q = lane & 3;           // mma fragment coords
    const int wrow = (wid >> 2) * (M / 4);           // warp row base
    const int wcol = (wid & 3) * 64;                 // warp col base

    const size_t aOff = (size_t)blockIdx.x * (M * 256);
    const size_t bOff = (size_t)blockIdx.y * 65536u;
    const __nv_bfloat16* Asrc[3] = { AhG + aOff, AmG + aOff, AlG + aOff };
    const __nv_bfloat16* Bsrc[3] = { BhG + bOff, BmG + bOff, BlG + bOff };

    // ============ GEMM: 4 K-chunks of 64, 6-term 3-level bf16 split ============
    float acc[MR][8][4];
    #pragma unroll
    for (int mr = 0; mr < MR; ++mr)
        #pragma unroll
        for (int nt = 0; nt < 8; ++nt)
            #pragma unroll
            for (int j = 0; j < 4; ++j) acc[mr][nt][j] = 0.0f;

    for (int kc = 0; kc < 4; ++kc) {
        const int k0g = kc * 64;
        // load 3 A tiles: M rows x 64 k each, uint4 = 8 bf16
        #pragma unroll
        for (int lv = 0; lv < 3; ++lv) {
            const __nv_bfloat16* src = Asrc[lv];
            uint32_t dstb = lv * ATB;
            for (int e = tid; e < M * 8; e += 512) {
                int r = e >> 3, seg = e & 7;
                *(uint4*)(smc + dstb + (uint32_t)(r * TS + seg * 8) * 2) =
                    *(const uint4*)(src + r * 256 + k0g + seg * 8);
            }
        }
        // load 3 B tiles: 256 rows x 64 k each
        #pragma unroll
        for (int lv = 0; lv < 3; ++lv) {
            const __nv_bfloat16* src = Bsrc[lv];
            uint32_t dstb = BSH + lv * BTB;
            for (int e = tid; e < 2048; e += 512) {
                int r = e >> 3, seg = e & 7;
                *(uint4*)(smc + dstb + (uint32_t)(r * TS + seg * 8) * 2) =
                    *(const uint4*)(src + r * 256 + k0g + seg * 8);
            }
        }
        __syncthreads();

        const __nv_bfloat16* Ash = (const __nv_bfloat16*)(smc + ASH);
        const __nv_bfloat16* Asm_ = (const __nv_bfloat16*)(smc + ASM);
        const __nv_bfloat16* Asl = (const __nv_bfloat16*)(smc + ASL);
        const __nv_bfloat16* Bsh = (const __nv_bfloat16*)(smc + BSH);
        const __nv_bfloat16* Bsm = (const __nv_bfloat16*)(smc + BSM);
        const __nv_bfloat16* Bsl = (const __nv_bfloat16*)(smc + BSL);

        #pragma unroll
        for (int ks = 0; ks < 4; ++ks) {
            const int k0 = ks * 16;
            // A fragments for all three levels
            uint32_t ah[MR][4], am[MR][4], al[MR][4];
            #pragma unroll
            for (int mr = 0; mr < MR; ++mr) {
                const int rb = (wrow + mr * 16 + g) * TS + k0 + 2 * q;
                const __nv_bfloat16* ar = Ash + rb;
                ah[mr][0] = *(const uint32_t*)ar;
                ah[mr][1] = *(const uint32_t*)(ar + 8 * TS);
                ah[mr][2] = *(const uint32_t*)(ar + 8);
                ah[mr][3] = *(const uint32_t*)(ar + 8 * TS + 8);
                const __nv_bfloat16* am_ = Asm_ + rb;
                am[mr][0] = *(const uint32_t*)am_;
                am[mr][1] = *(const uint32_t*)(am_ + 8 * TS);
                am[mr][2] = *(const uint32_t*)(am_ + 8);
                am[mr][3] = *(const uint32_t*)(am_ + 8 * TS + 8);
                const __nv_bfloat16* al_ = Asl + rb;
                al[mr][0] = *(const uint32_t*)al_;
                al[mr][1] = *(const uint32_t*)(al_ + 8 * TS);
                al[mr][2] = *(const uint32_t*)(al_ + 8);
                al[mr][3] = *(const uint32_t*)(al_ + 8 * TS + 8);
            }
            #pragma unroll
            for (int nt = 0; nt < 8; ++nt) {
                const int cb = (wcol + nt * 8 + g) * TS + k0 + 2 * q;
                // Bh pass: (Ah + Am + Al) x Bh
                {
                    const __nv_bfloat16* br = Bsh + cb;
                    uint32_t b0 = *(const uint32_t*)br;
                    uint32_t b1 = *(const uint32_t*)(br + 8);
                    #pragma unroll
                    for (int mr = 0; mr < MR; ++mr) {
                        mma_bf16(acc[mr][nt], ah[mr], b0, b1);
                        mma_bf16(acc[mr][nt], am[mr], b0, b1);
                        mma_bf16(acc[mr][nt], al[mr], b0, b1);
                    }
                }
                // Bm pass: (Ah + Am) x Bm
                {
                    const __nv_bfloat16* br = Bsm + cb;
                    uint32_t b0 = *(const uint32_t*)br;
                    uint32_t b1 = *(const uint32_t*)(br + 8);
                    #pragma unroll
                    for (int mr = 0; mr < MR; ++mr) {
                        mma_bf16(acc[mr][nt], ah[mr], b0, b1);
                        mma_bf16(acc[mr][nt], am[mr], b0, b1);
                    }
                }
                // Bl pass: Ah x Bl
                {
                    const __nv_bfloat16* br = Bsl + cb;
                    uint32_t b0 = *(const uint32_t*)br;
                    uint32_t b1 = *(const uint32_t*)(br + 8);
                    #pragma unroll
                    for (int mr = 0; mr < MR; ++mr)
                        mma_bf16(acc[mr][nt], ah[mr], b0, b1);
                }
            }
        }
        __syncthreads();   // tiles free for reuse / P overlay
    }

    // ============ epilogue: accumulators -> P (overlays tiles) ============
    #pragma unroll
    for (int mr = 0; mr < MR; ++mr) {
        #pragma unroll
        for (int nt = 0; nt < 8; ++nt) {
            int r0 = wrow + mr * 16 + g;
            int col = wcol + nt * 8 + 2 * q;
            *(float2*)&P[r0 * PS + col]       = make_float2(acc[mr][nt][0], acc[mr][nt][1]);
            *(float2*)&P[(r0 + 8) * PS + col] = make_float2(acc[mr][nt][2], acc[mr][nt][3]);
        }
    }
    __syncthreads();

    // ============ dynamic routing (3 iterations) ============
    if (tid < M) logits[tid] = 0.0f;

    for (int it = 0; it < 3; ++it) {
        if (it == 0) {
            if (tid < M) probs[tid] = 1.0f / (float)M;
        } else {
            float lv = (tid < M) ? logits[tid] : -3.402823466e38f;
            float mx = blockMax(lv, red);
            float ev = (tid < M) ? expf(lv - mx) : 0.0f;
            float Z = blockSum(ev, red);
            if (tid < M) probs[tid] = ev / Z;
        }
        __syncthreads();

        // s[d] = sum_b probs[b] * P[b][d]
        {
            int d = tid & 255, hf = tid >> 8;
            int b0 = hf * (M / 2);
            float a = 0.0f;
            #pragma unroll 8
            for (int b = 0; b < M / 2; ++b)
                a = fmaf(probs[b0 + b], P[(b0 + b) * PS + d], a);
            part[tid] = a;
        }
        __syncthreads();
        float sd = 0.0f;
        if (tid < 256) sd = part[tid] + part[tid + 256];

        float sq = blockSum(sd * sd, red);
        float scale = sq / ((1.0f + sq) * sqrtf(sq));
        if (tid < 256) vout[tid] = sd * scale;
        __syncthreads();

        if (it < 2) {
            constexpr int RPW = M / 16;
            #pragma unroll
            for (int rr = 0; rr < RPW; ++rr) {
                int r = wid * RPW + rr;
                float a = 0.0f;
                #pragma unroll
                for (int k = 0; k < 8; ++k)
                    a = fmaf(P[r * PS + k * 32 + lane], vout[k * 32 + lane], a);
                a = warpSum(a);
                if (lane == 0) logits[r] += a;
            }
            __syncthreads();
        } else {
            if (tid < 256) {
                float v = vout[tid];
                size_t o = (size_t)blockIdx.x * outXStride + (size_t)blockIdx.y * outYStride + tid;
                if (F32OUT) {
                    OutF[o] = v;
                } else {
                    __nv_bfloat16 h, m, l;
                    split3(v, h, m, l);
                    OutH[o] = h; OutM[o] = m; OutL[o] = l;
                }
            }
        }
    }
}

static size_t stage_smem(int M) {
    size_t tiles = 3ull * M * 72 * 2 + 3ull * 256 * 72 * 2;
    size_t pbytes = (size_t)M * 258 * 4;
    size_t scr = ((size_t)M + M + 256 + 512 + 64) * 4;
    return (tiles > pbytes ? tiles : pbytes) + scr;
}

extern "C" void kernel_launch(void* const* d_in, const int* in_sizes, int n_in,
                              void* d_out, int out_size) {
    (void)in_sizes; (void)n_in; (void)out_size;
    const float* x  = (const float*)d_in[0];   // [64,128,256]
    const float* w1 = (const float*)d_in[1];   // [64,256,256]
    const float* w2 = (const float*)d_in[2];   // [32,256,256]
    float* out = (float*)d_out;                // [32,64,256]

    void* p;
    cudaGetSymbolAddress(&p, g_xh);  __nv_bfloat16* xh  = (__nv_bfloat16*)p;
    cudaGetSymbolAddress(&p, g_xm);  __nv_bfloat16* xm  = (__nv_bfloat16*)p;
    cudaGetSymbolAddress(&p, g_xl);  __nv_bfloat16* xl  = (__nv_bfloat16*)p;
    cudaGetSymbolAddress(&p, g_w1h); __nv_bfloat16* w1h = (__nv_bfloat16*)p;
    cudaGetSymbolAddress(&p, g_w1m); __nv_bfloat16* w1m = (__nv_bfloat16*)p;
    cudaGetSymbolAddress(&p, g_w1l); __nv_bfloat16* w1l = (__nv_bfloat16*)p;
    cudaGetSymbolAddress(&p, g_w2h); __nv_bfloat16* w2h = (__nv_bfloat16*)p;
    cudaGetSymbolAddress(&p, g_w2m); __nv_bfloat16* w2m = (__nv_bfloat16*)p;
    cudaGetSymbolAddress(&p, g_w2l); __nv_bfloat16* w2l = (__nv_bfloat16*)p;
    cudaGetSymbolAddress(&p, g_o1h); __nv_bfloat16* o1h = (__nv_bfloat16*)p;
    cudaGetSymbolAddress(&p, g_o1m); __nv_bfloat16* o1m = (__nv_bfloat16*)p;
    cudaGetSymbolAddress(&p, g_o1l); __nv_bfloat16* o1l = (__nv_bfloat16*)p;

    // pre-pass: 3-level bf16 splits (+ W transposed to [n][k])
    split_x_kernel<<<8192, 256>>>(x, xh, xm, xl, 64 * 128 * 256);
    trans_split_w<<<dim3(8, 8, 64), 256>>>(w1, w1h, w1m, w1l);
    trans_split_w<<<dim3(8, 8, 32), 256>>>(w2, w2h, w2m, w2l);

    const size_t sm1 = stage_smem(128);   // ~166 KB
    const size_t sm2 = stage_smem(64);    // ~139 KB
    cudaFuncSetAttribute(caps_mma_route<128, false>,
                         cudaFuncAttributeMaxDynamicSharedMemorySize, (int)sm1);
    cudaFuncSetAttribute(caps_mma_route<64, true>,
                         cudaFuncAttributeMaxDynamicSharedMemorySize, (int)sm2);

    // Stage 1: (a=64, h=64) -> out1 3-level bf16 [a][h][256]
    caps_mma_route<128, false><<<dim3(64, 64), 512, sm1>>>(
        xh, xm, xl, w1h, w1m, w1l, nullptr, o1h, o1m, o1l,
        /*x=a*/ 64 * 256, /*y=h*/ 256);

    // Stage 2: (a=64, c=32) -> out fp32 [c][a][256]
    caps_mma_route<64, true><<<dim3(64, 32), 512, sm2>>>(
        o1h, o1m, o1l, w2h, w2m, w2l, out, nullptr, nullptr, nullptr,
        /*x=a*/ 256, /*y=c*/ 64 * 256);
}

// round 9
// speedup vs baseline: 1.5951x; 1.1630x over previous
#include <cuda_runtime.h>
#include <cuda_bf16.h>
#include <math.h>
#include <stdint.h>

// ---------------- device globals (no allocations allowed) ----------------
// 3-level bf16 splits: v = vh + vm + vl (each level bf16)
__device__ __nv_bfloat16 g_xh[64 * 128 * 256], g_xm[64 * 128 * 256], g_xl[64 * 128 * 256];
__device__ __nv_bfloat16 g_w1h[64 * 256 * 256], g_w1m[64 * 256 * 256], g_w1l[64 * 256 * 256];
__device__ __nv_bfloat16 g_w2h[32 * 256 * 256], g_w2m[32 * 256 * 256], g_w2l[32 * 256 * 256];
__device__ __nv_bfloat16 g_o1h[64 * 64 * 256], g_o1m[64 * 64 * 256], g_o1l[64 * 64 * 256];

// ---------------- bf16 HMMA via mma.sync (sm_80+ baseline PTX) ----------------
__device__ __forceinline__ void mma_bf16(float* c, const uint32_t* a, uint32_t b0, uint32_t b1) {
    asm volatile(
        "mma.sync.aligned.m16n8k16.row.col.f32.bf16.bf16.f32 "
        "{%0,%1,%2,%3}, {%4,%5,%6,%7}, {%8,%9}, {%0,%1,%2,%3};"
        : "+f"(c[0]), "+f"(c[1]), "+f"(c[2]), "+f"(c[3])
        : "r"(a[0]), "r"(a[1]), "r"(a[2]), "r"(a[3]), "r"(b0), "r"(b1));
}

// ---------------- cp.async helpers (sm_80+ baseline PTX) ----------------
__device__ __forceinline__ void cp16(uint32_t smem_dst, const void* gsrc) {
    asm volatile("cp.async.cg.shared.global [%0], [%1], 16;" :: "r"(smem_dst), "l"(gsrc));
}
__device__ __forceinline__ void cp_commit() {
    asm volatile("cp.async.commit_group;");
}
template<int N>
__device__ __forceinline__ void cp_wait() {
    asm volatile("cp.async.wait_group %0;" :: "n"(N));
}
__device__ __forceinline__ uint32_t smem_u32(const void* p) {
    uint32_t a;
    asm("{ .reg .u64 t; cvta.to.shared.u64 t, %1; cvt.u32.u64 %0, t; }" : "=r"(a) : "l"(p));
    return a;
}

// ---------------- block reductions over 512 threads (16 warps) ----------------
__device__ __forceinline__ float warpSum(float v) {
    #pragma unroll
    for (int o = 16; o; o >>= 1) v += __shfl_down_sync(0xffffffffu, v, o);
    return v;
}
__device__ __forceinline__ float warpMax(float v) {
    #pragma unroll
    for (int o = 16; o; o >>= 1) v = fmaxf(v, __shfl_down_sync(0xffffffffu, v, o));
    return v;
}
__device__ __forceinline__ float blockSum(float v, float* red) {
    v = warpSum(v);
    __syncthreads();
    if ((threadIdx.x & 31) == 0) red[threadIdx.x >> 5] = v;
    __syncthreads();
    if (threadIdx.x < 32) {
        float x = (threadIdx.x < 16) ? red[threadIdx.x] : 0.0f;
        x = warpSum(x);
        if (threadIdx.x == 0) red[32] = x;
    }
    __syncthreads();
    return red[32];
}
__device__ __forceinline__ float blockMax(float v, float* red) {
    v = warpMax(v);
    __syncthreads();
    if ((threadIdx.x & 31) == 0) red[threadIdx.x >> 5] = v;
    __syncthreads();
    if (threadIdx.x < 32) {
        float x = (threadIdx.x < 16) ? red[threadIdx.x] : -3.402823466e38f;
        x = warpMax(x);
        if (threadIdx.x == 0) red[32] = x;
    }
    __syncthreads();
    return red[32];
}

// 3-level split of a float
__device__ __forceinline__ void split3(float v, __nv_bfloat16& h, __nv_bfloat16& m, __nv_bfloat16& l) {
    h = __float2bfloat16(v);
    float r1 = v - __bfloat162float(h);
    m = __float2bfloat16(r1);
    float r2 = r1 - __bfloat162float(m);
    l = __float2bfloat16(r2);
}

// ---------------- pre-pass: split X into bf16 h/m/l ----------------
__global__ void split_x_kernel(const float* __restrict__ x,
                               __nv_bfloat16* __restrict__ xh,
                               __nv_bfloat16* __restrict__ xm,
                               __nv_bfloat16* __restrict__ xl, int n) {
    int i = blockIdx.x * blockDim.x + threadIdx.x;
    if (i >= n) return;
    __nv_bfloat16 h, m, l;
    split3(x[i], h, m, l);
    xh[i] = h; xm[i] = m; xl[i] = l;
}

// ---------------- pre-pass: transpose + split W[k][n] -> Wt[n][k] bf16 h/m/l ----------------
__global__ void trans_split_w(const float* __restrict__ W,
                              __nv_bfloat16* __restrict__ Wth,
                              __nv_bfloat16* __restrict__ Wtm,
                              __nv_bfloat16* __restrict__ Wtl) {
    __shared__ float st[32][33];
    int mb = blockIdx.z, k0 = blockIdx.x * 32, n0 = blockIdx.y * 32;
    const float* Wm = W + (size_t)mb * 65536;
    int tid = threadIdx.x;
    #pragma unroll
    for (int i = 0; i < 4; ++i) {
        int e = tid + i * 256, k = e >> 5, n = e & 31;
        st[k][n] = Wm[(k0 + k) * 256 + n0 + n];
    }
    __syncthreads();
    #pragma unroll
    for (int i = 0; i < 4; ++i) {
        int e = tid + i * 256, n = e >> 5, k = e & 31;
        float f = st[k][n];
        __nv_bfloat16 h, m, l;
        split3(f, h, m, l);
        size_t o = (size_t)mb * 65536 + (size_t)(n0 + n) * 256 + k0 + k;
        Wth[o] = h; Wtm[o] = m; Wtl[o] = l;
    }
}

// ---------------- fused HMMA-GEMM + routing kernel (cp.async pipelined) ----------------
// One CTA = one (weight, batch) pair.
//   P[M,256] = A[M,256] @ B^T via 6-term 3-level bf16 split,
//   K-chunks of 32 double-buffered through cp.async; fp32 accumulators;
//   then 3 routing iterations on P in SMEM (P overlays the tile buffers).
// 16 warps: 4 row-groups x 4 col-groups; warp tile (M/4) x 64.
template<int M, bool F32OUT>
__global__ void __launch_bounds__(512)
caps_mma_route(const __nv_bfloat16* __restrict__ AhG, const __nv_bfloat16* __restrict__ AmG,
               const __nv_bfloat16* __restrict__ AlG,
               const __nv_bfloat16* __restrict__ BhG, const __nv_bfloat16* __restrict__ BmG,
               const __nv_bfloat16* __restrict__ BlG,
               float* __restrict__ OutF,
               __nv_bfloat16* __restrict__ OutH, __nv_bfloat16* __restrict__ OutM,
               __nv_bfloat16* __restrict__ OutL,
               int outXStride, int outYStride)
{
    constexpr int PS = 258;              // padded P row stride (floats)
    constexpr int KC = 32;               // k-chunk
    constexpr int NT = 256 / KC;         // 8 chunks
    constexpr int TS = KC + 8;           // 40 bf16 row stride (80B, 16B-aligned)
    constexpr int MR = M / 64;           // mma row-tiles per warp
    constexpr uint32_t ATB = (uint32_t)M * TS * 2;    // one A level tile bytes
    constexpr uint32_t BTB = 256u * TS * 2;           // one B level tile bytes
    constexpr uint32_t BUF = 3 * ATB + 3 * BTB;       // one pipeline buffer
    constexpr uint32_t PBYTES = (uint32_t)M * PS * 4;
    constexpr uint32_t SCR = (2 * BUF > PBYTES ? 2 * BUF : PBYTES);

    extern __shared__ char smc[];
    const uint32_t smb = smem_u32(smc);
    float* P      = (float*)smc;         // overlays buffers after GEMM
    float* logits = (float*)(smc + SCR);
    float* probs  = logits + M;
    float* vout   = probs + M;
    float* part   = vout + 256;
    float* red    = part + 512;

    const int tid = threadIdx.x;
    const int wid = tid >> 5, lane = tid & 31;
    const int g = lane >> 2, q = lane & 3;           // mma fragment coords
    const int wrow = (wid >> 2) * (M / 4);           // warp row base
    const int wcol = (wid & 3) * 64;                 // warp col base

    const size_t aOff = (size_t)blockIdx.x * (M * 256);
    const size_t bOff = (size_t)blockIdx.y * 65536u;
    const __nv_bfloat16* Asrc[3] = { AhG + aOff, AmG + aOff, AlG + aOff };
    const __nv_bfloat16* Bsrc[3] = { BhG + bOff, BmG + bOff, BlG + bOff };

    // -------- async tile loader: chunk t -> buffer at byte offset bb --------
    auto load_chunk = [&](uint32_t bb, int t) {
        const int k0g = t * KC;
        #pragma unroll
        for (int lv = 0; lv < 3; ++lv) {
            const __nv_bfloat16* src = Asrc[lv] + k0g;
            uint32_t dstb = smb + bb + lv * ATB;
            #pragma unroll
            for (int e = tid; e < M * 4; e += 512) {
                int r = e >> 2, seg = e & 3;
                cp16(dstb + (uint32_t)(r * TS + seg * 8) * 2, src + r * 256 + seg * 8);
            }
        }
        #pragma unroll
        for (int lv = 0; lv < 3; ++lv) {
            const __nv_bfloat16* src = Bsrc[lv] + k0g;
            uint32_t dstb = smb + bb + 3 * ATB + lv * BTB;
            #pragma unroll
            for (int e = tid; e < 1024; e += 512) {
                int r = e >> 2, seg = e & 3;
                cp16(dstb + (uint32_t)(r * TS + seg * 8) * 2, src + r * 256 + seg * 8);
            }
        }
        cp_commit();
    };

    // ============ GEMM: 8 K-chunks of 32, 6-term 3-level bf16 split ============
    float acc[MR][8][4];
    #pragma unroll
    for (int mr = 0; mr < MR; ++mr)
        #pragma unroll
        for (int nt = 0; nt < 8; ++nt)
            #pragma unroll
            for (int j = 0; j < 4; ++j) acc[mr][nt][j] = 0.0f;

    load_chunk(0, 0);

    for (int t = 0; t < NT; ++t) {
        const uint32_t bb = (t & 1) ? BUF : 0;
        if (t + 1 < NT) {
            load_chunk((t & 1) ? 0 : BUF, t + 1);
            cp_wait<1>();
        } else {
            cp_wait<0>();
        }
        __syncthreads();

        const __nv_bfloat16* Ash  = (const __nv_bfloat16*)(smc + bb);
        const __nv_bfloat16* Asm_ = (const __nv_bfloat16*)(smc + bb + ATB);
        const __nv_bfloat16* Asl  = (const __nv_bfloat16*)(smc + bb + 2 * ATB);
        const __nv_bfloat16* Bsh  = (const __nv_bfloat16*)(smc + bb + 3 * ATB);
        const __nv_bfloat16* Bsm  = (const __nv_bfloat16*)(smc + bb + 3 * ATB + BTB);
        const __nv_bfloat16* Bsl  = (const __nv_bfloat16*)(smc + bb + 3 * ATB + 2 * BTB);

        #pragma unroll
        for (int ks = 0; ks < KC / 16; ++ks) {
            const int k0 = ks * 16;
            uint32_t ah[MR][4], am[MR][4], al[MR][4];
            #pragma unroll
            for (int mr = 0; mr < MR; ++mr) {
                const int rb = (wrow + mr * 16 + g) * TS + k0 + 2 * q;
                const __nv_bfloat16* ar = Ash + rb;
                ah[mr][0] = *(const uint32_t*)ar;
                ah[mr][1] = *(const uint32_t*)(ar + 8 * TS);
                ah[mr][2] = *(const uint32_t*)(ar + 8);
                ah[mr][3] = *(const uint32_t*)(ar + 8 * TS + 8);
                const __nv_bfloat16* am2 = Asm_ + rb;
                am[mr][0] = *(const uint32_t*)am2;
                am[mr][1] = *(const uint32_t*)(am2 + 8 * TS);
                am[mr][2] = *(const uint32_t*)(am2 + 8);
                am[mr][3] = *(const uint32_t*)(am2 + 8 * TS + 8);
                const __nv_bfloat16* al2 = Asl + rb;
                al[mr][0] = *(const uint32_t*)al2;
                al[mr][1] = *(const uint32_t*)(al2 + 8 * TS);
                al[mr][2] = *(const uint32_t*)(al2 + 8);
                al[mr][3] = *(const uint32_t*)(al2 + 8 * TS + 8);
            }
            #pragma unroll
            for (int nt = 0; nt < 8; ++nt) {
                const int cb = (wcol + nt * 8 + g) * TS + k0 + 2 * q;
                {   // Bh pass: (Ah + Am + Al) x Bh
                    const __nv_bfloat16* br = Bsh + cb;
                    uint32_t b0 = *(const uint32_t*)br;
                    uint32_t b1 = *(const uint32_t*)(br + 8);
                    #pragma unroll
                    for (int mr = 0; mr < MR; ++mr) {
                        mma_bf16(acc[mr][nt], ah[mr], b0, b1);
                        mma_bf16(acc[mr][nt], am[mr], b0, b1);
                        mma_bf16(acc[mr][nt], al[mr], b0, b1);
                    }
                }
                {   // Bm pass: (Ah + Am) x Bm
                    const __nv_bfloat16* br = Bsm + cb;
                    uint32_t b0 = *(const uint32_t*)br;
                    uint32_t b1 = *(const uint32_t*)(br + 8);
                    #pragma unroll
                    for (int mr = 0; mr < MR; ++mr) {
                        mma_bf16(acc[mr][nt], ah[mr], b0, b1);
                        mma_bf16(acc[mr][nt], am[mr], b0, b1);
                    }
                }
                {   // Bl pass: Ah x Bl
                    const __nv_bfloat16* br = Bsl + cb;
                    uint32_t b0 = *(const uint32_t*)br;
                    uint32_t b1 = *(const uint32_t*)(br + 8);
                    #pragma unroll
                    for (int mr = 0; mr < MR; ++mr)
                        mma_bf16(acc[mr][nt], ah[mr], b0, b1);
                }
            }
        }
        __syncthreads();   // all warps done with this buffer before it is refilled
    }

    // ============ epilogue: accumulators -> P (overlays tile buffers) ============
    #pragma unroll
    for (int mr = 0; mr < MR; ++mr) {
        #pragma unroll
        for (int nt = 0; nt < 8; ++nt) {
            int r0 = wrow + mr * 16 + g;
            int col = wcol + nt * 8 + 2 * q;
            *(float2*)&P[r0 * PS + col]       = make_float2(acc[mr][nt][0], acc[mr][nt][1]);
            *(float2*)&P[(r0 + 8) * PS + col] = make_float2(acc[mr][nt][2], acc[mr][nt][3]);
        }
    }
    __syncthreads();

    // ============ dynamic routing (3 iterations) ============
    if (tid < M) logits[tid] = 0.0f;

    for (int it = 0; it < 3; ++it) {
        if (it == 0) {
            if (tid < M) probs[tid] = 1.0f / (float)M;
        } else {
            float lv = (tid < M) ? logits[tid] : -3.402823466e38f;
            float mx = blockMax(lv, red);
            float ev = (tid < M) ? expf(lv - mx) : 0.0f;
            float Z = blockSum(ev, red);
            if (tid < M) probs[tid] = ev / Z;
        }
        __syncthreads();

        // s[d] = sum_b probs[b] * P[b][d]
        {
            int d = tid & 255, hf = tid >> 8;
            int b0 = hf * (M / 2);
            float a = 0.0f;
            #pragma unroll 8
            for (int b = 0; b < M / 2; ++b)
                a = fmaf(probs[b0 + b], P[(b0 + b) * PS + d], a);
            part[tid] = a;
        }
        __syncthreads();
        float sd = 0.0f;
        if (tid < 256) sd = part[tid] + part[tid + 256];

        float sq = blockSum(sd * sd, red);
        float scale = sq / ((1.0f + sq) * sqrtf(sq));
        if (tid < 256) vout[tid] = sd * scale;
        __syncthreads();

        if (it < 2) {
            constexpr int RPW = M / 16;
            #pragma unroll
            for (int rr = 0; rr < RPW; ++rr) {
                int r = wid * RPW + rr;
                float a = 0.0f;
                #pragma unroll
                for (int k = 0; k < 8; ++k)
                    a = fmaf(P[r * PS + k * 32 + lane], vout[k * 32 + lane], a);
                a = warpSum(a);
                if (lane == 0) logits[r] += a;
            }
            __syncthreads();
        } else {
            if (tid < 256) {
                float v = vout[tid];
                size_t o = (size_t)blockIdx.x * outXStride + (size_t)blockIdx.y * outYStride + tid;
                if (F32OUT) {
                    OutF[o] = v;
                } else {
                    __nv_bfloat16 h, m, l;
                    split3(v, h, m, l);
                    OutH[o] = h; OutM[o] = m; OutL[o] = l;
                }
            }
        }
    }
}

static size_t stage_smem(int M) {
    size_t buf = 3ull * M * 40 * 2 + 3ull * 256 * 40 * 2;   // one pipeline buffer
    size_t pbytes = (size_t)M * 258 * 4;
    size_t body = (2 * buf > pbytes ? 2 * buf : pbytes);
    size_t scr = ((size_t)M + M + 256 + 512 + 64) * 4;
    return body + scr;
}

extern "C" void kernel_launch(void* const* d_in, const int* in_sizes, int n_in,
                              void* d_out, int out_size) {
    (void)in_sizes; (void)n_in; (void)out_size;
    const float* x  = (const float*)d_in[0];   // [64,128,256]
    const float* w1 = (const float*)d_in[1];   // [64,256,256]
    const float* w2 = (const float*)d_in[2];   // [32,256,256]
    float* out = (float*)d_out;                // [32,64,256]

    void* p;
    cudaGetSymbolAddress(&p, g_xh);  __nv_bfloat16* xh  = (__nv_bfloat16*)p;
    cudaGetSymbolAddress(&p, g_xm);  __nv_bfloat16* xm  = (__nv_bfloat16*)p;
    cudaGetSymbolAddress(&p, g_xl);  __nv_bfloat16* xl  = (__nv_bfloat16*)p;
    cudaGetSymbolAddress(&p, g_w1h); __nv_bfloat16* w1h = (__nv_bfloat16*)p;
    cudaGetSymbolAddress(&p, g_w1m); __nv_bfloat16* w1m = (__nv_bfloat16*)p;
    cudaGetSymbolAddress(&p, g_w1l); __nv_bfloat16* w1l = (__nv_bfloat16*)p;
    cudaGetSymbolAddress(&p, g_w2h); __nv_bfloat16* w2h = (__nv_bfloat16*)p;
    cudaGetSymbolAddress(&p, g_w2m); __nv_bfloat16* w2m = (__nv_bfloat16*)p;
    cudaGetSymbolAddress(&p, g_w2l); __nv_bfloat16* w2l = (__nv_bfloat16*)p;
    cudaGetSymbolAddress(&p, g_o1h); __nv_bfloat16* o1h = (__nv_bfloat16*)p;
    cudaGetSymbolAddress(&p, g_o1m); __nv_bfloat16* o1m = (__nv_bfloat16*)p;
    cudaGetSymbolAddress(&p, g_o1l); __nv_bfloat16* o1l = (__nv_bfloat16*)p;

    // pre-pass: 3-level bf16 splits (+ W transposed to [n][k])
    split_x_kernel<<<8192, 256>>>(x, xh, xm, xl, 64 * 128 * 256);
    trans_split_w<<<dim3(8, 8, 64), 256>>>(w1, w1h, w1m, w1l);
    trans_split_w<<<dim3(8, 8, 32), 256>>>(w2, w2h, w2m, w2l);

    const size_t sm1 = stage_smem(128);   // ~188 KB
    const size_t sm2 = stage_smem(64);    // ~157 KB
    cudaFuncSetAttribute(caps_mma_route<128, false>,
                         cudaFuncAttributeMaxDynamicSharedMemorySize, (int)sm1);
    cudaFuncSetAttribute(caps_mma_route<64, true>,
                         cudaFuncAttributeMaxDynamicSharedMemorySize, (int)sm2);

    // Stage 1: (a=64, h=64) -> out1 3-level bf16 [a][h][256]
    caps_mma_route<128, false><<<dim3(64, 64), 512, sm1>>>(
        xh, xm, xl, w1h, w1m, w1l, nullptr, o1h, o1m, o1l,
        /*x=a*/ 64 * 256, /*y=h*/ 256);

    // Stage 2: (a=64, c=32) -> out fp32 [c][a][256]
    caps_mma_route<64, true><<<dim3(64, 32), 512, sm2>>>(
        o1h, o1m, o1l, w2h, w2m, w2l, out, nullptr, nullptr, nullptr,
        /*x=a*/ 256, /*y=c*/ 64 * 256);
}

// round 10
// speedup vs baseline: 1.7139x; 1.0745x over previous
#include <cuda_runtime.h>
#include <cuda_bf16.h>
#include <math.h>
#include <stdint.h>

// ---------------- device globals (no allocations allowed) ----------------
// 3-level bf16 splits: v = vh + vm + vl (each level bf16)
__device__ __nv_bfloat16 g_xh[64 * 128 * 256], g_xm[64 * 128 * 256], g_xl[64 * 128 * 256];
__device__ __nv_bfloat16 g_w1h[64 * 256 * 256], g_w1m[64 * 256 * 256], g_w1l[64 * 256 * 256];
__device__ __nv_bfloat16 g_w2h[32 * 256 * 256], g_w2m[32 * 256 * 256], g_w2l[32 * 256 * 256];
__device__ __nv_bfloat16 g_o1h[64 * 64 * 256], g_o1m[64 * 64 * 256], g_o1l[64 * 64 * 256];

// ---------------- bf16 HMMA via mma.sync (sm_80+ baseline PTX) ----------------
__device__ __forceinline__ void mma_bf16(float* c, const uint32_t* a, uint32_t b0, uint32_t b1) {
    asm volatile(
        "mma.sync.aligned.m16n8k16.row.col.f32.bf16.bf16.f32 "
        "{%0,%1,%2,%3}, {%4,%5,%6,%7}, {%8,%9}, {%0,%1,%2,%3};"
        : "+f"(c[0]), "+f"(c[1]), "+f"(c[2]), "+f"(c[3])
        : "r"(a[0]), "r"(a[1]), "r"(a[2]), "r"(a[3]), "r"(b0), "r"(b1));
}

// ---------------- cp.async helpers (sm_80+ baseline PTX) ----------------
__device__ __forceinline__ void cp16(uint32_t smem_dst, const void* gsrc) {
    asm volatile("cp.async.cg.shared.global [%0], [%1], 16;" :: "r"(smem_dst), "l"(gsrc));
}
__device__ __forceinline__ void cp_commit() {
    asm volatile("cp.async.commit_group;");
}
template<int N>
__device__ __forceinline__ void cp_wait() {
    asm volatile("cp.async.wait_group %0;" :: "n"(N));
}
__device__ __forceinline__ uint32_t smem_u32(const void* p) {
    uint32_t a;
    asm("{ .reg .u64 t; cvta.to.shared.u64 t, %1; cvt.u32.u64 %0, t; }" : "=r"(a) : "l"(p));
    return a;
}

// ---------------- block reductions over 512 threads (16 warps) ----------------
__device__ __forceinline__ float warpSum(float v) {
    #pragma unroll
    for (int o = 16; o; o >>= 1) v += __shfl_down_sync(0xffffffffu, v, o);
    return v;
}
__device__ __forceinline__ float warpMax(float v) {
    #pragma unroll
    for (int o = 16; o; o >>= 1) v = fmaxf(v, __shfl_down_sync(0xffffffffu, v, o));
    return v;
}
__device__ __forceinline__ float blockSum(float v, float* red) {
    v = warpSum(v);
    __syncthreads();
    if ((threadIdx.x & 31) == 0) red[threadIdx.x >> 5] = v;
    __syncthreads();
    if (threadIdx.x < 32) {
        float x = (threadIdx.x < 16) ? red[threadIdx.x] : 0.0f;
        x = warpSum(x);
        if (threadIdx.x == 0) red[32] = x;
    }
    __syncthreads();
    return red[32];
}
__device__ __forceinline__ float blockMax(float v, float* red) {
    v = warpMax(v);
    __syncthreads();
    if ((threadIdx.x & 31) == 0) red[threadIdx.x >> 5] = v;
    __syncthreads();
    if (threadIdx.x < 32) {
        float x = (threadIdx.x < 16) ? red[threadIdx.x] : -3.402823466e38f;
        x = warpMax(x);
        if (threadIdx.x == 0) red[32] = x;
    }
    __syncthreads();
    return red[32];
}

// 3-level split of a float
__device__ __forceinline__ void split3(float v, __nv_bfloat16& h, __nv_bfloat16& m, __nv_bfloat16& l) {
    h = __float2bfloat16(v);
    float r1 = v - __bfloat162float(h);
    m = __float2bfloat16(r1);
    float r2 = r1 - __bfloat162float(m);
    l = __float2bfloat16(r2);
}

// ---------------- pre-pass: split X into bf16 h/m/l ----------------
__global__ void split_x_kernel(const float* __restrict__ x,
                               __nv_bfloat16* __restrict__ xh,
                               __nv_bfloat16* __restrict__ xm,
                               __nv_bfloat16* __restrict__ xl, int n) {
    int i = blockIdx.x * blockDim.x + threadIdx.x;
    if (i >= n) return;
    __nv_bfloat16 h, m, l;
    split3(x[i], h, m, l);
    xh[i] = h; xm[i] = m; xl[i] = l;
}

// ---------------- pre-pass: transpose + split W[k][n] -> Wt[n][k] bf16 h/m/l ----------------
__global__ void trans_split_w(const float* __restrict__ W,
                              __nv_bfloat16* __restrict__ Wth,
                              __nv_bfloat16* __restrict__ Wtm,
                              __nv_bfloat16* __restrict__ Wtl) {
    __shared__ float st[32][33];
    int mb = blockIdx.z, k0 = blockIdx.x * 32, n0 = blockIdx.y * 32;
    const float* Wm = W + (size_t)mb * 65536;
    int tid = threadIdx.x;
    #pragma unroll
    for (int i = 0; i < 4; ++i) {
        int e = tid + i * 256, k = e >> 5, n = e & 31;
        st[k][n] = Wm[(k0 + k) * 256 + n0 + n];
    }
    __syncthreads();
    #pragma unroll
    for (int i = 0; i < 4; ++i) {
        int e = tid + i * 256, n = e >> 5, k = e & 31;
        float f = st[k][n];
        __nv_bfloat16 h, m, l;
        split3(f, h, m, l);
        size_t o = (size_t)mb * 65536 + (size_t)(n0 + n) * 256 + k0 + k;
        Wth[o] = h; Wtm[o] = m; Wtl[o] = l;
    }
}

// ---------------- fused HMMA-GEMM + register-resident routing ----------------
// One CTA = one (weight, batch) pair.
//   P[M,256] = A[M,256] @ B^T via 6-term 3-level bf16 split, cp.async
//   double-buffered; P stays entirely in the mma accumulators; routing
//   is done via shfl reductions + a small smem combine buffer.
// 16 warps: 4 row-groups x 4 col-groups; warp tile (M/4) x 64.
template<int M, bool F32OUT>
__global__ void __launch_bounds__(512)
caps_mma_route(const __nv_bfloat16* __restrict__ AhG, const __nv_bfloat16* __restrict__ AmG,
               const __nv_bfloat16* __restrict__ AlG,
               const __nv_bfloat16* __restrict__ BhG, const __nv_bfloat16* __restrict__ BmG,
               const __nv_bfloat16* __restrict__ BlG,
               float* __restrict__ OutF,
               __nv_bfloat16* __restrict__ OutH, __nv_bfloat16* __restrict__ OutM,
               __nv_bfloat16* __restrict__ OutL,
               int outXStride, int outYStride)
{
    constexpr int KC = 32;               // k-chunk
    constexpr int NT = 256 / KC;         // 8 chunks
    constexpr int TS = KC + 8;           // 40 bf16 row stride (80B, 16B-aligned)
    constexpr int MR = M / 64;           // mma row-tiles per warp
    constexpr uint32_t ATB = (uint32_t)M * TS * 2;    // one A level tile bytes
    constexpr uint32_t BTB = 256u * TS * 2;           // one B level tile bytes
    constexpr uint32_t BUF = 3 * ATB + 3 * BTB;       // one pipeline buffer
    constexpr uint32_t SCR = 2 * BUF;

    extern __shared__ char smc[];
    const uint32_t smb = smem_u32(smc);
    float* part   = (float*)(smc + SCR);   // 1024 floats (4 x 256 combine buffer)
    float* vout   = part + 1024;           // 256
    float* probs  = vout + 256;            // M
    float* logits = probs + M;             // M
    float* red    = logits + M;            // 64

    const int tid = threadIdx.x;
    const int wid = tid >> 5, lane = tid & 31;
    const int g = lane >> 2, q = lane & 3;           // mma fragment coords
    const int rg = wid >> 2, cg = wid & 3;           // row-group / col-group
    const int wrow = rg * (M / 4);                   // warp row base
    const int wcol = cg * 64;                        // warp col base

    const size_t aOff = (size_t)blockIdx.x * (M * 256);
    const size_t bOff = (size_t)blockIdx.y * 65536u;
    const __nv_bfloat16* Asrc[3] = { AhG + aOff, AmG + aOff, AlG + aOff };
    const __nv_bfloat16* Bsrc[3] = { BhG + bOff, BmG + bOff, BlG + bOff };

    // -------- async tile loader: chunk t -> buffer at byte offset bb --------
    auto load_chunk = [&](uint32_t bb, int t) {
        const int k0g = t * KC;
        #pragma unroll
        for (int lv = 0; lv < 3; ++lv) {
            const __nv_bfloat16* src = Asrc[lv] + k0g;
            uint32_t dstb = smb + bb + lv * ATB;
            #pragma unroll
            for (int e = tid; e < M * 4; e += 512) {
                int r = e >> 2, seg = e & 3;
                cp16(dstb + (uint32_t)(r * TS + seg * 8) * 2, src + r * 256 + seg * 8);
            }
        }
        #pragma unroll
        for (int lv = 0; lv < 3; ++lv) {
            const __nv_bfloat16* src = Bsrc[lv] + k0g;
            uint32_t dstb = smb + bb + 3 * ATB + lv * BTB;
            #pragma unroll
            for (int e = tid; e < 1024; e += 512) {
                int r = e >> 2, seg = e & 3;
                cp16(dstb + (uint32_t)(r * TS + seg * 8) * 2, src + r * 256 + seg * 8);
            }
        }
        cp_commit();
    };

    // ============ GEMM: 8 K-chunks of 32, 6-term 3-level bf16 split ============
    float acc[MR][8][4];
    #pragma unroll
    for (int mr = 0; mr < MR; ++mr)
        #pragma unroll
        for (int nt = 0; nt < 8; ++nt)
            #pragma unroll
            for (int j = 0; j < 4; ++j) acc[mr][nt][j] = 0.0f;

    load_chunk(0, 0);

    for (int t = 0; t < NT; ++t) {
        const uint32_t bb = (t & 1) ? BUF : 0;
        if (t + 1 < NT) {
            load_chunk((t & 1) ? 0 : BUF, t + 1);
            cp_wait<1>();
        } else {
            cp_wait<0>();
        }
        __syncthreads();

        const __nv_bfloat16* Ash  = (const __nv_bfloat16*)(smc + bb);
        const __nv_bfloat16* Asm_ = (const __nv_bfloat16*)(smc + bb + ATB);
        const __nv_bfloat16* Asl  = (const __nv_bfloat16*)(smc + bb + 2 * ATB);
        const __nv_bfloat16* Bsh  = (const __nv_bfloat16*)(smc + bb + 3 * ATB);
        const __nv_bfloat16* Bsm  = (const __nv_bfloat16*)(smc + bb + 3 * ATB + BTB);
        const __nv_bfloat16* Bsl  = (const __nv_bfloat16*)(smc + bb + 3 * ATB + 2 * BTB);

        #pragma unroll
        for (int ks = 0; ks < KC / 16; ++ks) {
            const int k0 = ks * 16;
            uint32_t ah[MR][4], am[MR][4], al[MR][4];
            #pragma unroll
            for (int mr = 0; mr < MR; ++mr) {
                const int rb = (wrow + mr * 16 + g) * TS + k0 + 2 * q;
                const __nv_bfloat16* ar = Ash + rb;
                ah[mr][0] = *(const uint32_t*)ar;
                ah[mr][1] = *(const uint32_t*)(ar + 8 * TS);
                ah[mr][2] = *(const uint32_t*)(ar + 8);
                ah[mr][3] = *(const uint32_t*)(ar + 8 * TS + 8);
                const __nv_bfloat16* am2 = Asm_ + rb;
                am[mr][0] = *(const uint32_t*)am2;
                am[mr][1] = *(const uint32_t*)(am2 + 8 * TS);
                am[mr][2] = *(const uint32_t*)(am2 + 8);
                am[mr][3] = *(const uint32_t*)(am2 + 8 * TS + 8);
                const __nv_bfloat16* al2 = Asl + rb;
                al[mr][0] = *(const uint32_t*)al2;
                al[mr][1] = *(const uint32_t*)(al2 + 8 * TS);
                al[mr][2] = *(const uint32_t*)(al2 + 8);
                al[mr][3] = *(const uint32_t*)(al2 + 8 * TS + 8);
            }
            #pragma unroll
            for (int nt = 0; nt < 8; ++nt) {
                const int cb = (wcol + nt * 8 + g) * TS + k0 + 2 * q;
                {   // Bh pass: (Ah + Am + Al) x Bh
                    const __nv_bfloat16* br = Bsh + cb;
                    uint32_t b0 = *(const uint32_t*)br;
                    uint32_t b1 = *(const uint32_t*)(br + 8);
                    #pragma unroll
                    for (int mr = 0; mr < MR; ++mr) {
                        mma_bf16(acc[mr][nt], ah[mr], b0, b1);
                        mma_bf16(acc[mr][nt], am[mr], b0, b1);
                        mma_bf16(acc[mr][nt], al[mr], b0, b1);
                    }
                }
                {   // Bm pass: (Ah + Am) x Bm
                    const __nv_bfloat16* br = Bsm + cb;
                    uint32_t b0 = *(const uint32_t*)br;
                    uint32_t b1 = *(const uint32_t*)(br + 8);
                    #pragma unroll
                    for (int mr = 0; mr < MR; ++mr) {
                        mma_bf16(acc[mr][nt], ah[mr], b0, b1);
                        mma_bf16(acc[mr][nt], am[mr], b0, b1);
                    }
                }
                {   // Bl pass: Ah x Bl
                    const __nv_bfloat16* br = Bsl + cb;
                    uint32_t b0 = *(const uint32_t*)br;
                    uint32_t b1 = *(const uint32_t*)(br + 8);
                    #pragma unroll
                    for (int mr = 0; mr < MR; ++mr)
                        mma_bf16(acc[mr][nt], ah[mr], b0, b1);
                }
            }
        }
        __syncthreads();   // all warps done with this buffer before refill
    }

    // ============ routing directly on register accumulators ============
    // acc[mr][nt][0,1] -> row (wrow+mr*16+g),   cols wcol+nt*8+2q+{0,1}
    // acc[mr][nt][2,3] -> row (wrow+mr*16+g+8), same cols
    if (tid < M) logits[tid] = 0.0f;

    for (int it = 0; it < 3; ++it) {
        // ---- probs = softmax(logits) ----
        if (it == 0) {
            if (tid < M) probs[tid] = 1.0f / (float)M;
        } else {
            float lv = (tid < M) ? logits[tid] : -3.402823466e38f;
            float mx = blockMax(lv, red);
            float ev = (tid < M) ? expf(lv - mx) : 0.0f;
            float Z = blockSum(ev, red);
            if (tid < M) probs[tid] = ev / Z;
        }
        __syncthreads();

        // ---- s[d] = sum_b probs[b] * P[b][d] from registers ----
        {
            float pr[MR][2];
            #pragma unroll
            for (int mr = 0; mr < MR; ++mr) {
                pr[mr][0] = probs[wrow + mr * 16 + g];
                pr[mr][1] = probs[wrow + mr * 16 + g + 8];
            }
            #pragma unroll
            for (int nt = 0; nt < 8; ++nt) {
                float c0 = 0.0f, c1 = 0.0f;
                #pragma unroll
                for (int mr = 0; mr < MR; ++mr) {
                    c0 = fmaf(pr[mr][0], acc[mr][nt][0], fmaf(pr[mr][1], acc[mr][nt][2], c0));
                    c1 = fmaf(pr[mr][0], acc[mr][nt][1], fmaf(pr[mr][1], acc[mr][nt][3], c1));
                }
                // reduce over the 8 g-lanes (stride-4 butterfly)
                #pragma unroll
                for (int o = 4; o <= 16; o <<= 1) {
                    c0 += __shfl_xor_sync(0xffffffffu, c0, o);
                    c1 += __shfl_xor_sync(0xffffffffu, c1, o);
                }
                if (g == 0) {
                    part[rg * 256 + wcol + nt * 8 + 2 * q]     = c0;
                    part[rg * 256 + wcol + nt * 8 + 2 * q + 1] = c1;
                }
            }
        }
        __syncthreads();

        // ---- squash ----
        float sd = 0.0f;
        if (tid < 256)
            sd = part[tid] + part[256 + tid] + part[512 + tid] + part[768 + tid];
        float sq = blockSum(sd * sd, red);
        float scale = sq / ((1.0f + sq) * sqrtf(sq));
        if (tid < 256) vout[tid] = sd * scale;
        __syncthreads();

        if (it < 2) {
            // ---- logits[b] += sum_d P[b][d] * v[d] from registers ----
            float rowp[MR][2];
            #pragma unroll
            for (int mr = 0; mr < MR; ++mr) { rowp[mr][0] = 0.0f; rowp[mr][1] = 0.0f; }
            #pragma unroll
            for (int nt = 0; nt < 8; ++nt) {
                float v0 = vout[wcol + nt * 8 + 2 * q];
                float v1 = vout[wcol + nt * 8 + 2 * q + 1];
                #pragma unroll
                for (int mr = 0; mr < MR; ++mr) {
                    rowp[mr][0] = fmaf(acc[mr][nt][0], v0, fmaf(acc[mr][nt][1], v1, rowp[mr][0]));
                    rowp[mr][1] = fmaf(acc[mr][nt][2], v0, fmaf(acc[mr][nt][3], v1, rowp[mr][1]));
                }
            }
            // reduce over the 4 q-lanes
            #pragma unroll
            for (int mr = 0; mr < MR; ++mr) {
                #pragma unroll
                for (int o = 1; o <= 2; o <<= 1) {
                    rowp[mr][0] += __shfl_xor_sync(0xffffffffu, rowp[mr][0], o);
                    rowp[mr][1] += __shfl_xor_sync(0xffffffffu, rowp[mr][1], o);
                }
            }
            __syncthreads();   // part free (all reads done pre-blockSum syncs)
            if (q == 0) {
                #pragma unroll
                for (int mr = 0; mr < MR; ++mr) {
                    part[cg * M + wrow + mr * 16 + g]     = rowp[mr][0];
                    part[cg * M + wrow + mr * 16 + g + 8] = rowp[mr][1];
                }
            }
            __syncthreads();
            if (tid < M)
                logits[tid] += part[tid] + part[M + tid] + part[2 * M + tid] + part[3 * M + tid];
            __syncthreads();
        } else {
            if (tid < 256) {
                float v = vout[tid];
                size_t o = (size_t)blockIdx.x * outXStride + (size_t)blockIdx.y * outYStride + tid;
                if (F32OUT) {
                    OutF[o] = v;
                } else {
                    __nv_bfloat16 h, m, l;
                    split3(v, h, m, l);
                    OutH[o] = h; OutM[o] = m; OutL[o] = l;
                }
            }
        }
    }
}

static size_t stage_smem(int M) {
    size_t buf = 3ull * M * 40 * 2 + 3ull * 256 * 40 * 2;   // one pipeline buffer
    size_t scr = (1024 + 256 + 2 * (size_t)M + 64) * 4;
    return 2 * buf + scr;
}

extern "C" void kernel_launch(void* const* d_in, const int* in_sizes, int n_in,
                              void* d_out, int out_size) {
    (void)in_sizes; (void)n_in; (void)out_size;
    const float* x  = (const float*)d_in[0];   // [64,128,256]
    const float* w1 = (const float*)d_in[1];   // [64,256,256]
    const float* w2 = (const float*)d_in[2];   // [32,256,256]
    float* out = (float*)d_out;                // [32,64,256]

    void* p;
    cudaGetSymbolAddress(&p, g_xh);  __nv_bfloat16* xh  = (__nv_bfloat16*)p;
    cudaGetSymbolAddress(&p, g_xm);  __nv_bfloat16* xm  = (__nv_bfloat16*)p;
    cudaGetSymbolAddress(&p, g_xl);  __nv_bfloat16* xl  = (__nv_bfloat16*)p;
    cudaGetSymbolAddress(&p, g_w1h); __nv_bfloat16* w1h = (__nv_bfloat16*)p;
    cudaGetSymbolAddress(&p, g_w1m); __nv_bfloat16* w1m = (__nv_bfloat16*)p;
    cudaGetSymbolAddress(&p, g_w1l); __nv_bfloat16* w1l = (__nv_bfloat16*)p;
    cudaGetSymbolAddress(&p, g_w2h); __nv_bfloat16* w2h = (__nv_bfloat16*)p;
    cudaGetSymbolAddress(&p, g_w2m); __nv_bfloat16* w2m = (__nv_bfloat16*)p;
    cudaGetSymbolAddress(&p, g_w2l); __nv_bfloat16* w2l = (__nv_bfloat16*)p;
    cudaGetSymbolAddress(&p, g_o1h); __nv_bfloat16* o1h = (__nv_bfloat16*)p;
    cudaGetSymbolAddress(&p, g_o1m); __nv_bfloat16* o1m = (__nv_bfloat16*)p;
    cudaGetSymbolAddress(&p, g_o1l); __nv_bfloat16* o1l = (__nv_bfloat16*)p;

    // pre-pass: 3-level bf16 splits (+ W transposed to [n][k])
    split_x_kernel<<<8192, 256>>>(x, xh, xm, xl, 64 * 128 * 256);
    trans_split_w<<<dim3(8, 8, 64), 256>>>(w1, w1h, w1m, w1l);
    trans_split_w<<<dim3(8, 8, 32), 256>>>(w2, w2h, w2m, w2l);

    const size_t sm1 = stage_smem(128);   // ~190 KB
    const size_t sm2 = stage_smem(64);    // ~159 KB
    cudaFuncSetAttribute(caps_mma_route<128, false>,
                         cudaFuncAttributeMaxDynamicSharedMemorySize, (int)sm1);
    cudaFuncSetAttribute(caps_mma_route<64, true>,
                         cudaFuncAttributeMaxDynamicSharedMemorySize, (int)sm2);

    // Stage 1: (a=64, h=64) -> out1 3-level bf16 [a][h][256]
    caps_mma_route<128, false><<<dim3(64, 64), 512, sm1>>>(
        xh, xm, xl, w1h, w1m, w1l, nullptr, o1h, o1m, o1l,
        /*x=a*/ 64 * 256, /*y=h*/ 256);

    // Stage 2: (a=64, c=32) -> out fp32 [c][a][256]
    caps_mma_route<64, true><<<dim3(64, 32), 512, sm2>>>(
        o1h, o1m, o1l, w2h, w2m, w2l, out, nullptr, nullptr, nullptr,
        /*x=a*/ 256, /*y=c*/ 64 * 256);
}

// round 11
// speedup vs baseline: 2.8262x; 1.6490x over previous
#include <cuda_runtime.h>
#include <cuda_fp16.h>
#include <math.h>
#include <stdint.h>

// ---------------- device globals (no allocations allowed) ----------------
// 2-level fp16 splits: v = vh + vl (each level fp16)
__device__ __half g_xh[64 * 128 * 256], g_xl[64 * 128 * 256];     // X split    [a][b][d]
__device__ __half g_w1h[64 * 256 * 256], g_w1l[64 * 256 * 256];   // W1^T split [h][n][k]
__device__ __half g_w2h[32 * 256 * 256], g_w2l[32 * 256 * 256];   // W2^T split [c][n][k]
__device__ __half g_o1h[64 * 64 * 256], g_o1l[64 * 64 * 256];     // out1 split [a][h][d]

// ---------------- fp16 HMMA via mma.sync (sm_80+ baseline PTX) ----------------
__device__ __forceinline__ void mma_fp16(float* c, const uint32_t* a, uint32_t b0, uint32_t b1) {
    asm volatile(
        "mma.sync.aligned.m16n8k16.row.col.f32.f16.f16.f32 "
        "{%0,%1,%2,%3}, {%4,%5,%6,%7}, {%8,%9}, {%0,%1,%2,%3};"
        : "+f"(c[0]), "+f"(c[1]), "+f"(c[2]), "+f"(c[3])
        : "r"(a[0]), "r"(a[1]), "r"(a[2]), "r"(a[3]), "r"(b0), "r"(b1));
}

// ---------------- cp.async helpers (sm_80+ baseline PTX) ----------------
__device__ __forceinline__ void cp16(uint32_t smem_dst, const void* gsrc) {
    asm volatile("cp.async.cg.shared.global [%0], [%1], 16;" :: "r"(smem_dst), "l"(gsrc));
}
__device__ __forceinline__ void cp_commit() {
    asm volatile("cp.async.commit_group;");
}
template<int N>
__device__ __forceinline__ void cp_wait() {
    asm volatile("cp.async.wait_group %0;" :: "n"(N));
}
__device__ __forceinline__ uint32_t smem_u32(const void* p) {
    uint32_t a;
    asm("{ .reg .u64 t; cvta.to.shared.u64 t, %1; cvt.u32.u64 %0, t; }" : "=r"(a) : "l"(p));
    return a;
}

// ---------------- block reductions over 512 threads (16 warps) ----------------
__device__ __forceinline__ float warpSum(float v) {
    #pragma unroll
    for (int o = 16; o; o >>= 1) v += __shfl_down_sync(0xffffffffu, v, o);
    return v;
}
__device__ __forceinline__ float warpMax(float v) {
    #pragma unroll
    for (int o = 16; o; o >>= 1) v = fmaxf(v, __shfl_down_sync(0xffffffffu, v, o));
    return v;
}
__device__ __forceinline__ float blockSum(float v, float* red) {
    v = warpSum(v);
    __syncthreads();
    if ((threadIdx.x & 31) == 0) red[threadIdx.x >> 5] = v;
    __syncthreads();
    if (threadIdx.x < 32) {
        float x = (threadIdx.x < 16) ? red[threadIdx.x] : 0.0f;
        x = warpSum(x);
        if (threadIdx.x == 0) red[32] = x;
    }
    __syncthreads();
    return red[32];
}
__device__ __forceinline__ float blockMax(float v, float* red) {
    v = warpMax(v);
    __syncthreads();
    if ((threadIdx.x & 31) == 0) red[threadIdx.x >> 5] = v;
    __syncthreads();
    if (threadIdx.x < 32) {
        float x = (threadIdx.x < 16) ? red[threadIdx.x] : -3.402823466e38f;
        x = warpMax(x);
        if (threadIdx.x == 0) red[32] = x;
    }
    __syncthreads();
    return red[32];
}

// 2-level fp16 split of a float
__device__ __forceinline__ void split2(float v, __half& h, __half& l) {
    h = __float2half_rn(v);
    l = __float2half_rn(v - __half2float(h));
}

// ---------------- pre-pass: split X into fp16 h/l ----------------
__global__ void split_x_kernel(const float* __restrict__ x,
                               __half* __restrict__ xh, __half* __restrict__ xl, int n) {
    int i = blockIdx.x * blockDim.x + threadIdx.x;
    if (i >= n) return;
    __half h, l;
    split2(x[i], h, l);
    xh[i] = h; xl[i] = l;
}

// ---------------- pre-pass: transpose + split W[k][n] -> Wt[n][k] fp16 h/l ----------------
__global__ void trans_split_w(const float* __restrict__ W,
                              __half* __restrict__ Wth, __half* __restrict__ Wtl) {
    __shared__ float st[32][33];
    int mb = blockIdx.z, k0 = blockIdx.x * 32, n0 = blockIdx.y * 32;
    const float* Wm = W + (size_t)mb * 65536;
    int tid = threadIdx.x;
    #pragma unroll
    for (int i = 0; i < 4; ++i) {
        int e = tid + i * 256, k = e >> 5, n = e & 31;
        st[k][n] = Wm[(k0 + k) * 256 + n0 + n];
    }
    __syncthreads();
    #pragma unroll
    for (int i = 0; i < 4; ++i) {
        int e = tid + i * 256, n = e >> 5, k = e & 31;
        float f = st[k][n];
        __half h, l;
        split2(f, h, l);
        size_t o = (size_t)mb * 65536 + (size_t)(n0 + n) * 256 + k0 + k;
        Wth[o] = h; Wtl[o] = l;
    }
}

// ---------------- fused HMMA-GEMM + register-resident routing ----------------
// One CTA = one (weight, batch) pair.
//   P[M,256] = A[M,256] @ B^T via 3-term 2-level fp16 split (hh + lh + hl),
//   cp.async double-buffered; P lives in the mma accumulators; routing via
//   shfl reductions + a small smem combine buffer.
// 16 warps: 4 row-groups x 4 col-groups; warp tile (M/4) x 64.
template<int M, bool F32OUT, int MINCTA>
__global__ void __launch_bounds__(512, MINCTA)
caps_mma_route(const __half* __restrict__ AhG, const __half* __restrict__ AlG,
               const __half* __restrict__ BhG, const __half* __restrict__ BlG,
               float* __restrict__ OutF,
               __half* __restrict__ OutH, __half* __restrict__ OutL,
               int outXStride, int outYStride)
{
    constexpr int KC = 32;               // k-chunk
    constexpr int NT = 256 / KC;         // 8 chunks
    constexpr int TS = KC + 8;           // 40 fp16 row stride (80B, 16B-aligned)
    constexpr int MR = M / 64;           // mma row-tiles per warp
    constexpr uint32_t ATB = (uint32_t)M * TS * 2;    // one A level tile bytes
    constexpr uint32_t BTB = 256u * TS * 2;           // one B level tile bytes
    constexpr uint32_t BUF = 2 * ATB + 2 * BTB;       // one pipeline buffer
    constexpr uint32_t SCR = 2 * BUF;

    extern __shared__ char smc[];
    const uint32_t smb = smem_u32(smc);
    float* part   = (float*)(smc + SCR);   // 1024 floats (4 x 256 combine buffer)
    float* vout   = part + 1024;           // 256
    float* probs  = vout + 256;            // M
    float* logits = probs + M;             // M
    float* red    = logits + M;            // 64

    const int tid = threadIdx.x;
    const int wid = tid >> 5, lane = tid & 31;
    const int g = lane >> 2, q = lane & 3;           // mma fragment coords
    const int rg = wid >> 2, cg = wid & 3;           // row-group / col-group
    const int wrow = rg * (M / 4);                   // warp row base
    const int wcol = cg * 64;                        // warp col base

    const size_t aOff = (size_t)blockIdx.x * (M * 256);
    const size_t bOff = (size_t)blockIdx.y * 65536u;
    const __half* Asrc[2] = { AhG + aOff, AlG + aOff };
    const __half* Bsrc[2] = { BhG + bOff, BlG + bOff };

    // -------- async tile loader: chunk t -> buffer at byte offset bb --------
    auto load_chunk = [&](uint32_t bb, int t) {
        const int k0g = t * KC;
        #pragma unroll
        for (int lv = 0; lv < 2; ++lv) {
            const __half* src = Asrc[lv] + k0g;
            uint32_t dstb = smb + bb + lv * ATB;
            #pragma unroll
            for (int e = tid; e < M * 4; e += 512) {
                int r = e >> 2, seg = e & 3;
                cp16(dstb + (uint32_t)(r * TS + seg * 8) * 2, src + r * 256 + seg * 8);
            }
        }
        #pragma unroll
        for (int lv = 0; lv < 2; ++lv) {
            const __half* src = Bsrc[lv] + k0g;
            uint32_t dstb = smb + bb + 2 * ATB + lv * BTB;
            #pragma unroll
            for (int e = tid; e < 1024; e += 512) {
                int r = e >> 2, seg = e & 3;
                cp16(dstb + (uint32_t)(r * TS + seg * 8) * 2, src + r * 256 + seg * 8);
            }
        }
        cp_commit();
    };

    // ============ GEMM: 8 K-chunks of 32, 3-term 2-level fp16 split ============
    float acc[MR][8][4];
    #pragma unroll
    for (int mr = 0; mr < MR; ++mr)
        #pragma unroll
        for (int nt = 0; nt < 8; ++nt)
            #pragma unroll
            for (int j = 0; j < 4; ++j) acc[mr][nt][j] = 0.0f;

    load_chunk(0, 0);

    for (int t = 0; t < NT; ++t) {
        const uint32_t bb = (t & 1) ? BUF : 0;
        if (t + 1 < NT) {
            load_chunk((t & 1) ? 0 : BUF, t + 1);
            cp_wait<1>();
        } else {
            cp_wait<0>();
        }
        __syncthreads();

        const __half* Ash = (const __half*)(smc + bb);
        const __half* Asl = (const __half*)(smc + bb + ATB);
        const __half* Bsh = (const __half*)(smc + bb + 2 * ATB);
        const __half* Bsl = (const __half*)(smc + bb + 2 * ATB + BTB);

        #pragma unroll
        for (int ks = 0; ks < KC / 16; ++ks) {
            const int k0 = ks * 16;
            uint32_t ah[MR][4], al[MR][4];
            #pragma unroll
            for (int mr = 0; mr < MR; ++mr) {
                const int rb = (wrow + mr * 16 + g) * TS + k0 + 2 * q;
                const __half* ar = Ash + rb;
                ah[mr][0] = *(const uint32_t*)ar;
                ah[mr][1] = *(const uint32_t*)(ar + 8 * TS);
                ah[mr][2] = *(const uint32_t*)(ar + 8);
                ah[mr][3] = *(const uint32_t*)(ar + 8 * TS + 8);
                const __half* al2 = Asl + rb;
                al[mr][0] = *(const uint32_t*)al2;
                al[mr][1] = *(const uint32_t*)(al2 + 8 * TS);
                al[mr][2] = *(const uint32_t*)(al2 + 8);
                al[mr][3] = *(const uint32_t*)(al2 + 8 * TS + 8);
            }
            #pragma unroll
            for (int nt = 0; nt < 8; ++nt) {
                const int cb = (wcol + nt * 8 + g) * TS + k0 + 2 * q;
                {   // Bh pass: (Ah + Al) x Bh
                    const __half* br = Bsh + cb;
                    uint32_t b0 = *(const uint32_t*)br;
                    uint32_t b1 = *(const uint32_t*)(br + 8);
                    #pragma unroll
                    for (int mr = 0; mr < MR; ++mr) {
                        mma_fp16(acc[mr][nt], ah[mr], b0, b1);
                        mma_fp16(acc[mr][nt], al[mr], b0, b1);
                    }
                }
                {   // Bl pass: Ah x Bl
                    const __half* br = Bsl + cb;
                    uint32_t b0 = *(const uint32_t*)br;
                    uint32_t b1 = *(const uint32_t*)(br + 8);
                    #pragma unroll
                    for (int mr = 0; mr < MR; ++mr)
                        mma_fp16(acc[mr][nt], ah[mr], b0, b1);
                }
            }
        }
        __syncthreads();   // all warps done with this buffer before refill
    }

    // ============ routing directly on register accumulators ============
    // acc[mr][nt][0,1] -> row (wrow+mr*16+g),   cols wcol+nt*8+2q+{0,1}
    // acc[mr][nt][2,3] -> row (wrow+mr*16+g+8), same cols
    if (tid < M) logits[tid] = 0.0f;

    for (int it = 0; it < 3; ++it) {
        // ---- probs = softmax(logits) ----
        if (it == 0) {
            if (tid < M) probs[tid] = 1.0f / (float)M;
        } else {
            float lv = (tid < M) ? logits[tid] : -3.402823466e38f;
            float mx = blockMax(lv, red);
            float ev = (tid < M) ? expf(lv - mx) : 0.0f;
            float Z = blockSum(ev, red);
            if (tid < M) probs[tid] = ev / Z;
        }
        __syncthreads();

        // ---- s[d] = sum_b probs[b] * P[b][d] from registers ----
        {
            float pr[MR][2];
            #pragma unroll
            for (int mr = 0; mr < MR; ++mr) {
                pr[mr][0] = probs[wrow + mr * 16 + g];
                pr[mr][1] = probs[wrow + mr * 16 + g + 8];
            }
            #pragma unroll
            for (int nt = 0; nt < 8; ++nt) {
                float c0 = 0.0f, c1 = 0.0f;
                #pragma unroll
                for (int mr = 0; mr < MR; ++mr) {
                    c0 = fmaf(pr[mr][0], acc[mr][nt][0], fmaf(pr[mr][1], acc[mr][nt][2], c0));
                    c1 = fmaf(pr[mr][0], acc[mr][nt][1], fmaf(pr[mr][1], acc[mr][nt][3], c1));
                }
                // reduce over the 8 g-lanes (stride-4 butterfly)
                #pragma unroll
                for (int o = 4; o <= 16; o <<= 1) {
                    c0 += __shfl_xor_sync(0xffffffffu, c0, o);
                    c1 += __shfl_xor_sync(0xffffffffu, c1, o);
                }
                if (g == 0) {
                    part[rg * 256 + wcol + nt * 8 + 2 * q]     = c0;
                    part[rg * 256 + wcol + nt * 8 + 2 * q + 1] = c1;
                }
            }
        }
        __syncthreads();

        // ---- squash ----
        float sd = 0.0f;
        if (tid < 256)
            sd = part[tid] + part[256 + tid] + part[512 + tid] + part[768 + tid];
        float sq = blockSum(sd * sd, red);
        float scale = sq / ((1.0f + sq) * sqrtf(sq));
        if (tid < 256) vout[tid] = sd * scale;
        __syncthreads();

        if (it < 2) {
            // ---- logits[b] += sum_d P[b][d] * v[d] from registers ----
            float rowp[MR][2];
            #pragma unroll
            for (int mr = 0; mr < MR; ++mr) { rowp[mr][0] = 0.0f; rowp[mr][1] = 0.0f; }
            #pragma unroll
            for (int nt = 0; nt < 8; ++nt) {
                float v0 = vout[wcol + nt * 8 + 2 * q];
                float v1 = vout[wcol + nt * 8 + 2 * q + 1];
                #pragma unroll
                for (int mr = 0; mr < MR; ++mr) {
                    rowp[mr][0] = fmaf(acc[mr][nt][0], v0, fmaf(acc[mr][nt][1], v1, rowp[mr][0]));
                    rowp[mr][1] = fmaf(acc[mr][nt][2], v0, fmaf(acc[mr][nt][3], v1, rowp[mr][1]));
                }
            }
            // reduce over the 4 q-lanes
            #pragma unroll
            for (int mr = 0; mr < MR; ++mr) {
                #pragma unroll
                for (int o = 1; o <= 2; o <<= 1) {
                    rowp[mr][0] += __shfl_xor_sync(0xffffffffu, rowp[mr][0], o);
                    rowp[mr][1] += __shfl_xor_sync(0xffffffffu, rowp[mr][1], o);
                }
            }
            __syncthreads();   // part free
            if (q == 0) {
                #pragma unroll
                for (int mr = 0; mr < MR; ++mr) {
                    part[cg * M + wrow + mr * 16 + g]     = rowp[mr][0];
                    part[cg * M + wrow + mr * 16 + g + 8] = rowp[mr][1];
                }
            }
            __syncthreads();
            if (tid < M)
                logits[tid] += part[tid] + part[M + tid] + part[2 * M + tid] + part[3 * M + tid];
            __syncthreads();
        } else {
            if (tid < 256) {
                float v = vout[tid];
                size_t o = (size_t)blockIdx.x * outXStride + (size_t)blockIdx.y * outYStride + tid;
                if (F32OUT) {
                    OutF[o] = v;
                } else {
                    __half h, l;
                    split2(v, h, l);
                    OutH[o] = h; OutL[o] = l;
                }
            }
        }
    }
}

static size_t stage_smem(int M) {
    size_t buf = 2ull * M * 40 * 2 + 2ull * 256 * 40 * 2;   // one pipeline buffer
    size_t scr = (1024 + 256 + 2 * (size_t)M + 64) * 4;
    return 2 * buf + scr;
}

extern "C" void kernel_launch(void* const* d_in, const int* in_sizes, int n_in,
                              void* d_out, int out_size) {
    (void)in_sizes; (void)n_in; (void)out_size;
    const float* x  = (const float*)d_in[0];   // [64,128,256]
    const float* w1 = (const float*)d_in[1];   // [64,256,256]
    const float* w2 = (const float*)d_in[2];   // [32,256,256]
    float* out = (float*)d_out;                // [32,64,256]

    void* p;
    cudaGetSymbolAddress(&p, g_xh);  __half* xh  = (__half*)p;
    cudaGetSymbolAddress(&p, g_xl);  __half* xl  = (__half*)p;
    cudaGetSymbolAddress(&p, g_w1h); __half* w1h = (__half*)p;
    cudaGetSymbolAddress(&p, g_w1l); __half* w1l = (__half*)p;
    cudaGetSymbolAddress(&p, g_w2h); __half* w2h = (__half*)p;
    cudaGetSymbolAddress(&p, g_w2l); __half* w2l = (__half*)p;
    cudaGetSymbolAddress(&p, g_o1h); __half* o1h = (__half*)p;
    cudaGetSymbolAddress(&p, g_o1l); __half* o1l = (__half*)p;

    // pre-pass: fp16 hi/lo splits (+ W transposed to [n][k])
    split_x_kernel<<<8192, 256>>>(x, xh, xl, 64 * 128 * 256);
    trans_split_w<<<dim3(8, 8, 64), 256>>>(w1, w1h, w1l);
    trans_split_w<<<dim3(8, 8, 32), 256>>>(w2, w2h, w2l);

    const size_t sm1 = stage_smem(128);   // ~129 KB
    const size_t sm2 = stage_smem(64);    // ~109 KB
    cudaFuncSetAttribute((const void*)caps_mma_route<128, false, 1>,
                         cudaFuncAttributeMaxDynamicSharedMemorySize, (int)sm1);
    cudaFuncSetAttribute((const void*)caps_mma_route<64, true, 2>,
                         cudaFuncAttributeMaxDynamicSharedMemorySize, (int)sm2);

    // Stage 1: (a=64, h=64) -> out1 fp16 h/l [a][h][256]
    caps_mma_route<128, false, 1><<<dim3(64, 64), 512, sm1>>>(
        xh, xl, w1h, w1l, nullptr, o1h, o1l, /*x=a*/ 64 * 256, /*y=h*/ 256);

    // Stage 2: (a=64, c=32) -> out fp32 [c][a][256]; 2 CTAs/SM
    caps_mma_route<64, true, 2><<<dim3(64, 32), 512, sm2>>>(
        o1h, o1l, w2h, w2l, out, nullptr, nullptr, /*x=a*/ 256, /*y=c*/ 64 * 256);
}

// round 12
// speedup vs baseline: 2.9437x; 1.0416x over previous
#include <cuda_runtime.h>
#include <cuda_fp16.h>
#include <math.h>
#include <stdint.h>

// ---------------- device globals (no allocations allowed) ----------------
// 2-level fp16 splits: v = vh + vl (each level fp16)
__device__ __half g_xh[64 * 128 * 256], g_xl[64 * 128 * 256];     // X split    [a][b][d]
__device__ __half g_w1h[64 * 256 * 256], g_w1l[64 * 256 * 256];   // W1^T split [h][n][k]
__device__ __half g_w2h[32 * 256 * 256], g_w2l[32 * 256 * 256];   // W2^T split [c][n][k]
__device__ __half g_o1h[64 * 64 * 256], g_o1l[64 * 64 * 256];     // out1 split [a][h][d]

// ---------------- fp16 HMMA via mma.sync (sm_80+ baseline PTX) ----------------
__device__ __forceinline__ void mma_fp16(float* c, const uint32_t* a, uint32_t b0, uint32_t b1) {
    asm volatile(
        "mma.sync.aligned.m16n8k16.row.col.f32.f16.f16.f32 "
        "{%0,%1,%2,%3}, {%4,%5,%6,%7}, {%8,%9}, {%0,%1,%2,%3};"
        : "+f"(c[0]), "+f"(c[1]), "+f"(c[2]), "+f"(c[3])
        : "r"(a[0]), "r"(a[1]), "r"(a[2]), "r"(a[3]), "r"(b0), "r"(b1));
}

// ---------------- ldmatrix x4 (sm_75+ baseline PTX) ----------------
__device__ __forceinline__ void ldsm_x4(uint32_t* r, uint32_t addr) {
    asm volatile("ldmatrix.sync.aligned.m8n8.x4.shared.b16 {%0,%1,%2,%3}, [%4];"
                 : "=r"(r[0]), "=r"(r[1]), "=r"(r[2]), "=r"(r[3]) : "r"(addr));
}

// ---------------- cp.async helpers (sm_80+ baseline PTX) ----------------
__device__ __forceinline__ void cp16(uint32_t smem_dst, const void* gsrc) {
    asm volatile("cp.async.cg.shared.global [%0], [%1], 16;" :: "r"(smem_dst), "l"(gsrc));
}
__device__ __forceinline__ void cp_commit() {
    asm volatile("cp.async.commit_group;");
}
template<int N>
__device__ __forceinline__ void cp_wait() {
    asm volatile("cp.async.wait_group %0;" :: "n"(N));
}
__device__ __forceinline__ uint32_t smem_u32(const void* p) {
    uint32_t a;
    asm("{ .reg .u64 t; cvta.to.shared.u64 t, %1; cvt.u32.u64 %0, t; }" : "=r"(a) : "l"(p));
    return a;
}

// ---------------- block reductions over 512 threads (16 warps) ----------------
__device__ __forceinline__ float warpSum(float v) {
    #pragma unroll
    for (int o = 16; o; o >>= 1) v += __shfl_down_sync(0xffffffffu, v, o);
    return v;
}
__device__ __forceinline__ float warpMax(float v) {
    #pragma unroll
    for (int o = 16; o; o >>= 1) v = fmaxf(v, __shfl_down_sync(0xffffffffu, v, o));
    return v;
}
__device__ __forceinline__ float blockSum(float v, float* red) {
    v = warpSum(v);
    __syncthreads();
    if ((threadIdx.x & 31) == 0) red[threadIdx.x >> 5] = v;
    __syncthreads();
    if (threadIdx.x < 32) {
        float x = (threadIdx.x < 16) ? red[threadIdx.x] : 0.0f;
        x = warpSum(x);
        if (threadIdx.x == 0) red[32] = x;
    }
    __syncthreads();
    return red[32];
}
__device__ __forceinline__ float blockMax(float v, float* red) {
    v = warpMax(v);
    __syncthreads();
    if ((threadIdx.x & 31) == 0) red[threadIdx.x >> 5] = v;
    __syncthreads();
    if (threadIdx.x < 32) {
        float x = (threadIdx.x < 16) ? red[threadIdx.x] : -3.402823466e38f;
        x = warpMax(x);
        if (threadIdx.x == 0) red[32] = x;
    }
    __syncthreads();
    return red[32];
}

// 2-level fp16 split of a float
__device__ __forceinline__ void split2(float v, __half& h, __half& l) {
    h = __float2half_rn(v);
    l = __float2half_rn(v - __half2float(h));
}

// ---------------- pre-pass: split X into fp16 h/l ----------------
__global__ void split_x_kernel(const float* __restrict__ x,
                               __half* __restrict__ xh, __half* __restrict__ xl, int n) {
    int i = blockIdx.x * blockDim.x + threadIdx.x;
    if (i >= n) return;
    __half h, l;
    split2(x[i], h, l);
    xh[i] = h; xl[i] = l;
}

// ---------------- pre-pass: transpose + split W[k][n] -> Wt[n][k] fp16 h/l ----------------
__global__ void trans_split_w(const float* __restrict__ W,
                              __half* __restrict__ Wth, __half* __restrict__ Wtl) {
    __shared__ float st[32][33];
    int mb = blockIdx.z, k0 = blockIdx.x * 32, n0 = blockIdx.y * 32;
    const float* Wm = W + (size_t)mb * 65536;
    int tid = threadIdx.x;
    #pragma unroll
    for (int i = 0; i < 4; ++i) {
        int e = tid + i * 256, k = e >> 5, n = e & 31;
        st[k][n] = Wm[(k0 + k) * 256 + n0 + n];
    }
    __syncthreads();
    #pragma unroll
    for (int i = 0; i < 4; ++i) {
        int e = tid + i * 256, n = e >> 5, k = e & 31;
        float f = st[k][n];
        __half h, l;
        split2(f, h, l);
        size_t o = (size_t)mb * 65536 + (size_t)(n0 + n) * 256 + k0 + k;
        Wth[o] = h; Wtl[o] = l;
    }
}

// ---------------- fused HMMA-GEMM + register-resident routing ----------------
// One CTA = one (weight, batch) pair.
//   P[M,256] = A[M,256] @ B^T via 3-term 2-level fp16 split (hh + lh + hl),
//   cp.async double-buffered; fragments via ldmatrix.x4; P lives in the mma
//   accumulators; routing via shfl reductions + small smem combine buffer.
// 16 warps: 4 row-groups x 4 col-groups; warp tile (M/4) x 64.
template<int M, bool F32OUT, int MINCTA>
__global__ void __launch_bounds__(512, MINCTA)
caps_mma_route(const __half* __restrict__ AhG, const __half* __restrict__ AlG,
               const __half* __restrict__ BhG, const __half* __restrict__ BlG,
               float* __restrict__ OutF,
               __half* __restrict__ OutH, __half* __restrict__ OutL,
               int outXStride, int outYStride)
{
    constexpr int KC = 32;               // k-chunk
    constexpr int NT = 256 / KC;         // 8 chunks
    constexpr int TS = KC + 8;           // 40 fp16 row stride (80B, 16B-aligned)
    constexpr int MR = M / 64;           // mma row-tiles per warp
    constexpr uint32_t ATB = (uint32_t)M * TS * 2;    // one A level tile bytes
    constexpr uint32_t BTB = 256u * TS * 2;           // one B level tile bytes
    constexpr uint32_t BUF = 2 * ATB + 2 * BTB;       // one pipeline buffer
    constexpr uint32_t SCR = 2 * BUF;

    extern __shared__ char smc[];
    const uint32_t smb = smem_u32(smc);
    float* part   = (float*)(smc + SCR);   // 1024 floats (4 x 256 combine buffer)
    float* vout   = part + 1024;           // 256
    float* probs  = vout + 256;            // M
    float* logits = probs + M;             // M
    float* red    = logits + M;            // 64

    const int tid = threadIdx.x;
    const int wid = tid >> 5, lane = tid & 31;
    const int g = lane >> 2, q = lane & 3;           // mma fragment coords
    const int rg = wid >> 2, cg = wid & 3;           // row-group / col-group
    const int wrow = rg * (M / 4);                   // warp row base
    const int wcol = cg * 64;                        // warp col base

    // ldmatrix lane-address components (computed once)
    const int lsub = lane & 7;                       // row within 8x8 matrix
    const int lmi  = lane >> 3;                      // matrix index 0..3
    const int aRowOff = lsub + (lmi & 1) * 8;        // A: m0/m2 rows 0-7, m1/m3 rows 8-15
    const int aColOff = (lmi >> 1) * 8;              // A: m0/m1 cols k0, m2/m3 cols k0+8
    const int bColOff = (lmi & 1) * 8;               // B: m0/m2 col k0, m1/m3 col k0+8
    const int bNtOff  = (lmi >> 1);                  // B: m0/m1 -> nt, m2/m3 -> nt+1

    const size_t aOff = (size_t)blockIdx.x * (M * 256);
    const size_t bOff = (size_t)blockIdx.y * 65536u;
    const __half* Asrc[2] = { AhG + aOff, AlG + aOff };
    const __half* Bsrc[2] = { BhG + bOff, BlG + bOff };

    // -------- async tile loader: chunk t -> buffer at byte offset bb --------
    auto load_chunk = [&](uint32_t bb, int t) {
        const int k0g = t * KC;
        #pragma unroll
        for (int lv = 0; lv < 2; ++lv) {
            const __half* src = Asrc[lv] + k0g;
            uint32_t dstb = smb + bb + lv * ATB;
            #pragma unroll
            for (int e = tid; e < M * 4; e += 512) {
                int r = e >> 2, seg = e & 3;
                cp16(dstb + (uint32_t)(r * TS + seg * 8) * 2, src + r * 256 + seg * 8);
            }
        }
        #pragma unroll
        for (int lv = 0; lv < 2; ++lv) {
            const __half* src = Bsrc[lv] + k0g;
            uint32_t dstb = smb + bb + 2 * ATB + lv * BTB;
            #pragma unroll
            for (int e = tid; e < 1024; e += 512) {
                int r = e >> 2, seg = e & 3;
                cp16(dstb + (uint32_t)(r * TS + seg * 8) * 2, src + r * 256 + seg * 8);
            }
        }
        cp_commit();
    };

    // ============ GEMM: 8 K-chunks of 32, 3-term 2-level fp16 split ============
    float acc[MR][8][4];
    #pragma unroll
    for (int mr = 0; mr < MR; ++mr)
        #pragma unroll
        for (int nt = 0; nt < 8; ++nt)
            #pragma unroll
            for (int j = 0; j < 4; ++j) acc[mr][nt][j] = 0.0f;

    load_chunk(0, 0);

    for (int t = 0; t < NT; ++t) {
        const uint32_t bb = (t & 1) ? BUF : 0;
        if (t + 1 < NT) {
            load_chunk((t & 1) ? 0 : BUF, t + 1);
            cp_wait<1>();
        } else {
            cp_wait<0>();
        }
        __syncthreads();

        const uint32_t aBase = smb + bb;
        const uint32_t bBase = smb + bb + 2 * ATB;

        #pragma unroll
        for (int ks = 0; ks < KC / 16; ++ks) {
            const int k0 = ks * 16;
            // A fragments via ldmatrix.x4 (both levels)
            uint32_t ah[MR][4], al[MR][4];
            #pragma unroll
            for (int mr = 0; mr < MR; ++mr) {
                uint32_t aAddr = aBase +
                    (uint32_t)(((wrow + mr * 16 + aRowOff) * TS + k0 + aColOff) * 2);
                ldsm_x4(ah[mr], aAddr);
                ldsm_x4(al[mr], aAddr + ATB);
            }
            // B fragments per nt-pair, MMAs interleaved (keeps live B regs small)
            #pragma unroll
            for (int j = 0; j < 4; ++j) {
                uint32_t bAddr = bBase +
                    (uint32_t)(((wcol + (2 * j + bNtOff) * 8 + lsub) * TS + k0 + bColOff) * 2);
                uint32_t rh[4], rl[4];
                ldsm_x4(rh, bAddr);
                ldsm_x4(rl, bAddr + BTB);
                #pragma unroll
                for (int u = 0; u < 2; ++u) {
                    const int nt = 2 * j + u;
                    const uint32_t b0h = rh[2 * u], b1h = rh[2 * u + 1];
                    const uint32_t b0l = rl[2 * u], b1l = rl[2 * u + 1];
                    #pragma unroll
                    for (int mr = 0; mr < MR; ++mr) {
                        mma_fp16(acc[mr][nt], ah[mr], b0h, b1h);   // hh
                        mma_fp16(acc[mr][nt], al[mr], b0h, b1h);   // lh
                        mma_fp16(acc[mr][nt], ah[mr], b0l, b1l);   // hl
                    }
                }
            }
        }
        __syncthreads();   // all warps done with this buffer before refill
    }

    // ============ routing directly on register accumulators ============
    // acc[mr][nt][0,1] -> row (wrow+mr*16+g),   cols wcol+nt*8+2q+{0,1}
    // acc[mr][nt][2,3] -> row (wrow+mr*16+g+8), same cols
    if (tid < M) logits[tid] = 0.0f;

    for (int it = 0; it < 3; ++it) {
        // ---- probs = softmax(logits) ----
        if (it == 0) {
            if (tid < M) probs[tid] = 1.0f / (float)M;
        } else {
            float lv = (tid < M) ? logits[tid] : -3.402823466e38f;
            float mx = blockMax(lv, red);
            float ev = (tid < M) ? expf(lv - mx) : 0.0f;
            float Z = blockSum(ev, red);
            if (tid < M) probs[tid] = ev / Z;
        }
        __syncthreads();

        // ---- s[d] = sum_b probs[b] * P[b][d] from registers ----
        {
            float pr[MR][2];
            #pragma unroll
            for (int mr = 0; mr < MR; ++mr) {
                pr[mr][0] = probs[wrow + mr * 16 + g];
                pr[mr][1] = probs[wrow + mr * 16 + g + 8];
            }
            #pragma unroll
            for (int nt = 0; nt < 8; ++nt) {
                float c0 = 0.0f, c1 = 0.0f;
                #pragma unroll
                for (int mr = 0; mr < MR; ++mr) {
                    c0 = fmaf(pr[mr][0], acc[mr][nt][0], fmaf(pr[mr][1], acc[mr][nt][2], c0));
                    c1 = fmaf(pr[mr][0], acc[mr][nt][1], fmaf(pr[mr][1], acc[mr][nt][3], c1));
                }
                // reduce over the 8 g-lanes (stride-4 butterfly)
                #pragma unroll
                for (int o = 4; o <= 16; o <<= 1) {
                    c0 += __shfl_xor_sync(0xffffffffu, c0, o);
                    c1 += __shfl_xor_sync(0xffffffffu, c1, o);
                }
                if (g == 0) {
                    part[rg * 256 + wcol + nt * 8 + 2 * q]     = c0;
                    part[rg * 256 + wcol + nt * 8 + 2 * q + 1] = c1;
                }
            }
        }
        __syncthreads();

        // ---- squash ----
        float sd = 0.0f;
        if (tid < 256)
            sd = part[tid] + part[256 + tid] + part[512 + tid] + part[768 + tid];
        float sq = blockSum(sd * sd, red);
        float scale = sq / ((1.0f + sq) * sqrtf(sq));
        if (tid < 256) vout[tid] = sd * scale;
        __syncthreads();

        if (it < 2) {
            // ---- logits[b] += sum_d P[b][d] * v[d] from registers ----
            float rowp[MR][2];
            #pragma unroll
            for (int mr = 0; mr < MR; ++mr) { rowp[mr][0] = 0.0f; rowp[mr][1] = 0.0f; }
            #pragma unroll
            for (int nt = 0; nt < 8; ++nt) {
                float v0 = vout[wcol + nt * 8 + 2 * q];
                float v1 = vout[wcol + nt * 8 + 2 * q + 1];
                #pragma unroll
                for (int mr = 0; mr < MR; ++mr) {
                    rowp[mr][0] = fmaf(acc[mr][nt][0], v0, fmaf(acc[mr][nt][1], v1, rowp[mr][0]));
                    rowp[mr][1] = fmaf(acc[mr][nt][2], v0, fmaf(acc[mr][nt][3], v1, rowp[mr][1]));
                }
            }
            // reduce over the 4 q-lanes
            #pragma unroll
            for (int mr = 0; mr < MR; ++mr) {
                #pragma unroll
                for (int o = 1; o <= 2; o <<= 1) {
                    rowp[mr][0] += __shfl_xor_sync(0xffffffffu, rowp[mr][0], o);
                    rowp[mr][1] += __shfl_xor_sync(0xffffffffu, rowp[mr][1], o);
                }
            }
            __syncthreads();   // part free
            if (q == 0) {
                #pragma unroll
                for (int mr = 0; mr < MR; ++mr) {
                    part[cg * M + wrow + mr * 16 + g]     = rowp[mr][0];
                    part[cg * M + wrow + mr * 16 + g + 8] = rowp[mr][1];
                }
            }
            __syncthreads();
            if (tid < M)
                logits[tid] += part[tid] + part[M + tid] + part[2 * M + tid] + part[3 * M + tid];
            __syncthreads();
        } else {
            if (tid < 256) {
                float v = vout[tid];
                size_t o = (size_t)blockIdx.x * outXStride + (size_t)blockIdx.y * outYStride + tid;
                if (F32OUT) {
                    OutF[o] = v;
                } else {
                    __half h, l;
                    split2(v, h, l);
                    OutH[o] = h; OutL[o] = l;
                }
            }
        }
    }
}

static size_t stage_smem(int M) {
    size_t buf = 2ull * M * 40 * 2 + 2ull * 256 * 40 * 2;   // one pipeline buffer
    size_t scr = (1024 + 256 + 2 * (size_t)M + 64) * 4;
    return 2 * buf + scr;
}

extern "C" void kernel_launch(void* const* d_in, const int* in_sizes, int n_in,
                              void* d_out, int out_size) {
    (void)in_sizes; (void)n_in; (void)out_size;
    const float* x  = (const float*)d_in[0];   // [64,128,256]
    const float* w1 = (const float*)d_in[1];   // [64,256,256]
    const float* w2 = (const float*)d_in[2];   // [32,256,256]
    float* out = (float*)d_out;                // [32,64,256]

    void* p;
    cudaGetSymbolAddress(&p, g_xh);  __half* xh  = (__half*)p;
    cudaGetSymbolAddress(&p, g_xl);  __half* xl  = (__half*)p;
    cudaGetSymbolAddress(&p, g_w1h); __half* w1h = (__half*)p;
    cudaGetSymbolAddress(&p, g_w1l); __half* w1l = (__half*)p;
    cudaGetSymbolAddress(&p, g_w2h); __half* w2h = (__half*)p;
    cudaGetSymbolAddress(&p, g_w2l); __half* w2l = (__half*)p;
    cudaGetSymbolAddress(&p, g_o1h); __half* o1h = (__half*)p;
    cudaGetSymbolAddress(&p, g_o1l); __half* o1l = (__half*)p;

    // pre-pass: fp16 hi/lo splits (+ W transposed to [n][k])
    split_x_kernel<<<8192, 256>>>(x, xh, xl, 64 * 128 * 256);
    trans_split_w<<<dim3(8, 8, 64), 256>>>(w1, w1h, w1l);
    trans_split_w<<<dim3(8, 8, 32), 256>>>(w2, w2h, w2l);

    const size_t sm1 = stage_smem(128);   // ~129 KB
    const size_t sm2 = stage_smem(64);    // ~109 KB
    cudaFuncSetAttribute((const void*)caps_mma_route<128, false, 1>,
                         cudaFuncAttributeMaxDynamicSharedMemorySize, (int)sm1);
    cudaFuncSetAttribute((const void*)caps_mma_route<64, true, 2>,
                         cudaFuncAttributeMaxDynamicSharedMemorySize, (int)sm2);

    // Stage 1: (a=64, h=64) -> out1 fp16 h/l [a][h][256]
    caps_mma_route<128, false, 1><<<dim3(64, 64), 512, sm1>>>(
        xh, xl, w1h, w1l, nullptr, o1h, o1l, /*x=a*/ 64 * 256, /*y=h*/ 256);

    // Stage 2: (a=64, c=32) -> out fp32 [c][a][256]; 2 CTAs/SM
    caps_mma_route<64, true, 2><<<dim3(64, 32), 512, sm2>>>(
        o1h, o1l, w2h, w2l, out, nullptr, nullptr, /*x=a*/ 256, /*y=c*/ 64 * 256);
}

// round 13
// speedup vs baseline: 3.0942x; 1.0511x over previous
#include <cuda_runtime.h>
#include <cuda_fp16.h>
#include <math.h>
#include <stdint.h>

// ---------------- device globals (no allocations allowed) ----------------
// 2-level fp16 splits: v = vh + vl (each level fp16)
__device__ __half g_xh[64 * 128 * 256], g_xl[64 * 128 * 256];     // X split    [a][b][d]
__device__ __half g_w1h[64 * 256 * 256], g_w1l[64 * 256 * 256];   // W1^T split [h][n][k]
__device__ __half g_w2h[32 * 256 * 256], g_w2l[32 * 256 * 256];   // W2^T split [c][n][k]
__device__ __half g_o1h[64 * 64 * 256], g_o1l[64 * 64 * 256];     // out1 split [a][h][d]

// ---------------- fp16 HMMA via mma.sync (sm_80+ baseline PTX) ----------------
__device__ __forceinline__ void mma_fp16(float* c, const uint32_t* a, uint32_t b0, uint32_t b1) {
    asm volatile(
        "mma.sync.aligned.m16n8k16.row.col.f32.f16.f16.f32 "
        "{%0,%1,%2,%3}, {%4,%5,%6,%7}, {%8,%9}, {%0,%1,%2,%3};"
        : "+f"(c[0]), "+f"(c[1]), "+f"(c[2]), "+f"(c[3])
        : "r"(a[0]), "r"(a[1]), "r"(a[2]), "r"(a[3]), "r"(b0), "r"(b1));
}

// ---------------- ldmatrix x4 (sm_75+ baseline PTX) ----------------
__device__ __forceinline__ void ldsm_x4(uint32_t* r, uint32_t addr) {
    asm volatile("ldmatrix.sync.aligned.m8n8.x4.shared.b16 {%0,%1,%2,%3}, [%4];"
                 : "=r"(r[0]), "=r"(r[1]), "=r"(r[2]), "=r"(r[3]) : "r"(addr));
}

// ---------------- cp.async helpers (sm_80+ baseline PTX) ----------------
__device__ __forceinline__ void cp16(uint32_t smem_dst, const void* gsrc) {
    asm volatile("cp.async.cg.shared.global [%0], [%1], 16;" :: "r"(smem_dst), "l"(gsrc));
}
__device__ __forceinline__ void cp_commit() {
    asm volatile("cp.async.commit_group;");
}
template<int N>
__device__ __forceinline__ void cp_wait() {
    asm volatile("cp.async.wait_group %0;" :: "n"(N));
}
__device__ __forceinline__ uint32_t smem_u32(const void* p) {
    uint32_t a;
    asm("{ .reg .u64 t; cvta.to.shared.u64 t, %1; cvt.u32.u64 %0, t; }" : "=r"(a) : "l"(p));
    return a;
}

// ---------------- block reductions over 256 threads (8 warps) ----------------
__device__ __forceinline__ float warpSum(float v) {
    #pragma unroll
    for (int o = 16; o; o >>= 1) v += __shfl_down_sync(0xffffffffu, v, o);
    return v;
}
__device__ __forceinline__ float warpMax(float v) {
    #pragma unroll
    for (int o = 16; o; o >>= 1) v = fmaxf(v, __shfl_down_sync(0xffffffffu, v, o));
    return v;
}
__device__ __forceinline__ float blockSum(float v, float* red) {
    v = warpSum(v);
    __syncthreads();
    if ((threadIdx.x & 31) == 0) red[threadIdx.x >> 5] = v;
    __syncthreads();
    if (threadIdx.x < 32) {
        float x = (threadIdx.x < 8) ? red[threadIdx.x] : 0.0f;
        x = warpSum(x);
        if (threadIdx.x == 0) red[32] = x;
    }
    __syncthreads();
    return red[32];
}
__device__ __forceinline__ float blockMax(float v, float* red) {
    v = warpMax(v);
    __syncthreads();
    if ((threadIdx.x & 31) == 0) red[threadIdx.x >> 5] = v;
    __syncthreads();
    if (threadIdx.x < 32) {
        float x = (threadIdx.x < 8) ? red[threadIdx.x] : -3.402823466e38f;
        x = warpMax(x);
        if (threadIdx.x == 0) red[32] = x;
    }
    __syncthreads();
    return red[32];
}

// 2-level fp16 split of a float
__device__ __forceinline__ void split2(float v, __half& h, __half& l) {
    h = __float2half_rn(v);
    l = __float2half_rn(v - __half2float(h));
}

// ---------------- pre-pass: split X into fp16 h/l ----------------
__global__ void split_x_kernel(const float* __restrict__ x,
                               __half* __restrict__ xh, __half* __restrict__ xl, int n) {
    int i = blockIdx.x * blockDim.x + threadIdx.x;
    if (i >= n) return;
    __half h, l;
    split2(x[i], h, l);
    xh[i] = h; xl[i] = l;
}

// ---------------- pre-pass: transpose + split W[k][n] -> Wt[n][k] fp16 h/l ----------------
__global__ void trans_split_w(const float* __restrict__ W,
                              __half* __restrict__ Wth, __half* __restrict__ Wtl) {
    __shared__ float st[32][33];
    int mb = blockIdx.z, k0 = blockIdx.x * 32, n0 = blockIdx.y * 32;
    const float* Wm = W + (size_t)mb * 65536;
    int tid = threadIdx.x;
    #pragma unroll
    for (int i = 0; i < 4; ++i) {
        int e = tid + i * 256, k = e >> 5, n = e & 31;
        st[k][n] = Wm[(k0 + k) * 256 + n0 + n];
    }
    __syncthreads();
    #pragma unroll
    for (int i = 0; i < 4; ++i) {
        int e = tid + i * 256, n = e >> 5, k = e & 31;
        float f = st[k][n];
        __half h, l;
        split2(f, h, l);
        size_t o = (size_t)mb * 65536 + (size_t)(n0 + n) * 256 + k0 + k;
        Wth[o] = h; Wtl[o] = l;
    }
}

// ---------------- fused HMMA-GEMM + register-resident routing ----------------
// One CTA = one (weight, batch) pair. 256 threads, 8 warps:
//   4 row-groups x 2 col-groups; warp tile (M/4) x 128 (16 n-tiles).
//   P[M,256] via 3-term 2-level fp16 split (hh + lh + hl), cp.async
//   double-buffered, ldmatrix fragments, register-resident routing.
template<int M, bool F32OUT, int MINCTA>
__global__ void __launch_bounds__(256, MINCTA)
caps_mma_route(const __half* __restrict__ AhG, const __half* __restrict__ AlG,
               const __half* __restrict__ BhG, const __half* __restrict__ BlG,
               float* __restrict__ OutF,
               __half* __restrict__ OutH, __half* __restrict__ OutL,
               int outXStride, int outYStride)
{
    constexpr int KC = 32;               // k-chunk
    constexpr int NT = 256 / KC;         // 8 chunks
    constexpr int TS = KC + 8;           // 40 fp16 row stride (80B, 16B-aligned)
    constexpr int MR = M / 64;           // mma row-tiles per warp (2 / 1)
    constexpr uint32_t ATB = (uint32_t)M * TS * 2;    // one A level tile bytes
    constexpr uint32_t BTB = 256u * TS * 2;           // one B level tile bytes
    constexpr uint32_t BUF = 2 * ATB + 2 * BTB;       // one pipeline buffer
    constexpr uint32_t SCR = 2 * BUF;

    extern __shared__ char smc[];
    const uint32_t smb = smem_u32(smc);
    float* part   = (float*)(smc + SCR);   // 1024 floats (4 x 256 combine buffer)
    float* vout   = part + 1024;           // 256
    float* probs  = vout + 256;            // M
    float* logits = probs + M;             // M
    float* red    = logits + M;            // 64

    const int tid = threadIdx.x;
    const int wid = tid >> 5, lane = tid & 31;
    const int g = lane >> 2, q = lane & 3;           // mma fragment coords
    const int rg = wid >> 1, cg = wid & 1;           // row-group (4) / col-group (2)
    const int wrow = rg * (M / 4);                   // warp row base
    const int wcol = cg * 128;                       // warp col base

    // ldmatrix lane-address components
    const int lsub = lane & 7;                       // row within 8x8 matrix
    const int lmi  = lane >> 3;                      // matrix index 0..3
    const int aRowOff = lsub + (lmi & 1) * 8;        // A: m0/m2 rows 0-7, m1/m3 rows 8-15
    const int aColOff = (lmi >> 1) * 8;              // A: m0/m1 cols k0, m2/m3 cols k0+8
    const int bColOff = (lmi & 1) * 8;               // B: m0/m2 col k0, m1/m3 col k0+8
    const int bNtOff  = (lmi >> 1);                  // B: m0/m1 -> nt, m2/m3 -> nt+1

    const size_t aOff = (size_t)blockIdx.x * (M * 256);
    const size_t bOff = (size_t)blockIdx.y * 65536u;
    const __half* Asrc[2] = { AhG + aOff, AlG + aOff };
    const __half* Bsrc[2] = { BhG + bOff, BlG + bOff };

    // -------- async tile loader: chunk t -> buffer at byte offset bb --------
    auto load_chunk = [&](uint32_t bb, int t) {
        const int k0g = t * KC;
        #pragma unroll
        for (int lv = 0; lv < 2; ++lv) {
            const __half* src = Asrc[lv] + k0g;
            uint32_t dstb = smb + bb + lv * ATB;
            #pragma unroll
            for (int e = tid; e < M * 4; e += 256) {
                int r = e >> 2, seg = e & 3;
                cp16(dstb + (uint32_t)(r * TS + seg * 8) * 2, src + r * 256 + seg * 8);
            }
        }
        #pragma unroll
        for (int lv = 0; lv < 2; ++lv) {
            const __half* src = Bsrc[lv] + k0g;
            uint32_t dstb = smb + bb + 2 * ATB + lv * BTB;
            #pragma unroll
            for (int e = tid; e < 1024; e += 256) {
                int r = e >> 2, seg = e & 3;
                cp16(dstb + (uint32_t)(r * TS + seg * 8) * 2, src + r * 256 + seg * 8);
            }
        }
        cp_commit();
    };

    // ============ GEMM: 8 K-chunks of 32, 3-term 2-level fp16 split ============
    float acc[MR][16][4];
    #pragma unroll
    for (int mr = 0; mr < MR; ++mr)
        #pragma unroll
        for (int nt = 0; nt < 16; ++nt)
            #pragma unroll
            for (int j = 0; j < 4; ++j) acc[mr][nt][j] = 0.0f;

    load_chunk(0, 0);

    for (int t = 0; t < NT; ++t) {
        const uint32_t bb = (t & 1) ? BUF : 0;
        if (t + 1 < NT) {
            load_chunk((t & 1) ? 0 : BUF, t + 1);
            cp_wait<1>();
        } else {
            cp_wait<0>();
        }
        __syncthreads();

        const uint32_t aBase = smb + bb;
        const uint32_t bBase = smb + bb + 2 * ATB;

        #pragma unroll
        for (int ks = 0; ks < KC / 16; ++ks) {
            const int k0 = ks * 16;
            // A fragments via ldmatrix.x4 (both levels)
            uint32_t ah[MR][4], al[MR][4];
            #pragma unroll
            for (int mr = 0; mr < MR; ++mr) {
                uint32_t aAddr = aBase +
                    (uint32_t)(((wrow + mr * 16 + aRowOff) * TS + k0 + aColOff) * 2);
                ldsm_x4(ah[mr], aAddr);
                ldsm_x4(al[mr], aAddr + ATB);
            }
            // B fragments per nt-pair (8 pairs covering 16 n-tiles)
            #pragma unroll
            for (int j = 0; j < 8; ++j) {
                uint32_t bAddr = bBase +
                    (uint32_t)(((wcol + (2 * j + bNtOff) * 8 + lsub) * TS + k0 + bColOff) * 2);
                uint32_t rh[4], rl[4];
                ldsm_x4(rh, bAddr);
                ldsm_x4(rl, bAddr + BTB);
                #pragma unroll
                for (int u = 0; u < 2; ++u) {
                    const int nt = 2 * j + u;
                    const uint32_t b0h = rh[2 * u], b1h = rh[2 * u + 1];
                    const uint32_t b0l = rl[2 * u], b1l = rl[2 * u + 1];
                    #pragma unroll
                    for (int mr = 0; mr < MR; ++mr) {
                        mma_fp16(acc[mr][nt], ah[mr], b0h, b1h);   // hh
                        mma_fp16(acc[mr][nt], al[mr], b0h, b1h);   // lh
                        mma_fp16(acc[mr][nt], ah[mr], b0l, b1l);   // hl
                    }
                }
            }
        }
        __syncthreads();   // all warps done with this buffer before refill
    }

    // ============ routing directly on register accumulators ============
    // acc[mr][nt][0,1] -> row (wrow+mr*16+g),   cols wcol+nt*8+2q+{0,1}
    // acc[mr][nt][2,3] -> row (wrow+mr*16+g+8), same cols
    if (tid < M) logits[tid] = 0.0f;

    for (int it = 0; it < 3; ++it) {
        // ---- probs = softmax(logits) ----
        if (it == 0) {
            if (tid < M) probs[tid] = 1.0f / (float)M;
        } else {
            float lv = (tid < M) ? logits[tid] : -3.402823466e38f;
            float mx = blockMax(lv, red);
            float ev = (tid < M) ? expf(lv - mx) : 0.0f;
            float Z = blockSum(ev, red);
            if (tid < M) probs[tid] = ev / Z;
        }
        __syncthreads();

        // ---- s[d] = sum_b probs[b] * P[b][d] from registers ----
        {
            float pr[MR][2];
            #pragma unroll
            for (int mr = 0; mr < MR; ++mr) {
                pr[mr][0] = probs[wrow + mr * 16 + g];
                pr[mr][1] = probs[wrow + mr * 16 + g + 8];
            }
            #pragma unroll
            for (int nt = 0; nt < 16; ++nt) {
                float c0 = 0.0f, c1 = 0.0f;
                #pragma unroll
                for (int mr = 0; mr < MR; ++mr) {
                    c0 = fmaf(pr[mr][0], acc[mr][nt][0], fmaf(pr[mr][1], acc[mr][nt][2], c0));
                    c1 = fmaf(pr[mr][0], acc[mr][nt][1], fmaf(pr[mr][1], acc[mr][nt][3], c1));
                }
                // reduce over the 8 g-lanes (stride-4 butterfly)
                #pragma unroll
                for (int o = 4; o <= 16; o <<= 1) {
                    c0 += __shfl_xor_sync(0xffffffffu, c0, o);
                    c1 += __shfl_xor_sync(0xffffffffu, c1, o);
                }
                if (g == 0) {
                    part[rg * 256 + wcol + nt * 8 + 2 * q]     = c0;
                    part[rg * 256 + wcol + nt * 8 + 2 * q + 1] = c1;
                }
            }
        }
        __syncthreads();

        // ---- squash ----
        float sd = 0.0f;
        if (tid < 256)
            sd = part[tid] + part[256 + tid] + part[512 + tid] + part[768 + tid];
        float sq = blockSum(sd * sd, red);
        float scale = sq / ((1.0f + sq) * sqrtf(sq));
        if (tid < 256) vout[tid] = sd * scale;
        __syncthreads();

        if (it < 2) {
            // ---- logits[b] += sum_d P[b][d] * v[d] from registers ----
            float rowp[MR][2];
            #pragma unroll
            for (int mr = 0; mr < MR; ++mr) { rowp[mr][0] = 0.0f; rowp[mr][1] = 0.0f; }
            #pragma unroll
            for (int nt = 0; nt < 16; ++nt) {
                float v0 = vout[wcol + nt * 8 + 2 * q];
                float v1 = vout[wcol + nt * 8 + 2 * q + 1];
                #pragma unroll
                for (int mr = 0; mr < MR; ++mr) {
                    rowp[mr][0] = fmaf(acc[mr][nt][0], v0, fmaf(acc[mr][nt][1], v1, rowp[mr][0]));
                    rowp[mr][1] = fmaf(acc[mr][nt][2], v0, fmaf(acc[mr][nt][3], v1, rowp[mr][1]));
                }
            }
            // reduce over the 4 q-lanes
            #pragma unroll
            for (int mr = 0; mr < MR; ++mr) {
                #pragma unroll
                for (int o = 1; o <= 2; o <<= 1) {
                    rowp[mr][0] += __shfl_xor_sync(0xffffffffu, rowp[mr][0], o);
                    rowp[mr][1] += __shfl_xor_sync(0xffffffffu, rowp[mr][1], o);
                }
            }
            __syncthreads();   // part free
            if (q == 0) {
                #pragma unroll
                for (int mr = 0; mr < MR; ++mr) {
                    part[cg * M + wrow + mr * 16 + g]     = rowp[mr][0];
                    part[cg * M + wrow + mr * 16 + g + 8] = rowp[mr][1];
                }
            }
            __syncthreads();
            if (tid < M)
                logits[tid] += part[tid] + part[M + tid];
            __syncthreads();
        } else {
            if (tid < 256) {
                float v = vout[tid];
                size_t o = (size_t)blockIdx.x * outXStride + (size_t)blockIdx.y * outYStride + tid;
                if (F32OUT) {
                    OutF[o] = v;
                } else {
                    __half h, l;
                    split2(v, h, l);
                    OutH[o] = h; OutL[o] = l;
                }
            }
        }
    }
}

static size_t stage_smem(int M) {
    size_t buf = 2ull * M * 40 * 2 + 2ull * 256 * 40 * 2;   // one pipeline buffer
    size_t scr = (1024 + 256 + 2 * (size_t)M + 64) * 4;
    return 2 * buf + scr;
}

extern "C" void kernel_launch(void* const* d_in, const int* in_sizes, int n_in,
                              void* d_out, int out_size) {
    (void)in_sizes; (void)n_in; (void)out_size;
    const float* x  = (const float*)d_in[0];   // [64,128,256]
    const float* w1 = (const float*)d_in[1];   // [64,256,256]
    const float* w2 = (const float*)d_in[2];   // [32,256,256]
    float* out = (float*)d_out;                // [32,64,256]

    void* p;
    cudaGetSymbolAddress(&p, g_xh);  __half* xh  = (__half*)p;
    cudaGetSymbolAddress(&p, g_xl);  __half* xl  = (__half*)p;
    cudaGetSymbolAddress(&p, g_w1h); __half* w1h = (__half*)p;
    cudaGetSymbolAddress(&p, g_w1l); __half* w1l = (__half*)p;
    cudaGetSymbolAddress(&p, g_w2h); __half* w2h = (__half*)p;
    cudaGetSymbolAddress(&p, g_w2l); __half* w2l = (__half*)p;
    cudaGetSymbolAddress(&p, g_o1h); __half* o1h = (__half*)p;
    cudaGetSymbolAddress(&p, g_o1l); __half* o1l = (__half*)p;

    // pre-pass: fp16 hi/lo splits (+ W transposed to [n][k])
    split_x_kernel<<<8192, 256>>>(x, xh, xl, 64 * 128 * 256);
    trans_split_w<<<dim3(8, 8, 64), 256>>>(w1, w1h, w1l);
    trans_split_w<<<dim3(8, 8, 32), 256>>>(w2, w2h, w2l);

    const size_t sm1 = stage_smem(128);   // ~129 KB
    const size_t sm2 = stage_smem(64);    // ~109 KB
    cudaFuncSetAttribute((const void*)caps_mma_route<128, false, 1>,
                         cudaFuncAttributeMaxDynamicSharedMemorySize, (int)sm1);
    cudaFuncSetAttribute((const void*)caps_mma_route<64, true, 2>,
                         cudaFuncAttributeMaxDynamicSharedMemorySize, (int)sm2);

    // Stage 1: (a=64, h=64) -> out1 fp16 h/l [a][h][256]
    caps_mma_route<128, false, 1><<<dim3(64, 64), 256, sm1>>>(
        xh, xl, w1h, w1l, nullptr, o1h, o1l, /*x=a*/ 64 * 256, /*y=h*/ 256);

    // Stage 2: (a=64, c=32) -> out fp32 [c][a][256]; 2 CTAs/SM
    caps_mma_route<64, true, 2><<<dim3(64, 32), 256, sm2>>>(
        o1h, o1l, w2h, w2l, out, nullptr, nullptr, /*x=a*/ 256, /*y=c*/ 64 * 256);
}

// round 14
// speedup vs baseline: 3.0983x; 1.0013x over previous
#include <cuda_runtime.h>
#include <cuda_fp16.h>
#include <math.h>
#include <stdint.h>

// ---------------- device globals (no allocations allowed) ----------------
// 2-level fp16 splits: v = vh + vl (each level fp16)
__device__ __half g_xh[64 * 128 * 256], g_xl[64 * 128 * 256];     // X split    [a][b][d]
__device__ __half g_w1h[64 * 256 * 256], g_w1l[64 * 256 * 256];   // W1^T split [h][n][k]
__device__ __half g_w2h[32 * 256 * 256], g_w2l[32 * 256 * 256];   // W2^T split [c][n][k]
__device__ __half g_o1h[64 * 64 * 256], g_o1l[64 * 64 * 256];     // out1 split [a][h][d]

// ---------------- fp16 HMMA via mma.sync (sm_80+ baseline PTX) ----------------
__device__ __forceinline__ void mma_fp16(float* c, const uint32_t* a, uint32_t b0, uint32_t b1) {
    asm volatile(
        "mma.sync.aligned.m16n8k16.row.col.f32.f16.f16.f32 "
        "{%0,%1,%2,%3}, {%4,%5,%6,%7}, {%8,%9}, {%0,%1,%2,%3};"
        : "+f"(c[0]), "+f"(c[1]), "+f"(c[2]), "+f"(c[3])
        : "r"(a[0]), "r"(a[1]), "r"(a[2]), "r"(a[3]), "r"(b0), "r"(b1));
}

// ---------------- ldmatrix x4 (sm_75+ baseline PTX) ----------------
__device__ __forceinline__ void ldsm_x4(uint32_t* r, uint32_t addr) {
    asm volatile("ldmatrix.sync.aligned.m8n8.x4.shared.b16 {%0,%1,%2,%3}, [%4];"
                 : "=r"(r[0]), "=r"(r[1]), "=r"(r[2]), "=r"(r[3]) : "r"(addr));
}

// ---------------- cp.async helpers (sm_80+ baseline PTX) ----------------
__device__ __forceinline__ void cp16(uint32_t smem_dst, const void* gsrc) {
    asm volatile("cp.async.cg.shared.global [%0], [%1], 16;" :: "r"(smem_dst), "l"(gsrc));
}
__device__ __forceinline__ void cp_commit() {
    asm volatile("cp.async.commit_group;");
}
template<int N>
__device__ __forceinline__ void cp_wait() {
    asm volatile("cp.async.wait_group %0;" :: "n"(N));
}
__device__ __forceinline__ uint32_t smem_u32(const void* p) {
    uint32_t a;
    asm("{ .reg .u64 t; cvta.to.shared.u64 t, %1; cvt.u32.u64 %0, t; }" : "=r"(a) : "l"(p));
    return a;
}

// ---------------- block reductions over 256 threads (8 warps) ----------------
__device__ __forceinline__ float warpSum(float v) {
    #pragma unroll
    for (int o = 16; o; o >>= 1) v += __shfl_down_sync(0xffffffffu, v, o);
    return v;
}
__device__ __forceinline__ float warpMax(float v) {
    #pragma unroll
    for (int o = 16; o; o >>= 1) v = fmaxf(v, __shfl_down_sync(0xffffffffu, v, o));
    return v;
}
__device__ __forceinline__ float blockSum(float v, float* red) {
    v = warpSum(v);
    __syncthreads();
    if ((threadIdx.x & 31) == 0) red[threadIdx.x >> 5] = v;
    __syncthreads();
    if (threadIdx.x < 32) {
        float x = (threadIdx.x < 8) ? red[threadIdx.x] : 0.0f;
        x = warpSum(x);
        if (threadIdx.x == 0) red[32] = x;
    }
    __syncthreads();
    return red[32];
}
__device__ __forceinline__ float blockMax(float v, float* red) {
    v = warpMax(v);
    __syncthreads();
    if ((threadIdx.x & 31) == 0) red[threadIdx.x >> 5] = v;
    __syncthreads();
    if (threadIdx.x < 32) {
        float x = (threadIdx.x < 8) ? red[threadIdx.x] : -3.402823466e38f;
        x = warpMax(x);
        if (threadIdx.x == 0) red[32] = x;
    }
    __syncthreads();
    return red[32];
}

// 2-level fp16 split of a float
__device__ __forceinline__ void split2(float v, __half& h, __half& l) {
    h = __float2half_rn(v);
    l = __float2half_rn(v - __half2float(h));
}

// ---------------- pre-pass: split X into fp16 h/l ----------------
__global__ void split_x_kernel(const float* __restrict__ x,
                               __half* __restrict__ xh, __half* __restrict__ xl, int n) {
    int i = blockIdx.x * blockDim.x + threadIdx.x;
    if (i >= n) return;
    __half h, l;
    split2(x[i], h, l);
    xh[i] = h; xl[i] = l;
}

// ---------------- pre-pass: transpose + split W[k][n] -> Wt[n][k] fp16 h/l ----------------
__global__ void trans_split_w(const float* __restrict__ W,
                              __half* __restrict__ Wth, __half* __restrict__ Wtl) {
    __shared__ float st[32][33];
    int mb = blockIdx.z, k0 = blockIdx.x * 32, n0 = blockIdx.y * 32;
    const float* Wm = W + (size_t)mb * 65536;
    int tid = threadIdx.x;
    #pragma unroll
    for (int i = 0; i < 4; ++i) {
        int e = tid + i * 256, k = e >> 5, n = e & 31;
        st[k][n] = Wm[(k0 + k) * 256 + n0 + n];
    }
    __syncthreads();
    #pragma unroll
    for (int i = 0; i < 4; ++i) {
        int e = tid + i * 256, n = e >> 5, k = e & 31;
        float f = st[k][n];
        __half h, l;
        split2(f, h, l);
        size_t o = (size_t)mb * 65536 + (size_t)(n0 + n) * 256 + k0 + k;
        Wth[o] = h; Wtl[o] = l;
    }
}

// ---------------- fused HMMA-GEMM + register-resident routing ----------------
// One CTA = one (weight, batch) pair. 256 threads, 8 warps:
//   4 row-groups x 2 col-groups; warp tile (M/4) x 128 (16 n-tiles).
//   3-term 2-level fp16 split (hh + lh + hl) issued in PASSES of 16
//   independent MMAs (different accumulators) to break HMMA RAW chains.
template<int M, bool F32OUT, int MINCTA>
__global__ void __launch_bounds__(256, MINCTA)
caps_mma_route(const __half* __restrict__ AhG, const __half* __restrict__ AlG,
               const __half* __restrict__ BhG, const __half* __restrict__ BlG,
               float* __restrict__ OutF,
               __half* __restrict__ OutH, __half* __restrict__ OutL,
               int outXStride, int outYStride)
{
    constexpr int KC = 32;               // k-chunk
    constexpr int NT = 256 / KC;         // 8 chunks
    constexpr int TS = KC + 8;           // 40 fp16 row stride (80B, 16B-aligned)
    constexpr int MR = M / 64;           // mma row-tiles per warp (2 / 1)
    constexpr uint32_t ATB = (uint32_t)M * TS * 2;    // one A level tile bytes
    constexpr uint32_t BTB = 256u * TS * 2;           // one B level tile bytes
    constexpr uint32_t BUF = 2 * ATB + 2 * BTB;       // one pipeline buffer
    constexpr uint32_t SCR = 2 * BUF;

    extern __shared__ char smc[];
    const uint32_t smb = smem_u32(smc);
    float* part   = (float*)(smc + SCR);   // 1024 floats (4 x 256 combine buffer)
    float* vout   = part + 1024;           // 256
    float* probs  = vout + 256;            // M
    float* logits = probs + M;             // M
    float* red    = logits + M;            // 64

    const int tid = threadIdx.x;
    const int wid = tid >> 5, lane = tid & 31;
    const int g = lane >> 2, q = lane & 3;           // mma fragment coords
    const int rg = wid >> 1, cg = wid & 1;           // row-group (4) / col-group (2)
    const int wrow = rg * (M / 4);                   // warp row base
    const int wcol = cg * 128;                       // warp col base

    // ldmatrix lane-address components
    const int lsub = lane & 7;                       // row within 8x8 matrix
    const int lmi  = lane >> 3;                      // matrix index 0..3
    const int aRowOff = lsub + (lmi & 1) * 8;        // A: m0/m2 rows 0-7, m1/m3 rows 8-15
    const int aColOff = (lmi >> 1) * 8;              // A: m0/m1 cols k0, m2/m3 cols k0+8
    const int bColOff = (lmi & 1) * 8;               // B: m0/m2 col k0, m1/m3 col k0+8
    const int bNtOff  = (lmi >> 1);                  // B: m0/m1 -> nt, m2/m3 -> nt+1

    const size_t aOff = (size_t)blockIdx.x * (M * 256);
    const size_t bOff = (size_t)blockIdx.y * 65536u;
    const __half* Asrc[2] = { AhG + aOff, AlG + aOff };
    const __half* Bsrc[2] = { BhG + bOff, BlG + bOff };

    // -------- async tile loader: chunk t -> buffer at byte offset bb --------
    auto load_chunk = [&](uint32_t bb, int t) {
        const int k0g = t * KC;
        #pragma unroll
        for (int lv = 0; lv < 2; ++lv) {
            const __half* src = Asrc[lv] + k0g;
            uint32_t dstb = smb + bb + lv * ATB;
            #pragma unroll
            for (int e = tid; e < M * 4; e += 256) {
                int r = e >> 2, seg = e & 3;
                cp16(dstb + (uint32_t)(r * TS + seg * 8) * 2, src + r * 256 + seg * 8);
            }
        }
        #pragma unroll
        for (int lv = 0; lv < 2; ++lv) {
            const __half* src = Bsrc[lv] + k0g;
            uint32_t dstb = smb + bb + 2 * ATB + lv * BTB;
            #pragma unroll
            for (int e = tid; e < 1024; e += 256) {
                int r = e >> 2, seg = e & 3;
                cp16(dstb + (uint32_t)(r * TS + seg * 8) * 2, src + r * 256 + seg * 8);
            }
        }
        cp_commit();
    };

    // ============ GEMM: 8 K-chunks of 32, 3-term 2-level fp16 split ============
    float acc[MR][16][4];
    #pragma unroll
    for (int mr = 0; mr < MR; ++mr)
        #pragma unroll
        for (int nt = 0; nt < 16; ++nt)
            #pragma unroll
            for (int j = 0; j < 4; ++j) acc[mr][nt][j] = 0.0f;

    load_chunk(0, 0);

    for (int t = 0; t < NT; ++t) {
        const uint32_t bb = (t & 1) ? BUF : 0;
        if (t + 1 < NT) {
            load_chunk((t & 1) ? 0 : BUF, t + 1);
            cp_wait<1>();
        } else {
            cp_wait<0>();
        }
        __syncthreads();

        const uint32_t aBase = smb + bb;
        const uint32_t bBase = smb + bb + 2 * ATB;

        #pragma unroll
        for (int ks = 0; ks < KC / 16; ++ks) {
            const int k0 = ks * 16;
            // A fragments via ldmatrix.x4 (both levels)
            uint32_t ah[MR][4], al[MR][4];
            #pragma unroll
            for (int mr = 0; mr < MR; ++mr) {
                uint32_t aAddr = aBase +
                    (uint32_t)(((wrow + mr * 16 + aRowOff) * TS + k0 + aColOff) * 2);
                ldsm_x4(ah[mr], aAddr);
                ldsm_x4(al[mr], aAddr + ATB);
            }
            // Process nt in groups of 8 (4 pair-ldsm per level); within a
            // group issue 3 passes of 16 INDEPENDENT MMAs (distinct acc) so
            // no back-to-back RAW on any accumulator.
            #pragma unroll
            for (int jg = 0; jg < 2; ++jg) {
                uint32_t bh[4][4], bl[4][4];
                #pragma unroll
                for (int j = 0; j < 4; ++j) {
                    const int jj = jg * 4 + j;
                    uint32_t bAddr = bBase +
                        (uint32_t)(((wcol + (2 * jj + bNtOff) * 8 + lsub) * TS + k0 + bColOff) * 2);
                    ldsm_x4(bh[j], bAddr);
                    ldsm_x4(bl[j], bAddr + BTB);
                }
                // pass 1: hh  (Ah x Bh)
                #pragma unroll
                for (int j = 0; j < 4; ++j)
                    #pragma unroll
                    for (int u = 0; u < 2; ++u) {
                        const int nt = (jg * 4 + j) * 2 + u;
                        #pragma unroll
                        for (int mr = 0; mr < MR; ++mr)
                            mma_fp16(acc[mr][nt], ah[mr], bh[j][2 * u], bh[j][2 * u + 1]);
                    }
                // pass 2: lh  (Al x Bh)
                #pragma unroll
                for (int j = 0; j < 4; ++j)
                    #pragma unroll
                    for (int u = 0; u < 2; ++u) {
                        const int nt = (jg * 4 + j) * 2 + u;
                        #pragma unroll
                        for (int mr = 0; mr < MR; ++mr)
                            mma_fp16(acc[mr][nt], al[mr], bh[j][2 * u], bh[j][2 * u + 1]);
                    }
                // pass 3: hl  (Ah x Bl)
                #pragma unroll
                for (int j = 0; j < 4; ++j)
                    #pragma unroll
                    for (int u = 0; u < 2; ++u) {
                        const int nt = (jg * 4 + j) * 2 + u;
                        #pragma unroll
                        for (int mr = 0; mr < MR; ++mr)
                            mma_fp16(acc[mr][nt], ah[mr], bl[j][2 * u], bl[j][2 * u + 1]);
                    }
            }
        }
        __syncthreads();   // all warps done with this buffer before refill
    }

    // ============ routing directly on register accumulators ============
    // acc[mr][nt][0,1] -> row (wrow+mr*16+g),   cols wcol+nt*8+2q+{0,1}
    // acc[mr][nt][2,3] -> row (wrow+mr*16+g+8), same cols
    if (tid < M) logits[tid] = 0.0f;

    for (int it = 0; it < 3; ++it) {
        // ---- probs = softmax(logits) ----
        if (it == 0) {
            if (tid < M) probs[tid] = 1.0f / (float)M;
        } else {
            float lv = (tid < M) ? logits[tid] : -3.402823466e38f;
            float mx = blockMax(lv, red);
            float ev = (tid < M) ? expf(lv - mx) : 0.0f;
            float Z = blockSum(ev, red);
            if (tid < M) probs[tid] = ev / Z;
        }
        __syncthreads();

        // ---- s[d] = sum_b probs[b] * P[b][d] from registers ----
        {
            float pr[MR][2];
            #pragma unroll
            for (int mr = 0; mr < MR; ++mr) {
                pr[mr][0] = probs[wrow + mr * 16 + g];
                pr[mr][1] = probs[wrow + mr * 16 + g + 8];
            }
            #pragma unroll
            for (int nt = 0; nt < 16; ++nt) {
                float c0 = 0.0f, c1 = 0.0f;
                #pragma unroll
                for (int mr = 0; mr < MR; ++mr) {
                    c0 = fmaf(pr[mr][0], acc[mr][nt][0], fmaf(pr[mr][1], acc[mr][nt][2], c0));
                    c1 = fmaf(pr[mr][0], acc[mr][nt][1], fmaf(pr[mr][1], acc[mr][nt][3], c1));
                }
                // reduce over the 8 g-lanes (stride-4 butterfly)
                #pragma unroll
                for (int o = 4; o <= 16; o <<= 1) {
                    c0 += __shfl_xor_sync(0xffffffffu, c0, o);
                    c1 += __shfl_xor_sync(0xffffffffu, c1, o);
                }
                if (g == 0) {
                    part[rg * 256 + wcol + nt * 8 + 2 * q]     = c0;
                    part[rg * 256 + wcol + nt * 8 + 2 * q + 1] = c1;
                }
            }
        }
        __syncthreads();

        // ---- squash ----
        float sd = 0.0f;
        if (tid < 256)
            sd = part[tid] + part[256 + tid] + part[512 + tid] + part[768 + tid];
        float sq = blockSum(sd * sd, red);
        float scale = sq / ((1.0f + sq) * sqrtf(sq));
        if (tid < 256) vout[tid] = sd * scale;
        __syncthreads();

        if (it < 2) {
            // ---- logits[b] += sum_d P[b][d] * v[d] from registers ----
            float rowp[MR][2];
            #pragma unroll
            for (int mr = 0; mr < MR; ++mr) { rowp[mr][0] = 0.0f; rowp[mr][1] = 0.0f; }
            #pragma unroll
            for (int nt = 0; nt < 16; ++nt) {
                float v0 = vout[wcol + nt * 8 + 2 * q];
                float v1 = vout[wcol + nt * 8 + 2 * q + 1];
                #pragma unroll
                for (int mr = 0; mr < MR; ++mr) {
                    rowp[mr][0] = fmaf(acc[mr][nt][0], v0, fmaf(acc[mr][nt][1], v1, rowp[mr][0]));
                    rowp[mr][1] = fmaf(acc[mr][nt][2], v0, fmaf(acc[mr][nt][3], v1, rowp[mr][1]));
                }
            }
            // reduce over the 4 q-lanes
            #pragma unroll
            for (int mr = 0; mr < MR; ++mr) {
                #pragma unroll
                for (int o = 1; o <= 2; o <<= 1) {
                    rowp[mr][0] += __shfl_xor_sync(0xffffffffu, rowp[mr][0], o);
                    rowp[mr][1] += __shfl_xor_sync(0xffffffffu, rowp[mr][1], o);
                }
            }
            __syncthreads();   // part free
            if (q == 0) {
                #pragma unroll
                for (int mr = 0; mr < MR; ++mr) {
                    part[cg * M + wrow + mr * 16 + g]     = rowp[mr][0];
                    part[cg * M + wrow + mr * 16 + g + 8] = rowp[mr][1];
                }
            }
            __syncthreads();
            if (tid < M)
                logits[tid] += part[tid] + part[M + tid];
            __syncthreads();
        } else {
            if (tid < 256) {
                float v = vout[tid];
                size_t o = (size_t)blockIdx.x * outXStride + (size_t)blockIdx.y * outYStride + tid;
                if (F32OUT) {
                    OutF[o] = v;
                } else {
                    __half h, l;
                    split2(v, h, l);
                    OutH[o] = h; OutL[o] = l;
                }
            }
        }
    }
}

static size_t stage_smem(int M) {
    size_t buf = 2ull * M * 40 * 2 + 2ull * 256 * 40 * 2;   // one pipeline buffer
    size_t scr = (1024 + 256 + 2 * (size_t)M + 64) * 4;
    return 2 * buf + scr;
}

extern "C" void kernel_launch(void* const* d_in, const int* in_sizes, int n_in,
                              void* d_out, int out_size) {
    (void)in_sizes; (void)n_in; (void)out_size;
    const float* x  = (const float*)d_in[0];   // [64,128,256]
    const float* w1 = (const float*)d_in[1];   // [64,256,256]
    const float* w2 = (const float*)d_in[2];   // [32,256,256]
    float* out = (float*)d_out;                // [32,64,256]

    void* p;
    cudaGetSymbolAddress(&p, g_xh);  __half* xh  = (__half*)p;
    cudaGetSymbolAddress(&p, g_xl);  __half* xl  = (__half*)p;
    cudaGetSymbolAddress(&p, g_w1h); __half* w1h = (__half*)p;
    cudaGetSymbolAddress(&p, g_w1l); __half* w1l = (__half*)p;
    cudaGetSymbolAddress(&p, g_w2h); __half* w2h = (__half*)p;
    cudaGetSymbolAddress(&p, g_w2l); __half* w2l = (__half*)p;
    cudaGetSymbolAddress(&p, g_o1h); __half* o1h = (__half*)p;
    cudaGetSymbolAddress(&p, g_o1l); __half* o1l = (__half*)p;

    // pre-pass: fp16 hi/lo splits (+ W transposed to [n][k])
    split_x_kernel<<<8192, 256>>>(x, xh, xl, 64 * 128 * 256);
    trans_split_w<<<dim3(8, 8, 64), 256>>>(w1, w1h, w1l);
    trans_split_w<<<dim3(8, 8, 32), 256>>>(w2, w2h, w2l);

    const size_t sm1 = stage_smem(128);   // ~129 KB
    const size_t sm2 = stage_smem(64);    // ~109 KB
    cudaFuncSetAttribute((const void*)caps_mma_route<128, false, 1>,
                         cudaFuncAttributeMaxDynamicSharedMemorySize, (int)sm1);
    cudaFuncSetAttribute((const void*)caps_mma_route<64, true, 2>,
                         cudaFuncAttributeMaxDynamicSharedMemorySize, (int)sm2);

    // Stage 1: (a=64, h=64) -> out1 fp16 h/l [a][h][256]
    caps_mma_route<128, false, 1><<<dim3(64, 64), 256, sm1>>>(
        xh, xl, w1h, w1l, nullptr, o1h, o1l, /*x=a*/ 64 * 256, /*y=h*/ 256);

    // Stage 2: (a=64, c=32) -> out fp32 [c][a][256]; 2 CTAs/SM
    caps_mma_route<64, true, 2><<<dim3(64, 32), 256, sm2>>>(
        o1h, o1l, w2h, w2l, out, nullptr, nullptr, /*x=a*/ 256, /*y=c*/ 64 * 256);
}

// round 15
// speedup vs baseline: 3.2272x; 1.0416x over previous
#include <cuda_runtime.h>
#include <cuda_fp16.h>
#include <math.h>
#include <stdint.h>

// ---------------- device globals (no allocations allowed) ----------------
// 2-level fp16 splits: v = vh + vl (each level fp16)
__device__ __half g_xh[64 * 128 * 256], g_xl[64 * 128 * 256];     // X split    [a][b][d]
__device__ __half g_w1h[64 * 256 * 256], g_w1l[64 * 256 * 256];   // W1^T split [h][n][k]
__device__ __half g_w2h[32 * 256 * 256], g_w2l[32 * 256 * 256];   // W2^T split [c][n][k]
__device__ __half g_o1h[64 * 64 * 256], g_o1l[64 * 64 * 256];     // out1 split [a][h][d]

// ---------------- fp16 HMMA via mma.sync (sm_80+ baseline PTX) ----------------
__device__ __forceinline__ void mma_fp16(float* c, const uint32_t* a, uint32_t b0, uint32_t b1) {
    asm volatile(
        "mma.sync.aligned.m16n8k16.row.col.f32.f16.f16.f32 "
        "{%0,%1,%2,%3}, {%4,%5,%6,%7}, {%8,%9}, {%0,%1,%2,%3};"
        : "+f"(c[0]), "+f"(c[1]), "+f"(c[2]), "+f"(c[3])
        : "r"(a[0]), "r"(a[1]), "r"(a[2]), "r"(a[3]), "r"(b0), "r"(b1));
}

// ---------------- ldmatrix x4 (sm_75+ baseline PTX) ----------------
__device__ __forceinline__ void ldsm_x4(uint32_t* r, uint32_t addr) {
    asm volatile("ldmatrix.sync.aligned.m8n8.x4.shared.b16 {%0,%1,%2,%3}, [%4];"
                 : "=r"(r[0]), "=r"(r[1]), "=r"(r[2]), "=r"(r[3]) : "r"(addr));
}

// ---------------- cp.async helpers (sm_80+ baseline PTX) ----------------
__device__ __forceinline__ void cp16(uint32_t smem_dst, const void* gsrc) {
    asm volatile("cp.async.cg.shared.global [%0], [%1], 16;" :: "r"(smem_dst), "l"(gsrc));
}
__device__ __forceinline__ void cp_commit() {
    asm volatile("cp.async.commit_group;");
}
template<int N>
__device__ __forceinline__ void cp_wait() {
    asm volatile("cp.async.wait_group %0;" :: "n"(N));
}
__device__ __forceinline__ uint32_t smem_u32(const void* p) {
    uint32_t a;
    asm("{ .reg .u64 t; cvta.to.shared.u64 t, %1; cvt.u32.u64 %0, t; }" : "=r"(a) : "l"(p));
    return a;
}

// ---------------- block reductions over 256 threads (8 warps) ----------------
__device__ __forceinline__ float warpSum(float v) {
    #pragma unroll
    for (int o = 16; o; o >>= 1) v += __shfl_down_sync(0xffffffffu, v, o);
    return v;
}
__device__ __forceinline__ float warpMax(float v) {
    #pragma unroll
    for (int o = 16; o; o >>= 1) v = fmaxf(v, __shfl_down_sync(0xffffffffu, v, o));
    return v;
}
__device__ __forceinline__ float blockSum(float v, float* red) {
    v = warpSum(v);
    __syncthreads();
    if ((threadIdx.x & 31) == 0) red[threadIdx.x >> 5] = v;
    __syncthreads();
    if (threadIdx.x < 32) {
        float x = (threadIdx.x < 8) ? red[threadIdx.x] : 0.0f;
        x = warpSum(x);
        if (threadIdx.x == 0) red[32] = x;
    }
    __syncthreads();
    return red[32];
}
__device__ __forceinline__ float blockMax(float v, float* red) {
    v = warpMax(v);
    __syncthreads();
    if ((threadIdx.x & 31) == 0) red[threadIdx.x >> 5] = v;
    __syncthreads();
    if (threadIdx.x < 32) {
        float x = (threadIdx.x < 8) ? red[threadIdx.x] : -3.402823466e38f;
        x = warpMax(x);
        if (threadIdx.x == 0) red[32] = x;
    }
    __syncthreads();
    return red[32];
}

// 2-level fp16 split of a float
__device__ __forceinline__ void split2(float v, __half& h, __half& l) {
    h = __float2half_rn(v);
    l = __float2half_rn(v - __half2float(h));
}

// ---------------- pre-pass: split X into fp16 h/l ----------------
__global__ void split_x_kernel(const float* __restrict__ x,
                               __half* __restrict__ xh, __half* __restrict__ xl, int n) {
    int i = blockIdx.x * blockDim.x + threadIdx.x;
    if (i >= n) return;
    __half h, l;
    split2(x[i], h, l);
    xh[i] = h; xl[i] = l;
}

// ---------------- pre-pass: transpose + split W[k][n] -> Wt[n][k] fp16 h/l ----------------
__global__ void trans_split_w(const float* __restrict__ W,
                              __half* __restrict__ Wth, __half* __restrict__ Wtl) {
    __shared__ float st[32][33];
    int mb = blockIdx.z, k0 = blockIdx.x * 32, n0 = blockIdx.y * 32;
    const float* Wm = W + (size_t)mb * 65536;
    int tid = threadIdx.x;
    #pragma unroll
    for (int i = 0; i < 4; ++i) {
        int e = tid + i * 256, k = e >> 5, n = e & 31;
        st[k][n] = Wm[(k0 + k) * 256 + n0 + n];
    }
    __syncthreads();
    #pragma unroll
    for (int i = 0; i < 4; ++i) {
        int e = tid + i * 256, n = e >> 5, k = e & 31;
        float f = st[k][n];
        __half h, l;
        split2(f, h, l);
        size_t o = (size_t)mb * 65536 + (size_t)(n0 + n) * 256 + k0 + k;
        Wth[o] = h; Wtl[o] = l;
    }
}

// ---------------- fused HMMA-GEMM + register-resident routing ----------------
// One CTA = one (weight, batch) pair. 256 threads, 8 warps arranged
//   2 row-groups x 4 col-groups; warp tile (M/2) x 64 — SQUARE-ish tile
//   minimizes ldmatrix wavefront traffic (crossbar is the binding pipe).
//   3-term 2-level fp16 split (hh + lh + hl), cp.async double-buffered,
//   register-resident routing.
template<int M, bool F32OUT, int MINCTA>
__global__ void __launch_bounds__(256, MINCTA)
caps_mma_route(const __half* __restrict__ AhG, const __half* __restrict__ AlG,
               const __half* __restrict__ BhG, const __half* __restrict__ BlG,
               float* __restrict__ OutF,
               __half* __restrict__ OutH, __half* __restrict__ OutL,
               int outXStride, int outYStride)
{
    constexpr int KC = 32;               // k-chunk
    constexpr int NT = 256 / KC;         // 8 chunks
    constexpr int TS = KC + 8;           // 40 fp16 row stride (80B, 16B-aligned)
    constexpr int MR = M / 32;           // mma row-tiles per warp (4 for M=128, 2 for M=64)
    constexpr uint32_t ATB = (uint32_t)M * TS * 2;    // one A level tile bytes
    constexpr uint32_t BTB = 256u * TS * 2;           // one B level tile bytes
    constexpr uint32_t BUF = 2 * ATB + 2 * BTB;       // one pipeline buffer
    constexpr uint32_t SCR = 2 * BUF;

    extern __shared__ char smc[];
    const uint32_t smb = smem_u32(smc);
    float* part   = (float*)(smc + SCR);   // 1024 floats (combine buffer)
    float* vout   = part + 1024;           // 256
    float* probs  = vout + 256;            // M
    float* logits = probs + M;             // M
    float* red    = logits + M;            // 64

    const int tid = threadIdx.x;
    const int wid = tid >> 5, lane = tid & 31;
    const int g = lane >> 2, q = lane & 3;           // mma fragment coords
    const int rg = wid >> 2, cg = wid & 3;           // row-group (2) / col-group (4)
    const int wrow = rg * (M / 2);                   // warp row base
    const int wcol = cg * 64;                        // warp col base

    // ldmatrix lane-address components
    const int lsub = lane & 7;                       // row within 8x8 matrix
    const int lmi  = lane >> 3;                      // matrix index 0..3
    const int aRowOff = lsub + (lmi & 1) * 8;        // A: m0/m2 rows 0-7, m1/m3 rows 8-15
    const int aColOff = (lmi >> 1) * 8;              // A: m0/m1 cols k0, m2/m3 cols k0+8
    const int bColOff = (lmi & 1) * 8;               // B: m0/m2 col k0, m1/m3 col k0+8
    const int bNtOff  = (lmi >> 1);                  // B: m0/m1 -> nt, m2/m3 -> nt+1

    const size_t aOff = (size_t)blockIdx.x * (M * 256);
    const size_t bOff = (size_t)blockIdx.y * 65536u;
    const __half* Asrc[2] = { AhG + aOff, AlG + aOff };
    const __half* Bsrc[2] = { BhG + bOff, BlG + bOff };

    // -------- async tile loader: chunk t -> buffer at byte offset bb --------
    auto load_chunk = [&](uint32_t bb, int t) {
        const int k0g = t * KC;
        #pragma unroll
        for (int lv = 0; lv < 2; ++lv) {
            const __half* src = Asrc[lv] + k0g;
            uint32_t dstb = smb + bb + lv * ATB;
            #pragma unroll
            for (int e = tid; e < M * 4; e += 256) {
                int r = e >> 2, seg = e & 3;
                cp16(dstb + (uint32_t)(r * TS + seg * 8) * 2, src + r * 256 + seg * 8);
            }
        }
        #pragma unroll
        for (int lv = 0; lv < 2; ++lv) {
            const __half* src = Bsrc[lv] + k0g;
            uint32_t dstb = smb + bb + 2 * ATB + lv * BTB;
            #pragma unroll
            for (int e = tid; e < 1024; e += 256) {
                int r = e >> 2, seg = e & 3;
                cp16(dstb + (uint32_t)(r * TS + seg * 8) * 2, src + r * 256 + seg * 8);
            }
        }
        cp_commit();
    };

    // ============ GEMM: 8 K-chunks of 32, 3-term 2-level fp16 split ============
    float acc[MR][8][4];
    #pragma unroll
    for (int mr = 0; mr < MR; ++mr)
        #pragma unroll
        for (int nt = 0; nt < 8; ++nt)
            #pragma unroll
            for (int j = 0; j < 4; ++j) acc[mr][nt][j] = 0.0f;

    load_chunk(0, 0);

    for (int t = 0; t < NT; ++t) {
        const uint32_t bb = (t & 1) ? BUF : 0;
        if (t + 1 < NT) {
            load_chunk((t & 1) ? 0 : BUF, t + 1);
            cp_wait<1>();
        } else {
            cp_wait<0>();
        }
        __syncthreads();

        const uint32_t aBase = smb + bb;
        const uint32_t bBase = smb + bb + 2 * ATB;

        #pragma unroll
        for (int ks = 0; ks < KC / 16; ++ks) {
            const int k0 = ks * 16;
            // A fragments via ldmatrix.x4 (both levels)
            uint32_t ah[MR][4], al[MR][4];
            #pragma unroll
            for (int mr = 0; mr < MR; ++mr) {
                uint32_t aAddr = aBase +
                    (uint32_t)(((wrow + mr * 16 + aRowOff) * TS + k0 + aColOff) * 2);
                ldsm_x4(ah[mr], aAddr);
                ldsm_x4(al[mr], aAddr + ATB);
            }
            // B fragments: 4 pairs covering the warp's 8 n-tiles, both levels
            uint32_t bh[4][4], bl[4][4];
            #pragma unroll
            for (int j = 0; j < 4; ++j) {
                uint32_t bAddr = bBase +
                    (uint32_t)(((wcol + (2 * j + bNtOff) * 8 + lsub) * TS + k0 + bColOff) * 2);
                ldsm_x4(bh[j], bAddr);
                ldsm_x4(bl[j], bAddr + BTB);
            }
            // pass 1: hh  (Ah x Bh)
            #pragma unroll
            for (int j = 0; j < 4; ++j)
                #pragma unroll
                for (int u = 0; u < 2; ++u) {
                    const int nt = j * 2 + u;
                    #pragma unroll
                    for (int mr = 0; mr < MR; ++mr)
                        mma_fp16(acc[mr][nt], ah[mr], bh[j][2 * u], bh[j][2 * u + 1]);
                }
            // pass 2: lh  (Al x Bh)
            #pragma unroll
            for (int j = 0; j < 4; ++j)
                #pragma unroll
                for (int u = 0; u < 2; ++u) {
                    const int nt = j * 2 + u;
                    #pragma unroll
                    for (int mr = 0; mr < MR; ++mr)
                        mma_fp16(acc[mr][nt], al[mr], bh[j][2 * u], bh[j][2 * u + 1]);
                }
            // pass 3: hl  (Ah x Bl)
            #pragma unroll
            for (int j = 0; j < 4; ++j)
                #pragma unroll
                for (int u = 0; u < 2; ++u) {
                    const int nt = j * 2 + u;
                    #pragma unroll
                    for (int mr = 0; mr < MR; ++mr)
                        mma_fp16(acc[mr][nt], ah[mr], bl[j][2 * u], bl[j][2 * u + 1]);
                }
        }
        __syncthreads();   // all warps done with this buffer before refill
    }

    // ============ routing directly on register accumulators ============
    // acc[mr][nt][0,1] -> row (wrow+mr*16+g),   cols wcol+nt*8+2q+{0,1}
    // acc[mr][nt][2,3] -> row (wrow+mr*16+g+8), same cols
    if (tid < M) logits[tid] = 0.0f;

    for (int it = 0; it < 3; ++it) {
        // ---- probs = softmax(logits) ----
        if (it == 0) {
            if (tid < M) probs[tid] = 1.0f / (float)M;
        } else {
            float lv = (tid < M) ? logits[tid] : -3.402823466e38f;
            float mx = blockMax(lv, red);
            float ev = (tid < M) ? expf(lv - mx) : 0.0f;
            float Z = blockSum(ev, red);
            if (tid < M) probs[tid] = ev / Z;
        }
        __syncthreads();

        // ---- s[d] = sum_b probs[b] * P[b][d] from registers ----
        {
            float pr[MR][2];
            #pragma unroll
            for (int mr = 0; mr < MR; ++mr) {
                pr[mr][0] = probs[wrow + mr * 16 + g];
                pr[mr][1] = probs[wrow + mr * 16 + g + 8];
            }
            #pragma unroll
            for (int nt = 0; nt < 8; ++nt) {
                float c0 = 0.0f, c1 = 0.0f;
                #pragma unroll
                for (int mr = 0; mr < MR; ++mr) {
                    c0 = fmaf(pr[mr][0], acc[mr][nt][0], fmaf(pr[mr][1], acc[mr][nt][2], c0));
                    c1 = fmaf(pr[mr][0], acc[mr][nt][1], fmaf(pr[mr][1], acc[mr][nt][3], c1));
                }
                // reduce over the 8 g-lanes (stride-4 butterfly)
                #pragma unroll
                for (int o = 4; o <= 16; o <<= 1) {
                    c0 += __shfl_xor_sync(0xffffffffu, c0, o);
                    c1 += __shfl_xor_sync(0xffffffffu, c1, o);
                }
                if (g == 0) {
                    part[rg * 256 + wcol + nt * 8 + 2 * q]     = c0;
                    part[rg * 256 + wcol + nt * 8 + 2 * q + 1] = c1;
                }
            }
        }
        __syncthreads();

        // ---- squash (2 row-groups to combine) ----
        float sd = 0.0f;
        if (tid < 256)
            sd = part[tid] + part[256 + tid];
        float sq = blockSum(sd * sd, red);
        float scale = sq / ((1.0f + sq) * sqrtf(sq));
        if (tid < 256) vout[tid] = sd * scale;
        __syncthreads();

        if (it < 2) {
            // ---- logits[b] += sum_d P[b][d] * v[d] from registers ----
            float rowp[MR][2];
            #pragma unroll
            for (int mr = 0; mr < MR; ++mr) { rowp[mr][0] = 0.0f; rowp[mr][1] = 0.0f; }
            #pragma unroll
            for (int nt = 0; nt < 8; ++nt) {
                float v0 = vout[wcol + nt * 8 + 2 * q];
                float v1 = vout[wcol + nt * 8 + 2 * q + 1];
                #pragma unroll
                for (int mr = 0; mr < MR; ++mr) {
                    rowp[mr][0] = fmaf(acc[mr][nt][0], v0, fmaf(acc[mr][nt][1], v1, rowp[mr][0]));
                    rowp[mr][1] = fmaf(acc[mr][nt][2], v0, fmaf(acc[mr][nt][3], v1, rowp[mr][1]));
                }
            }
            // reduce over the 4 q-lanes
            #pragma unroll
            for (int mr = 0; mr < MR; ++mr) {
                #pragma unroll
                for (int o = 1; o <= 2; o <<= 1) {
                    rowp[mr][0] += __shfl_xor_sync(0xffffffffu, rowp[mr][0], o);
                    rowp[mr][1] += __shfl_xor_sync(0xffffffffu, rowp[mr][1], o);
                }
            }
            __syncthreads();   // part free
            if (q == 0) {
                #pragma unroll
                for (int mr = 0; mr < MR; ++mr) {
                    part[cg * M + wrow + mr * 16 + g]     = rowp[mr][0];
                    part[cg * M + wrow + mr * 16 + g + 8] = rowp[mr][1];
                }
            }
            __syncthreads();
            if (tid < M)
                logits[tid] += part[tid] + part[M + tid] + part[2 * M + tid] + part[3 * M + tid];
            __syncthreads();
        } else {
            if (tid < 256) {
                float v = vout[tid];
                size_t o = (size_t)blockIdx.x * outXStride + (size_t)blockIdx.y * outYStride + tid;
                if (F32OUT) {
                    OutF[o] = v;
                } else {
                    __half h, l;
                    split2(v, h, l);
                    OutH[o] = h; OutL[o] = l;
                }
            }
        }
    }
}

static size_t stage_smem(int M) {
    size_t buf = 2ull * M * 40 * 2 + 2ull * 256 * 40 * 2;   // one pipeline buffer
    size_t scr = (1024 + 256 + 2 * (size_t)M + 64) * 4;
    return 2 * buf + scr;
}

extern "C" void kernel_launch(void* const* d_in, const int* in_sizes, int n_in,
                              void* d_out, int out_size) {
    (void)in_sizes; (void)n_in; (void)out_size;
    const float* x  = (const float*)d_in[0];   // [64,128,256]
    const float* w1 = (const float*)d_in[1];   // [64,256,256]
    const float* w2 = (const float*)d_in[2];   // [32,256,256]
    float* out = (float*)d_out;                // [32,64,256]

    void* p;
    cudaGetSymbolAddress(&p, g_xh);  __half* xh  = (__half*)p;
    cudaGetSymbolAddress(&p, g_xl);  __half* xl  = (__half*)p;
    cudaGetSymbolAddress(&p, g_w1h); __half* w1h = (__half*)p;
    cudaGetSymbolAddress(&p, g_w1l); __half* w1l = (__half*)p;
    cudaGetSymbolAddress(&p, g_w2h); __half* w2h = (__half*)p;
    cudaGetSymbolAddress(&p, g_w2l); __half* w2l = (__half*)p;
    cudaGetSymbolAddress(&p, g_o1h); __half* o1h = (__half*)p;
    cudaGetSymbolAddress(&p, g_o1l); __half* o1l = (__half*)p;

    // pre-pass: fp16 hi/lo splits (+ W transposed to [n][k])
    split_x_kernel<<<8192, 256>>>(x, xh, xl, 64 * 128 * 256);
    trans_split_w<<<dim3(8, 8, 64), 256>>>(w1, w1h, w1l);
    trans_split_w<<<dim3(8, 8, 32), 256>>>(w2, w2h, w2l);

    const size_t sm1 = stage_smem(128);   // ~129 KB
    const size_t sm2 = stage_smem(64);    // ~109 KB
    cudaFuncSetAttribute((const void*)caps_mma_route<128, false, 1>,
                         cudaFuncAttributeMaxDynamicSharedMemorySize, (int)sm1);
    cudaFuncSetAttribute((const void*)caps_mma_route<64, true, 2>,
                         cudaFuncAttributeMaxDynamicSharedMemorySize, (int)sm2);

    // Stage 1: (a=64, h=64) -> out1 fp16 h/l [a][h][256]
    caps_mma_route<128, false, 1><<<dim3(64, 64), 256, sm1>>>(
        xh, xl, w1h, w1l, nullptr, o1h, o1l, /*x=a*/ 64 * 256, /*y=h*/ 256);

    // Stage 2: (a=64, c=32) -> out fp32 [c][a][256]; 2 CTAs/SM
    caps_mma_route<64, true, 2><<<dim3(64, 32), 256, sm2>>>(
        o1h, o1l, w2h, w2l, out, nullptr, nullptr, /*x=a*/ 256, /*y=c*/ 64 * 256);
}

// round 16
// speedup vs baseline: 3.2451x; 1.0055x over previous
#include <cuda_runtime.h>
#include <cuda_fp16.h>
#include <math.h>
#include <stdint.h>

// ---------------- device globals (no allocations allowed) ----------------
// 2-level fp16 splits: v = vh + vl (each level fp16)
__device__ __half g_xh[64 * 128 * 256], g_xl[64 * 128 * 256];     // X split    [a][b][d]
__device__ __half g_w1h[64 * 256 * 256], g_w1l[64 * 256 * 256];   // W1^T split [h][n][k]
__device__ __half g_w2h[32 * 256 * 256], g_w2l[32 * 256 * 256];   // W2^T split [c][n][k]
__device__ __half g_o1h[64 * 64 * 256], g_o1l[64 * 64 * 256];     // out1 split [a][h][d]

// ---------------- fp16 HMMA via mma.sync (sm_80+ baseline PTX) ----------------
__device__ __forceinline__ void mma_fp16(float* c, const uint32_t* a, uint32_t b0, uint32_t b1) {
    asm volatile(
        "mma.sync.aligned.m16n8k16.row.col.f32.f16.f16.f32 "
        "{%0,%1,%2,%3}, {%4,%5,%6,%7}, {%8,%9}, {%0,%1,%2,%3};"
        : "+f"(c[0]), "+f"(c[1]), "+f"(c[2]), "+f"(c[3])
        : "r"(a[0]), "r"(a[1]), "r"(a[2]), "r"(a[3]), "r"(b0), "r"(b1));
}

// ---------------- ldmatrix x4 (sm_75+ baseline PTX) ----------------
__device__ __forceinline__ void ldsm_x4(uint32_t* r, uint32_t addr) {
    asm volatile("ldmatrix.sync.aligned.m8n8.x4.shared.b16 {%0,%1,%2,%3}, [%4];"
                 : "=r"(r[0]), "=r"(r[1]), "=r"(r[2]), "=r"(r[3]) : "r"(addr));
}

// ---------------- cp.async helpers (sm_80+ baseline PTX) ----------------
__device__ __forceinline__ void cp16(uint32_t smem_dst, const void* gsrc) {
    asm volatile("cp.async.cg.shared.global [%0], [%1], 16;" :: "r"(smem_dst), "l"(gsrc));
}
__device__ __forceinline__ void cp_commit() {
    asm volatile("cp.async.commit_group;");
}
template<int N>
__device__ __forceinline__ void cp_wait() {
    asm volatile("cp.async.wait_group %0;" :: "n"(N));
}
__device__ __forceinline__ uint32_t smem_u32(const void* p) {
    uint32_t a;
    asm("{ .reg .u64 t; cvta.to.shared.u64 t, %1; cvt.u32.u64 %0, t; }" : "=r"(a) : "l"(p));
    return a;
}

// ---------------- block reductions over 256 threads (8 warps) ----------------
__device__ __forceinline__ float warpSum(float v) {
    #pragma unroll
    for (int o = 16; o; o >>= 1) v += __shfl_down_sync(0xffffffffu, v, o);
    return v;
}
__device__ __forceinline__ float warpMax(float v) {
    #pragma unroll
    for (int o = 16; o; o >>= 1) v = fmaxf(v, __shfl_down_sync(0xffffffffu, v, o));
    return v;
}
__device__ __forceinline__ float blockSum(float v, float* red) {
    v = warpSum(v);
    __syncthreads();
    if ((threadIdx.x & 31) == 0) red[threadIdx.x >> 5] = v;
    __syncthreads();
    if (threadIdx.x < 32) {
        float x = (threadIdx.x < 8) ? red[threadIdx.x] : 0.0f;
        x = warpSum(x);
        if (threadIdx.x == 0) red[32] = x;
    }
    __syncthreads();
    return red[32];
}
__device__ __forceinline__ float blockMax(float v, float* red) {
    v = warpMax(v);
    __syncthreads();
    if ((threadIdx.x & 31) == 0) red[threadIdx.x >> 5] = v;
    __syncthreads();
    if (threadIdx.x < 32) {
        float x = (threadIdx.x < 8) ? red[threadIdx.x] : -3.402823466e38f;
        x = warpMax(x);
        if (threadIdx.x == 0) red[32] = x;
    }
    __syncthreads();
    return red[32];
}

// 2-level fp16 split of a float
__device__ __forceinline__ void split2(float v, __half& h, __half& l) {
    h = __float2half_rn(v);
    l = __float2half_rn(v - __half2float(h));
}

// ---------------- pre-pass: split X into fp16 h/l ----------------
__global__ void split_x_kernel(const float* __restrict__ x,
                               __half* __restrict__ xh, __half* __restrict__ xl, int n) {
    int i = blockIdx.x * blockDim.x + threadIdx.x;
    if (i >= n) return;
    __half h, l;
    split2(x[i], h, l);
    xh[i] = h; xl[i] = l;
}

// ---------------- pre-pass: transpose + split W[k][n] -> Wt[n][k] fp16 h/l ----------------
__global__ void trans_split_w(const float* __restrict__ W,
                              __half* __restrict__ Wth, __half* __restrict__ Wtl) {
    __shared__ float st[32][33];
    int mb = blockIdx.z, k0 = blockIdx.x * 32, n0 = blockIdx.y * 32;
    const float* Wm = W + (size_t)mb * 65536;
    int tid = threadIdx.x;
    #pragma unroll
    for (int i = 0; i < 4; ++i) {
        int e = tid + i * 256, k = e >> 5, n = e & 31;
        st[k][n] = Wm[(k0 + k) * 256 + n0 + n];
    }
    __syncthreads();
    #pragma unroll
    for (int i = 0; i < 4; ++i) {
        int e = tid + i * 256, n = e >> 5, k = e & 31;
        float f = st[k][n];
        __half h, l;
        split2(f, h, l);
        size_t o = (size_t)mb * 65536 + (size_t)(n0 + n) * 256 + k0 + k;
        Wth[o] = h; Wtl[o] = l;
    }
}

// ---------------- fused HMMA-GEMM + register-resident routing ----------------
// One CTA = one (weight, batch) pair. 256 threads, 8 warps arranged
//   2 row-groups x 4 col-groups; warp tile (M/2) x 64.
//   Anti-phased k-steps (odd warps reverse order) + B-fragment prefetch
//   interleave keep the tensor pipe fed through fragment-load windows.
template<int M, bool F32OUT, int MINCTA>
__global__ void __launch_bounds__(256, MINCTA)
caps_mma_route(const __half* __restrict__ AhG, const __half* __restrict__ AlG,
               const __half* __restrict__ BhG, const __half* __restrict__ BlG,
               float* __restrict__ OutF,
               __half* __restrict__ OutH, __half* __restrict__ OutL,
               int outXStride, int outYStride)
{
    constexpr int KC = 32;               // k-chunk
    constexpr int NT = 256 / KC;         // 8 chunks
    constexpr int TS = KC + 8;           // 40 fp16 row stride (80B, 16B-aligned)
    constexpr int MR = M / 32;           // mma row-tiles per warp (4 for M=128, 2 for M=64)
    constexpr uint32_t ATB = (uint32_t)M * TS * 2;    // one A level tile bytes
    constexpr uint32_t BTB = 256u * TS * 2;           // one B level tile bytes
    constexpr uint32_t BUF = 2 * ATB + 2 * BTB;       // one pipeline buffer
    constexpr uint32_t SCR = 2 * BUF;

    extern __shared__ char smc[];
    const uint32_t smb = smem_u32(smc);
    float* part   = (float*)(smc + SCR);   // 1024 floats (combine buffer)
    float* vout   = part + 1024;           // 256
    float* probs  = vout + 256;            // M
    float* logits = probs + M;             // M
    float* red    = logits + M;            // 64

    const int tid = threadIdx.x;
    const int wid = tid >> 5, lane = tid & 31;
    const int g = lane >> 2, q = lane & 3;           // mma fragment coords
    const int rg = wid >> 2, cg = wid & 3;           // row-group (2) / col-group (4)
    const int wrow = rg * (M / 2);                   // warp row base
    const int wcol = cg * 64;                        // warp col base

    // ldmatrix lane-address components
    const int lsub = lane & 7;                       // row within 8x8 matrix
    const int lmi  = lane >> 3;                      // matrix index 0..3
    const int aRowOff = lsub + (lmi & 1) * 8;        // A: m0/m2 rows 0-7, m1/m3 rows 8-15
    const int aColOff = (lmi >> 1) * 8;              // A: m0/m1 cols k0, m2/m3 cols k0+8
    const int bColOff = (lmi & 1) * 8;               // B: m0/m2 col k0, m1/m3 col k0+8
    const int bNtOff  = (lmi >> 1);                  // B: m0/m1 -> nt, m2/m3 -> nt+1

    const size_t aOff = (size_t)blockIdx.x * (M * 256);
    const size_t bOff = (size_t)blockIdx.y * 65536u;
    const __half* Asrc[2] = { AhG + aOff, AlG + aOff };
    const __half* Bsrc[2] = { BhG + bOff, BlG + bOff };

    // -------- async tile loader: chunk t -> buffer at byte offset bb --------
    auto load_chunk = [&](uint32_t bb, int t) {
        const int k0g = t * KC;
        #pragma unroll
        for (int lv = 0; lv < 2; ++lv) {
            const __half* src = Asrc[lv] + k0g;
            uint32_t dstb = smb + bb + lv * ATB;
            #pragma unroll
            for (int e = tid; e < M * 4; e += 256) {
                int r = e >> 2, seg = e & 3;
                cp16(dstb + (uint32_t)(r * TS + seg * 8) * 2, src + r * 256 + seg * 8);
            }
        }
        #pragma unroll
        for (int lv = 0; lv < 2; ++lv) {
            const __half* src = Bsrc[lv] + k0g;
            uint32_t dstb = smb + bb + 2 * ATB + lv * BTB;
            #pragma unroll
            for (int e = tid; e < 1024; e += 256) {
                int r = e >> 2, seg = e & 3;
                cp16(dstb + (uint32_t)(r * TS + seg * 8) * 2, src + r * 256 + seg * 8);
            }
        }
        cp_commit();
    };

    // B-fragment group loader: 2 n-tile pairs (j2 = 0 or 1 -> j in {2*j2, 2*j2+1})
    auto load_bgroup = [&](uint32_t bBase, int k0, int j2,
                           uint32_t bh[2][4], uint32_t bl[2][4]) {
        #pragma unroll
        for (int jj = 0; jj < 2; ++jj) {
            const int j = j2 * 2 + jj;
            uint32_t bAddr = bBase +
                (uint32_t)(((wcol + (2 * j + bNtOff) * 8 + lsub) * TS + k0 + bColOff) * 2);
            ldsm_x4(bh[jj], bAddr);
            ldsm_x4(bl[jj], bAddr + BTB);
        }
    };

    // ============ GEMM: 8 K-chunks of 32, 3-term 2-level fp16 split ============
    float acc[MR][8][4];
    #pragma unroll
    for (int mr = 0; mr < MR; ++mr)
        #pragma unroll
        for (int nt = 0; nt < 8; ++nt)
            #pragma unroll
            for (int j = 0; j < 4; ++j) acc[mr][nt][j] = 0.0f;

    load_chunk(0, 0);

    const int kphase = wid & 1;   // anti-phase odd warps

    for (int t = 0; t < NT; ++t) {
        const uint32_t bb = (t & 1) ? BUF : 0;
        if (t + 1 < NT) {
            load_chunk((t & 1) ? 0 : BUF, t + 1);
            cp_wait<1>();
        } else {
            cp_wait<0>();
        }
        __syncthreads();

        const uint32_t aBase = smb + bb;
        const uint32_t bBase = smb + bb + 2 * ATB;

        #pragma unroll
        for (int kss = 0; kss < 2; ++kss) {
            const int ks = kss ^ kphase;          // odd warps do k-steps in reverse
            const int k0 = ks * 16;
            // A fragments via ldmatrix.x4 (both levels)
            uint32_t ah[MR][4], al[MR][4];
            #pragma unroll
            for (int mr = 0; mr < MR; ++mr) {
                uint32_t aAddr = aBase +
                    (uint32_t)(((wrow + mr * 16 + aRowOff) * TS + k0 + aColOff) * 2);
                ldsm_x4(ah[mr], aAddr);
                ldsm_x4(al[mr], aAddr + ATB);
            }
            // Interleaved B prefetch: load group0; for each group, prefetch
            // the next group's fragments before running this group's MMAs.
            uint32_t bhA[2][4], blA[2][4], bhB[2][4], blB[2][4];
            load_bgroup(bBase, k0, 0, bhA, blA);
            #pragma unroll
            for (int j2 = 0; j2 < 2; ++j2) {
                uint32_t (*bh)[4] = (j2 == 0) ? bhA : bhB;
                uint32_t (*bl)[4] = (j2 == 0) ? blA : blB;
                if (j2 == 0) load_bgroup(bBase, k0, 1, bhB, blB);
                // pass 1: hh
                #pragma unroll
                for (int jj = 0; jj < 2; ++jj)
                    #pragma unroll
                    for (int u = 0; u < 2; ++u) {
                        const int nt = (j2 * 2 + jj) * 2 + u;
                        #pragma unroll
                        for (int mr = 0; mr < MR; ++mr)
                            mma_fp16(acc[mr][nt], ah[mr], bh[jj][2 * u], bh[jj][2 * u + 1]);
                    }
                // pass 2: lh
                #pragma unroll
                for (int jj = 0; jj < 2; ++jj)
                    #pragma unroll
                    for (int u = 0; u < 2; ++u) {
                        const int nt = (j2 * 2 + jj) * 2 + u;
                        #pragma unroll
                        for (int mr = 0; mr < MR; ++mr)
                            mma_fp16(acc[mr][nt], al[mr], bh[jj][2 * u], bh[jj][2 * u + 1]);
                    }
                // pass 3: hl
                #pragma unroll
                for (int jj = 0; jj < 2; ++jj)
                    #pragma unroll
                    for (int u = 0; u < 2; ++u) {
                        const int nt = (j2 * 2 + jj) * 2 + u;
                        #pragma unroll
                        for (int mr = 0; mr < MR; ++mr)
                            mma_fp16(acc[mr][nt], ah[mr], bl[jj][2 * u], bl[jj][2 * u + 1]);
                    }
            }
        }
        __syncthreads();   // all warps done with this buffer before refill
    }

    // ============ routing directly on register accumulators ============
    // acc[mr][nt][0,1] -> row (wrow+mr*16+g),   cols wcol+nt*8+2q+{0,1}
    // acc[mr][nt][2,3] -> row (wrow+mr*16+g+8), same cols
    if (tid < M) logits[tid] = 0.0f;

    for (int it = 0; it < 3; ++it) {
        // ---- probs = softmax(logits) ----
        if (it == 0) {
            if (tid < M) probs[tid] = 1.0f / (float)M;
        } else {
            float lv = (tid < M) ? logits[tid] : -3.402823466e38f;
            float mx = blockMax(lv, red);
            float ev = (tid < M) ? expf(lv - mx) : 0.0f;
            float Z = blockSum(ev, red);
            if (tid < M) probs[tid] = ev / Z;
        }
        __syncthreads();

        // ---- s[d] = sum_b probs[b] * P[b][d] from registers ----
        {
            float pr[MR][2];
            #pragma unroll
            for (int mr = 0; mr < MR; ++mr) {
                pr[mr][0] = probs[wrow + mr * 16 + g];
                pr[mr][1] = probs[wrow + mr * 16 + g + 8];
            }
            #pragma unroll
            for (int nt = 0; nt < 8; ++nt) {
                float c0 = 0.0f, c1 = 0.0f;
                #pragma unroll
                for (int mr = 0; mr < MR; ++mr) {
                    c0 = fmaf(pr[mr][0], acc[mr][nt][0], fmaf(pr[mr][1], acc[mr][nt][2], c0));
                    c1 = fmaf(pr[mr][0], acc[mr][nt][1], fmaf(pr[mr][1], acc[mr][nt][3], c1));
                }
                // reduce over the 8 g-lanes (stride-4 butterfly)
                #pragma unroll
                for (int o = 4; o <= 16; o <<= 1) {
                    c0 += __shfl_xor_sync(0xffffffffu, c0, o);
                    c1 += __shfl_xor_sync(0xffffffffu, c1, o);
                }
                if (g == 0) {
                    part[rg * 256 + wcol + nt * 8 + 2 * q]     = c0;
                    part[rg * 256 + wcol + nt * 8 + 2 * q + 1] = c1;
                }
            }
        }
        __syncthreads();

        // ---- squash (2 row-groups to combine) ----
        float sd = 0.0f;
        if (tid < 256)
            sd = part[tid] + part[256 + tid];
        float sq = blockSum(sd * sd, red);
        float scale = sq / ((1.0f + sq) * sqrtf(sq));
        if (tid < 256) vout[tid] = sd * scale;
        __syncthreads();

        if (it < 2) {
            // ---- logits[b] += sum_d P[b][d] * v[d] from registers ----
            float rowp[MR][2];
            #pragma unroll
            for (int mr = 0; mr < MR; ++mr) { rowp[mr][0] = 0.0f; rowp[mr][1] = 0.0f; }
            #pragma unroll
            for (int nt = 0; nt < 8; ++nt) {
                float v0 = vout[wcol + nt * 8 + 2 * q];
                float v1 = vout[wcol + nt * 8 + 2 * q + 1];
                #pragma unroll
                for (int mr = 0; mr < MR; ++mr) {
                    rowp[mr][0] = fmaf(acc[mr][nt][0], v0, fmaf(acc[mr][nt][1], v1, rowp[mr][0]));
                    rowp[mr][1] = fmaf(acc[mr][nt][2], v0, fmaf(acc[mr][nt][3], v1, rowp[mr][1]));
                }
            }
            // reduce over the 4 q-lanes
            #pragma unroll
            for (int mr = 0; mr < MR; ++mr) {
                #pragma unroll
                for (int o = 1; o <= 2; o <<= 1) {
                    rowp[mr][0] += __shfl_xor_sync(0xffffffffu, rowp[mr][0], o);
                    rowp[mr][1] += __shfl_xor_sync(0xffffffffu, rowp[mr][1], o);
                }
            }
            __syncthreads();   // part free
            if (q == 0) {
                #pragma unroll
                for (int mr = 0; mr < MR; ++mr) {
                    part[cg * M + wrow + mr * 16 + g]     = rowp[mr][0];
                    part[cg * M + wrow + mr * 16 + g + 8] = rowp[mr][1];
                }
            }
            __syncthreads();
            if (tid < M)
                logits[tid] += part[tid] + part[M + tid] + part[2 * M + tid] + part[3 * M + tid];
            __syncthreads();
        } else {
            if (tid < 256) {
                float v = vout[tid];
                size_t o = (size_t)blockIdx.x * outXStride + (size_t)blockIdx.y * outYStride + tid;
                if (F32OUT) {
                    OutF[o] = v;
                } else {
                    __half h, l;
                    split2(v, h, l);
                    OutH[o] = h; OutL[o] = l;
                }
            }
        }
    }
}

static size_t stage_smem(int M) {
    size_t buf = 2ull * M * 40 * 2 + 2ull * 256 * 40 * 2;   // one pipeline buffer
    size_t scr = (1024 + 256 + 2 * (size_t)M + 64) * 4;
    return 2 * buf + scr;
}

extern "C" void kernel_launch(void* const* d_in, const int* in_sizes, int n_in,
                              void* d_out, int out_size) {
    (void)in_sizes; (void)n_in; (void)out_size;
    const float* x  = (const float*)d_in[0];   // [64,128,256]
    const float* w1 = (const float*)d_in[1];   // [64,256,256]
    const float* w2 = (const float*)d_in[2];   // [32,256,256]
    float* out = (float*)d_out;                // [32,64,256]

    void* p;
    cudaGetSymbolAddress(&p, g_xh);  __half* xh  = (__half*)p;
    cudaGetSymbolAddress(&p, g_xl);  __half* xl  = (__half*)p;
    cudaGetSymbolAddress(&p, g_w1h); __half* w1h = (__half*)p;
    cudaGetSymbolAddress(&p, g_w1l); __half* w1l = (__half*)p;
    cudaGetSymbolAddress(&p, g_w2h); __half* w2h = (__half*)p;
    cudaGetSymbolAddress(&p, g_w2l); __half* w2l = (__half*)p;
    cudaGetSymbolAddress(&p, g_o1h); __half* o1h = (__half*)p;
    cudaGetSymbolAddress(&p, g_o1l); __half* o1l = (__half*)p;

    // pre-pass: fp16 hi/lo splits (+ W transposed to [n][k])
    split_x_kernel<<<8192, 256>>>(x, xh, xl, 64 * 128 * 256);
    trans_split_w<<<dim3(8, 8, 64), 256>>>(w1, w1h, w1l);
    trans_split_w<<<dim3(8, 8, 32), 256>>>(w2, w2h, w2l);

    const size_t sm1 = stage_smem(128);   // ~129 KB
    const size_t sm2 = stage_smem(64);    // ~109 KB
    cudaFuncSetAttribute((const void*)caps_mma_route<128, false, 1>,
                         cudaFuncAttributeMaxDynamicSharedMemorySize, (int)sm1);
    cudaFuncSetAttribute((const void*)caps_mma_route<64, true, 2>,
                         cudaFuncAttributeMaxDynamicSharedMemorySize, (int)sm2);

    // Stage 1: (a=64, h=64) -> out1 fp16 h/l [a][h][256]
    caps_mma_route<128, false, 1><<<dim3(64, 64), 256, sm1>>>(
        xh, xl, w1h, w1l, nullptr, o1h, o1l, /*x=a*/ 64 * 256, /*y=h*/ 256);

    // Stage 2: (a=64, c=32) -> out fp32 [c][a][256]; 2 CTAs/SM
    caps_mma_route<64, true, 2><<<dim3(64, 32), 256, sm2>>>(
        o1h, o1l, w2h, w2l, out, nullptr, nullptr, /*x=a*/ 256, /*y=c*/ 64 * 256);
}

// round 17
// speedup vs baseline: 4.9148x; 1.5146x over previous
#include <cuda_runtime.h>
#include <math.h>
#include <stdint.h>

// ---------------- device globals (no allocations allowed) ----------------
__device__ float g_U[64 * 64 * 256];        // [h][a][256]
__device__ float g_S[64 * 64 * 256];        // [h][a][256]
__device__ float g_V[64 * 64 * 256];        // [h][a][256]
__device__ float g_T[64 * 64 * 256];        // [h][a][256]
__device__ float g_logits[64 * 64 * 128];   // [h][a][R]
__device__ float g_out1[64 * 64 * 256];     // [a][h][256] (stage-2 input)

// =====================================================================
// k1: probs = softmax(logits) rows; U[h][a][dblk] = sum_b probs[h,a,b]*X[a,b,dblk]
// grid (a=64, dblk=4), block 256.
// =====================================================================
template<int R, int HN, bool ITER0>
__global__ void __launch_bounds__(256)
k1_formU(const float* __restrict__ X, const float* __restrict__ logits,
         float* __restrict__ U)
{
    constexpr int PS = R + 1;                 // probs row stride (bank-safe)
    extern __shared__ float sm[];
    float* Xs    = sm;                        // [R][68]  (17 float4 / row)
    float* probs = Xs + R * 68;               // [HN][PS]
    const int tid = threadIdx.x, a = blockIdx.x, dblk = blockIdx.y;
    const int wid = tid >> 5, lane = tid & 31;

    const float4* X4 = (const float4*)(X + (size_t)a * R * 256);
    float4* Xs4 = (float4*)Xs;
    for (int e = tid; e < R * 16; e += 256) {
        int b = e >> 4, d4 = e & 15;
        Xs4[b * 17 + d4] = X4[b * 64 + dblk * 16 + d4];
    }
    // softmax over the R routing rows, one warp per h row
    for (int hh = wid; hh < HN; hh += 8) {
        if (ITER0) {
            for (int i = lane; i < R; i += 32) probs[hh * PS + i] = 1.0f / (float)R;
        } else {
            constexpr int CNT = R / 32;
            float lv[CNT]; float mx = -3.402823466e38f;
            const float* lrow = logits + ((size_t)hh * 64 + a) * R;
            #pragma unroll
            for (int i = 0; i < CNT; ++i) { lv[i] = lrow[lane + 32 * i]; mx = fmaxf(mx, lv[i]); }
            #pragma unroll
            for (int o = 16; o; o >>= 1) mx = fmaxf(mx, __shfl_xor_sync(0xffffffffu, mx, o));
            float zs = 0.0f;
            #pragma unroll
            for (int i = 0; i < CNT; ++i) { lv[i] = expf(lv[i] - mx); zs += lv[i]; }
            #pragma unroll
            for (int o = 16; o; o >>= 1) zs += __shfl_xor_sync(0xffffffffu, zs, o);
            float inv = 1.0f / zs;
            #pragma unroll
            for (int i = 0; i < CNT; ++i) probs[hh * PS + lane + 32 * i] = lv[i] * inv;
        }
    }
    __syncthreads();

    // GEMM [HN,R] @ [R,64]: thread = (hq, dq) quad pair
    const int dq = tid & 15, hq = tid >> 4;
    if (hq < HN / 4) {
        float acc[4][4] = {};
        for (int b = 0; b < R; ++b) {
            float4 xv = Xs4[b * 17 + dq];
            #pragma unroll
            for (int i = 0; i < 4; ++i) {
                float p = probs[(hq * 4 + i) * PS + b];
                acc[i][0] += p * xv.x; acc[i][1] += p * xv.y;
                acc[i][2] += p * xv.z; acc[i][3] += p * xv.w;
            }
        }
        #pragma unroll
        for (int i = 0; i < 4; ++i) {
            float4* U4 = (float4*)(U + ((size_t)(hq * 4 + i) * 64 + a) * 256);
            U4[dblk * 16 + dq] = make_float4(acc[i][0], acc[i][1], acc[i][2], acc[i][3]);
        }
    }
}

// =====================================================================
// k2: S[h][a][n] = sum_d U[h][a][d] * W_h[d][n]   grid (h, nblk=4), block 256
// =====================================================================
__global__ void __launch_bounds__(256)
k2_S(const float* __restrict__ W, const float* __restrict__ U, float* __restrict__ S)
{
    extern __shared__ float sm[];
    float* Us = sm;                 // [64][260]
    float* Ws = Us + 64 * 260;      // [256][68]
    const int tid = threadIdx.x, h = blockIdx.x, n0 = blockIdx.y * 64;

    const float4* U4 = (const float4*)(U + (size_t)h * 64 * 256);
    float4* Us4 = (float4*)Us;
    for (int e = tid; e < 4096; e += 256) {
        int aa = e >> 6, d4 = e & 63;
        Us4[aa * 65 + d4] = U4[aa * 64 + d4];
    }
    const float4* W4 = (const float4*)(W + (size_t)h * 65536);
    float4* Ws4 = (float4*)Ws;
    for (int e = tid; e < 4096; e += 256) {
        int d = e >> 4, n4 = e & 15;
        Ws4[d * 17 + n4] = W4[d * 64 + (n0 >> 2) + n4];
    }
    __syncthreads();

    const int aq = tid >> 4, nq = tid & 15;
    float acc[4][4] = {};
    for (int d = 0; d < 256; ++d) {
        float4 w = Ws4[d * 17 + nq];
        #pragma unroll
        for (int i = 0; i < 4; ++i) {
            float u = Us[(aq * 4 + i) * 260 + d];
            acc[i][0] += u * w.x; acc[i][1] += u * w.y;
            acc[i][2] += u * w.z; acc[i][3] += u * w.w;
        }
    }
    #pragma unroll
    for (int i = 0; i < 4; ++i) {
        float4* S4 = (float4*)(S + ((size_t)h * 64 + aq * 4 + i) * 256);
        S4[(n0 >> 2) + nq] = make_float4(acc[i][0], acc[i][1], acc[i][2], acc[i][3]);
    }
}

// =====================================================================
// k3: squash rows of S -> V (optionally also write stage output)
// grid (HN*64/8), block 256 (warp per row)
// OUTMODE: 0 none, 1 out1[a][h][d], 2 d_out[c][a][d]
// =====================================================================
template<int HN, int OUTMODE>
__global__ void __launch_bounds__(256)
k3_squash(const float* __restrict__ S, float* __restrict__ V, float* __restrict__ Out)
{
    const int tid = threadIdx.x, wid = tid >> 5, lane = tid & 31;
    const int row = blockIdx.x * 8 + wid;     // h*64 + a
    const int h = row >> 6, a = row & 63;
    const float4* S4 = (const float4*)(S + (size_t)row * 256);
    float4 s0 = S4[lane * 2], s1 = S4[lane * 2 + 1];
    float sq = s0.x*s0.x + s0.y*s0.y + s0.z*s0.z + s0.w*s0.w
             + s1.x*s1.x + s1.y*s1.y + s1.z*s1.z + s1.w*s1.w;
    #pragma unroll
    for (int o = 16; o; o >>= 1) sq += __shfl_xor_sync(0xffffffffu, sq, o);
    float sc = sq / ((1.0f + sq) * sqrtf(sq));
    float4 v0 = make_float4(s0.x*sc, s0.y*sc, s0.z*sc, s0.w*sc);
    float4 v1 = make_float4(s1.x*sc, s1.y*sc, s1.z*sc, s1.w*sc);
    float4* V4 = (float4*)(V + (size_t)row * 256);
    V4[lane * 2] = v0; V4[lane * 2 + 1] = v1;
    if (OUTMODE == 1) {
        float4* O4 = (float4*)(Out + ((size_t)a * HN + h) * 256);
        O4[lane * 2] = v0; O4[lane * 2 + 1] = v1;
    } else if (OUTMODE == 2) {
        float4* O4 = (float4*)(Out + ((size_t)h * 64 + a) * 256);
        O4[lane * 2] = v0; O4[lane * 2 + 1] = v1;
    }
}

// =====================================================================
// k4: T[h][a][k] = sum_d V[h][a][d] * W_h[k][d]   grid (h, kblk=4), block 256
// =====================================================================
__global__ void __launch_bounds__(256)
k4_T(const float* __restrict__ W, const float* __restrict__ V, float* __restrict__ T)
{
    extern __shared__ float sm[];
    float* Vs = sm;                 // [64][260]
    float* Ws = Vs + 64 * 260;      // [64][260]
    const int tid = threadIdx.x, h = blockIdx.x, k0 = blockIdx.y * 64;

    const float4* V4 = (const float4*)(V + (size_t)h * 64 * 256);
    float4* Vs4 = (float4*)Vs;
    for (int e = tid; e < 4096; e += 256) {
        int aa = e >> 6, d4 = e & 63;
        Vs4[aa * 65 + d4] = V4[aa * 64 + d4];
    }
    const float4* W4 = (const float4*)(W + (size_t)h * 65536);
    float4* Ws4 = (float4*)Ws;
    for (int e = tid; e < 4096; e += 256) {
        int k = e >> 6, d4 = e & 63;
        Ws4[k * 65 + d4] = W4[(k0 + k) * 64 + d4];
    }
    __syncthreads();

    const int aq = tid >> 4, kq = tid & 15;
    float acc[4][4] = {};
    for (int d4 = 0; d4 < 64; ++d4) {
        float4 vv[4];
        #pragma unroll
        for (int i = 0; i < 4; ++i) vv[i] = Vs4[(aq * 4 + i) * 65 + d4];
        #pragma unroll
        for (int j = 0; j < 4; ++j) {
            float4 w = Ws4[(kq * 4 + j) * 65 + d4];
            #pragma unroll
            for (int i = 0; i < 4; ++i)
                acc[i][j] += vv[i].x*w.x + vv[i].y*w.y + vv[i].z*w.z + vv[i].w*w.w;
        }
    }
    #pragma unroll
    for (int i = 0; i < 4; ++i) {
        float4* T4 = (float4*)(T + ((size_t)h * 64 + aq * 4 + i) * 256);
        T4[(k0 >> 2) + kq] = make_float4(acc[i][0], acc[i][1], acc[i][2], acc[i][3]);
    }
}

// =====================================================================
// k5: logits[h][a][b] (+)= sum_d X[a][b][d] * T[h][a][d]
// grid (a=64, hblk = HN/8), block 256
// =====================================================================
template<int R, bool FIRST>
__global__ void __launch_bounds__(256)
k5_logits(const float* __restrict__ X, const float* __restrict__ T,
          float* __restrict__ logits)
{
    extern __shared__ float sm[];
    float* Xs = sm;                 // [R][260]
    float* Ts = Xs + R * 260;       // [8][260]
    const int tid = threadIdx.x, a = blockIdx.x, h0 = blockIdx.y * 8;

    const float4* X4 = (const float4*)(X + (size_t)a * R * 256);
    float4* Xs4 = (float4*)Xs;
    for (int e = tid; e < R * 64; e += 256) {
        int b = e >> 6, d4 = e & 63;
        Xs4[b * 65 + d4] = X4[b * 64 + d4];
    }
    float4* Ts4 = (float4*)Ts;
    for (int e = tid; e < 512; e += 256) {
        int hh = e >> 6, d4 = e & 63;
        Ts4[hh * 65 + d4] = ((const float4*)(T + ((size_t)(h0 + hh) * 64 + a) * 256))[d4];
    }
    __syncthreads();

    constexpr int SPLIT = 256 / R;            // 2 (R=128) or 4 (R=64)
    constexpr int NF4 = 64 / SPLIT;
    const int b = tid / SPLIT, hf = tid % SPLIT;
    #pragma unroll
    for (int hh = 0; hh < 8; ++hh) {
        float s = 0.0f;
        #pragma unroll 8
        for (int d4 = 0; d4 < NF4; ++d4) {
            float4 x = Xs4[b * 65 + hf * NF4 + d4];
            float4 t = Ts4[hh * 65 + hf * NF4 + d4];
            s += x.x*t.x + x.y*t.y + x.z*t.z + x.w*t.w;
        }
        #pragma unroll
        for (int o = 1; o < SPLIT; o <<= 1) s += __shfl_xor_sync(0xffffffffu, s, o);
        if (hf == 0) {
            size_t idx = ((size_t)(h0 + hh) * 64 + a) * R + b;
            logits[idx] = FIRST ? s : (logits[idx] + s);
        }
    }
}

// ---------------- host ----------------
extern "C" void kernel_launch(void* const* d_in, const int* in_sizes, int n_in,
                              void* d_out, int out_size) {
    (void)in_sizes; (void)n_in; (void)out_size;
    const float* x  = (const float*)d_in[0];   // [64,128,256]
    const float* w1 = (const float*)d_in[1];   // [64,256,256]
    const float* w2 = (const float*)d_in[2];   // [32,256,256]
    float* out = (float*)d_out;                // [32,64,256]

    void* p;
    cudaGetSymbolAddress(&p, g_U);      float* U  = (float*)p;
    cudaGetSymbolAddress(&p, g_S);      float* S  = (float*)p;
    cudaGetSymbolAddress(&p, g_V);      float* V  = (float*)p;
    cudaGetSymbolAddress(&p, g_T);      float* T  = (float*)p;
    cudaGetSymbolAddress(&p, g_logits); float* lg = (float*)p;
    cudaGetSymbolAddress(&p, g_out1);   float* o1 = (float*)p;

    const size_t smk1a = (size_t)(128 * 68 + 64 * 129) * 4;   // 67,840
    const size_t smk1b = (size_t)(64 * 68 + 32 * 65) * 4;     // 25,728
    const size_t smk2  = (size_t)(64 * 260 + 256 * 68) * 4;   // 136,192
    const size_t smk4  = (size_t)(64 * 260 + 64 * 260) * 4;   // 133,120
    const size_t smk5a = (size_t)(128 * 260 + 8 * 260) * 4;   // 141,440
    const size_t smk5b = (size_t)(64 * 260 + 8 * 260) * 4;    // 74,880

    cudaFuncSetAttribute((const void*)k1_formU<128, 64, true>,
                         cudaFuncAttributeMaxDynamicSharedMemorySize, (int)smk1a);
    cudaFuncSetAttribute((const void*)k1_formU<128, 64, false>,
                         cudaFuncAttributeMaxDynamicSharedMemorySize, (int)smk1a);
    cudaFuncSetAttribute((const void*)k1_formU<64, 32, true>,
                         cudaFuncAttributeMaxDynamicSharedMemorySize, (int)smk1b);
    cudaFuncSetAttribute((const void*)k1_formU<64, 32, false>,
                         cudaFuncAttributeMaxDynamicSharedMemorySize, (int)smk1b);
    cudaFuncSetAttribute((const void*)k2_S,
                         cudaFuncAttributeMaxDynamicSharedMemorySize, (int)smk2);
    cudaFuncSetAttribute((const void*)k4_T,
                         cudaFuncAttributeMaxDynamicSharedMemorySize, (int)smk4);
    cudaFuncSetAttribute((const void*)k5_logits<128, true>,
                         cudaFuncAttributeMaxDynamicSharedMemorySize, (int)smk5a);
    cudaFuncSetAttribute((const void*)k5_logits<128, false>,
                         cudaFuncAttributeMaxDynamicSharedMemorySize, (int)smk5a);
    cudaFuncSetAttribute((const void*)k5_logits<64, true>,
                         cudaFuncAttributeMaxDynamicSharedMemorySize, (int)smk5b);
    cudaFuncSetAttribute((const void*)k5_logits<64, false>,
                         cudaFuncAttributeMaxDynamicSharedMemorySize, (int)smk5b);

    // ================= Stage 1: R=128, HN=64 =================
    // iter 0
    k1_formU<128, 64, true><<<dim3(64, 4), 256, smk1a>>>(x, lg, U);
    k2_S<<<dim3(64, 4), 256, smk2>>>(w1, U, S);
    k3_squash<64, 0><<<512, 256>>>(S, V, nullptr);
    k4_T<<<dim3(64, 4), 256, smk4>>>(w1, V, T);
    k5_logits<128, true><<<dim3(64, 8), 256, smk5a>>>(x, T, lg);
    // iter 1
    k1_formU<128, 64, false><<<dim3(64, 4), 256, smk1a>>>(x, lg, U);
    k2_S<<<dim3(64, 4), 256, smk2>>>(w1, U, S);
    k3_squash<64, 0><<<512, 256>>>(S, V, nullptr);
    k4_T<<<dim3(64, 4), 256, smk4>>>(w1, V, T);
    k5_logits<128, false><<<dim3(64, 8), 256, smk5a>>>(x, T, lg);
    // iter 2 (final -> out1[a][h][d])
    k1_formU<128, 64, false><<<dim3(64, 4), 256, smk1a>>>(x, lg, U);
    k2_S<<<dim3(64, 4), 256, smk2>>>(w1, U, S);
    k3_squash<64, 1><<<512, 256>>>(S, V, o1);

    // ================= Stage 2: R=64, HN=32 =================
    // iter 0
    k1_formU<64, 32, true><<<dim3(64, 4), 256, smk1b>>>(o1, lg, U);
    k2_S<<<dim3(32, 4), 256, smk2>>>(w2, U, S);
    k3_squash<32, 0><<<256, 256>>>(S, V, nullptr);
    k4_T<<<dim3(32, 4), 256, smk4>>>(w2, V, T);
    k5_logits<64, true><<<dim3(64, 4), 256, smk5b>>>(o1, T, lg);
    // iter 1
    k1_formU<64, 32, false><<<dim3(64, 4), 256, smk1b>>>(o1, lg, U);
    k2_S<<<dim3(32, 4), 256, smk2>>>(w2, U, S);
    k3_squash<32, 0><<<256, 256>>>(S, V, nullptr);
    k4_T<<<dim3(32, 4), 256, smk4>>>(w2, V, T);
    k5_logits<64, false><<<dim3(64, 4), 256, smk5b>>>(o1, T, lg);
    // iter 2 (final -> d_out[c][a][d])
    k1_formU<64, 32, false><<<dim3(64, 4), 256, smk1b>>>(o1, lg, U);
    k2_S<<<dim3(32, 4), 256, smk2>>>(w2, U, S);
    k3_squash<32, 2><<<256, 256>>>(S, V, out);
}